// round 10
// baseline (speedup 1.0000x reference)
#include <cuda_runtime.h>
#include <cuda_fp16.h>
#include <math.h>
#include <stdint.h>

// Problem constants
#define C0 64
#define T  512
#define F  256
#define LL 506
#define KW 7
#define C2 128
#define M_ROWS (F*LL)          // 129536
#define U_STRIDE (M_ROWS*128)  // 16580608
#define EPSV 1e-6f

// ---------------- scratch ----------------
__device__ __half g_X2h[T*F*C0],  g_X2l[T*F*C0];
__device__ float  g_U  [2*M_ROWS*128];
__device__ float  g_y  [M_ROWS*C0];      // raw SRU output
__device__ float  g_a1 [M_ROWS*C2];      // raw c1 out (biased)
__device__ float  g_a2 [M_ROWS*C2];      // raw c2 out (biased)
__device__ float  g_a3r[M_ROWS*C0];      // raw c3 out (biased)
__device__ double g_part[1024];
__device__ float  g_stats0[2];
__device__ float  g_stats[3][F*2];
// fp16 hi/lo split, K-major weights: [o][k]
__device__ __half g_wsruh[256*448], g_wsrul[256*448];
__device__ __half g_w2h [128*896],  g_w2l [128*896];
__device__ __half g_w1h [128*64],   g_w1l [128*64];
__device__ __half g_w3h [64*128],   g_w3l [64*128];
__device__ __half g_wcth[64*448],   g_wctl[64*448];

__device__ __forceinline__ float sigf(float v){ return 1.f/(1.f+__expf(-v)); }
__device__ __forceinline__ void split16(float v, __half* hp, __half* lp){
    __half h = __float2half_rn(v);
    *hp = h;
    *lp = __float2half_rn(v - __half2float(h));
}
__device__ __forceinline__ uint32_t smem_u32(const void* p){
    uint32_t a;
    asm("{ .reg .u64 t; cvta.to.shared.u64 t, %1; cvt.u32.u64 %0, t; }" : "=r"(a) : "l"(p));
    return a;
}
__device__ __forceinline__ void cp16(uint32_t dst, const void* src, bool pred){
    int sz = pred ? 16 : 0;
    asm volatile("cp.async.cg.shared.global [%0], [%1], 16, %2;" :: "r"(dst), "l"(src), "r"(sz) : "memory");
}
#define CP_COMMIT() asm volatile("cp.async.commit_group;" ::: "memory")
#define CP_WAIT1()  asm volatile("cp.async.wait_group 1;" ::: "memory")
#define CP_WAIT0()  asm volatile("cp.async.wait_group 0;" ::: "memory")

__device__ __forceinline__ void ldsm4(uint32_t* r, uint32_t addr){
    asm volatile("ldmatrix.sync.aligned.m8n8.x4.shared.b16 {%0,%1,%2,%3}, [%4];"
        : "=r"(r[0]),"=r"(r[1]),"=r"(r[2]),"=r"(r[3]) : "r"(addr));
}
__device__ __forceinline__ void sts128w(uint32_t a, uint32_t x,uint32_t y,uint32_t z,uint32_t w){
    asm volatile("st.shared.v4.b32 [%0], {%1,%2,%3,%4};" :: "r"(a),"r"(x),"r"(y),"r"(z),"r"(w) : "memory");
}
__device__ __forceinline__ uint32_t packh2(__half a, __half b){
    return (uint32_t)__half_as_ushort(a) | ((uint32_t)__half_as_ushort(b) << 16);
}

// ---------------- gn0 reductions ----------------
__global__ void k_red0(const float* __restrict__ x){
    double s=0.0, q=0.0;
    for(int i = blockIdx.x*256 + threadIdx.x; i < T*F*C0; i += 512*256){
        double v = x[i]; s += v; q += v*v;
    }
    __shared__ double shs[256], shq[256];
    int tid = threadIdx.x;
    shs[tid]=s; shq[tid]=q; __syncthreads();
    for(int o=128;o>0;o>>=1){ if(tid<o){shs[tid]+=shs[tid+o]; shq[tid]+=shq[tid+o];} __syncthreads(); }
    if(tid==0){ g_part[blockIdx.x*2]=shs[0]; g_part[blockIdx.x*2+1]=shq[0]; }
}
__global__ void k_red0b(){
    double s=0.0, q=0.0;
    int tid = threadIdx.x;
    for(int b=tid;b<512;b+=256){ s += g_part[2*b]; q += g_part[2*b+1]; }
    __shared__ double shs[256], shq[256];
    shs[tid]=s; shq[tid]=q; __syncthreads();
    for(int o=128;o>0;o>>=1){ if(tid<o){shs[tid]+=shs[tid+o]; shq[tid]+=shq[tid+o];} __syncthreads(); }
    if(tid==0){
        double n = (double)T*F*C0;
        double m = shs[0]/n;
        double v = shq[0]/n - m*m;
        g_stats0[0] = (float)m;
        g_stats0[1] = rsqrtf((float)v + EPSV);
    }
}

// ---------------- weight prep: K-major [o][k], fp16 hi/lo split ----------------
__global__ void k_prep(const float* __restrict__ w1, const float* __restrict__ w2,
                       const float* __restrict__ w3, const float* __restrict__ wc,
                       const float* __restrict__ sw){
    int i = blockIdx.x*blockDim.x + threadIdx.x;
    if(i < 114688){
        int o=i/448, kl=i%448, k7=kl>>6, c=kl&63;
        float v = sw[(o>>7)*57344 + (c*7+k7)*128 + (o&127)];
        split16(v, &g_wsruh[i], &g_wsrul[i]); return;
    }
    i -= 114688;
    if(i < 114688){
        int o=i/896, kl=i%896, k7=kl>>7, c=kl&127;
        split16(w2[o*896 + c*7 + k7], &g_w2h[i], &g_w2l[i]); return;
    }
    i -= 114688;
    if(i < 8192){ split16(w1[i], &g_w1h[i], &g_w1l[i]); return; }
    i -= 8192;
    if(i < 8192){ split16(w3[i], &g_w3h[i], &g_w3l[i]); return; }
    i -= 8192;
    if(i < 28672){
        int o=i/448, kl=i%448, k7=kl>>6, c=kl&63;
        split16(wc[c*448 + o*7 + k7], &g_wcth[i], &g_wctl[i]);
    }
}

// ---------------- gn0 apply + transpose to [t][f][c], split store ----------------
__global__ void k_xn(const float* __restrict__ x, const float* __restrict__ w, const float* __restrict__ b){
    __shared__ float sm[32*65];
    int t0 = blockIdx.x*32;
    int f  = blockIdx.y;
    int tid = threadIdx.x;
    float mean = g_stats0[0], rstd = g_stats0[1];
    #pragma unroll
    for(int rep=0;rep<8;rep++){
        int lin = tid + rep*256;
        int c = lin >> 5, tl = lin & 31;
        float v = x[((size_t)c*F + f)*T + t0 + tl];
        v = (v-mean)*rstd*w[c] + b[c];
        sm[tl*65 + c] = v;
    }
    __syncthreads();
    #pragma unroll
    for(int rep=0;rep<8;rep++){
        int lin = tid + rep*256;
        int c = lin & 63, tl = lin >> 6;
        size_t idx = ((size_t)(t0+tl)*F + f)*C0 + c;
        split16(sm[tl*65 + c], &g_X2h[idx], &g_X2l[idx]);
    }
}

// ---------------- fp16x3 mma.sync GEMM with fused A-transform ----------------
enum { M_SRU=0, M_C1=1, M_C2=2, M_C3=3, M_CT=4 };

__device__ __forceinline__ void mma16(float* c, const uint32_t* a, const uint32_t* b){
    asm volatile(
        "mma.sync.aligned.m16n8k16.row.col.f32.f16.f16.f32 "
        "{%0,%1,%2,%3},{%4,%5,%6,%7},{%8,%9},{%0,%1,%2,%3};"
        : "+f"(c[0]), "+f"(c[1]), "+f"(c[2]), "+f"(c[3])
        : "r"(a[0]), "r"(a[1]), "r"(a[2]), "r"(a[3]), "r"(b[0]), "r"(b[1]));
}

// smem layout (32-bit words), rows padded to 40 halfs (80 B)
#define AH_W 0
#define AL_W (128*20)              // 2560
#define BH_W (2*128*20)            // 5120

template<int MODE, int BN, int KCHUNKS, int KTOT>
__global__ void __launch_bounds__(256,2)
k_mma(const float* __restrict__ bias, const float* __restrict__ xs, float* __restrict__ outp,
      const float* __restrict__ nw, const float* __restrict__ nb){
    extern __shared__ uint32_t dsm[];
    __shared__ int s_aux[128];
    __shared__ float s_w[128], s_b[128], s_mn[128], s_rs[128];
    constexpr int NI = BN/16;
    constexpr int BUF_Wc = BH_W + 2*BN*20;
    constexpr bool NORM = (MODE==M_C2 || MODE==M_C3 || MODE==M_CT);
    constexpr int SIDX = (MODE==M_C2)?0 : (MODE==M_C3)?1 : 2;
    constexpr int CHN  = (MODE==M_CT)?64 : 128;

    const int tid = threadIdx.x, lane = tid & 31, wid = tid >> 5;
    const int warp_m = wid & 3, warp_n = wid >> 2;
    const int lr = lane >> 2, lc = lane & 3;
    const int col0 = blockIdx.x * BN;
    const int row0 = blockIdx.y * 128;
    const uint32_t smb = smem_u32(dsm);
    // ldmatrix lane geometry
    const int rin = lane & 7, tt = lane >> 3;
    const int a_row = (tt&1)*8 + rin;
    const int a_kb  = (tt>>1)*16;
    const int b_nt  = (tt>>1)*8;
    const int b_kb  = (tt&1)*16;

    const __half* BpH = (MODE==M_SRU)? g_wsruh: (MODE==M_C1)? g_w1h : (MODE==M_C2)? g_w2h: (MODE==M_C3)? g_w3h: g_wcth;
    const __half* BpL = (MODE==M_SRU)? g_wsrul: (MODE==M_C1)? g_w1l : (MODE==M_C2)? g_w2l: (MODE==M_C3)? g_w3l: g_wctl;
    const float*  Araw = (MODE==M_C1)? g_y : (MODE==M_C2)? g_a1 : (MODE==M_C3)? g_a2 : g_a3r;

    if(MODE==M_C2 || MODE==M_CT){
        if(tid<128){
            int r = row0 + tid;
            s_aux[tid] = (MODE==M_C2) ? (r % LL) : (r & 511);
        }
    }
    if(NORM){
        if(tid < CHN){ s_w[tid] = nw[tid]; s_b[tid] = nb[tid]; }
        if(tid < 128){
            int n = (MODE==M_CT) ? ((row0+tid)>>9) : ((row0+tid)/LL);
            s_mn[tid] = g_stats[SIDX][2*n];
            s_rs[tid] = g_stats[SIDX][2*n+1];
        }
    }
    __syncthreads();

    // B cp.async issue (shared by both paths)
    auto cpB = [&](int ch, int b){
        const int kbase = ch*32;
        const uint32_t base = smb + b*(BUF_Wc*4);
        #pragma unroll
        for(int rep=0;rep<BN/64;rep++){
            int o = rep*64 + (tid>>2), k4 = tid&3;
            size_t off = (size_t)(col0+o)*KTOT + kbase + k4*8;
            uint32_t d = base + BH_W*4 + o*80 + k4*16;
            cp16(d,               BpH+off, true);
            cp16(d + BN*20*4,     BpL+off, true);
        }
    };

    float acc[2][NI][4] = {};

    // ---- mma on one buffered chunk (interleaved: acc reuse distance = 8) ----
    auto mma_chunk = [&](int b){
        const uint32_t bufb = smb + b*(BUF_Wc*4);
        #pragma unroll
        for(int k16=0;k16<2;k16++){
            uint32_t ah[2][4], al[2][4];
            #pragma unroll
            for(int mi=0;mi<2;mi++){
                uint32_t ra = bufb + (warp_m*32 + mi*16 + a_row)*80 + k16*32 + a_kb;
                ldsm4(ah[mi], ra);
                ldsm4(al[mi], ra + AL_W*4);
            }
            #pragma unroll
            for(int pg=0; pg<NI/4; pg++){
                const int p0 = 2*pg, p1 = 2*pg+1;
                uint32_t rb0 = bufb + BH_W*4 + (warp_n*(BN/2) + p0*16 + b_nt + rin)*80 + k16*32 + b_kb;
                uint32_t rb1 = bufb + BH_W*4 + (warp_n*(BN/2) + p1*16 + b_nt + rin)*80 + k16*32 + b_kb;
                uint32_t bh0[4], bl0[4], bh1[4], bl1[4];
                ldsm4(bh0, rb0); ldsm4(bl0, rb0 + BN*20*4);
                ldsm4(bh1, rb1); ldsm4(bl1, rb1 + BN*20*4);
                // hh pass (8 independent accumulators)
                mma16(acc[0][2*p0],   ah[0], bh0);   mma16(acc[1][2*p0],   ah[1], bh0);
                mma16(acc[0][2*p0+1], ah[0], bh0+2); mma16(acc[1][2*p0+1], ah[1], bh0+2);
                mma16(acc[0][2*p1],   ah[0], bh1);   mma16(acc[1][2*p1],   ah[1], bh1);
                mma16(acc[0][2*p1+1], ah[0], bh1+2); mma16(acc[1][2*p1+1], ah[1], bh1+2);
                // lh pass
                mma16(acc[0][2*p0],   al[0], bh0);   mma16(acc[1][2*p0],   al[1], bh0);
                mma16(acc[0][2*p0+1], al[0], bh0+2); mma16(acc[1][2*p0+1], al[1], bh0+2);
                mma16(acc[0][2*p1],   al[0], bh1);   mma16(acc[1][2*p1],   al[1], bh1);
                mma16(acc[0][2*p1+1], al[0], bh1+2); mma16(acc[1][2*p1+1], al[1], bh1+2);
                // hl pass
                mma16(acc[0][2*p0],   ah[0], bl0);   mma16(acc[1][2*p0],   ah[1], bl0);
                mma16(acc[0][2*p0+1], ah[0], bl0+2); mma16(acc[1][2*p0+1], ah[1], bl0+2);
                mma16(acc[0][2*p1],   ah[0], bl1);   mma16(acc[1][2*p1],   ah[1], bl1);
                mma16(acc[0][2*p1+1], ah[0], bl1+2); mma16(acc[1][2*p1+1], ah[1], bl1+2);
            }
        }
    };

    if(MODE==M_SRU){
        // ---- cp.async A path (pre-split X2) ----
        auto issue = [&](int ch, int b){
            int k7 = ch>>1, c0 = (ch&1)*32;
            const uint32_t base = smb + b*(BUF_Wc*4);
            #pragma unroll
            for(int rep=0;rep<2;rep++){
                int lin = tid + rep*256;
                int m = lin>>2, k4 = lin&3;
                size_t off=(size_t)(row0+m+k7*256)*64 + c0 + k4*8;
                uint32_t d = base + m*80 + k4*16;
                cp16(d,            g_X2h+off, true);
                cp16(d + AL_W*4,   g_X2l+off, true);
            }
            cpB(ch, b);
        };
        issue(0, 0);
        CP_COMMIT();
        for(int ch=0; ch<KCHUNKS; ch++){
            if(ch+1 < KCHUNKS){ issue(ch+1, (ch+1)&1); CP_COMMIT(); CP_WAIT1(); }
            else { CP_WAIT0(); }
            __syncthreads();
            mma_chunk(ch&1);
            __syncthreads();
        }
    } else {
        // ---- register A path with fused transform ----
        const int am = tid>>1, akh = (tid&1)*16;
        const float mymn = NORM ? s_mn[am] : 0.f;
        const float myrs = NORM ? s_rs[am] : 0.f;
        float4 a4[4], y4[4];
        bool apred = true;
        int acbase = 0;

        auto loadA = [&](int ch){
            size_t off = 0;
            if(MODE==M_C1){
                apred = true;
                off = (size_t)(row0+am)*64 + ch*32 + akh;
            } else if(MODE==M_C2){
                int k7 = ch>>2, c0 = (ch&3)*32;
                int l2 = s_aux[am] + k7 - 3;
                apred = ((unsigned)l2 < LL);
                off = (size_t)(row0+am+k7-3)*128 + c0 + akh;
                acbase = c0 + akh;
            } else if(MODE==M_C3){
                apred = true;
                off = (size_t)(row0+am)*128 + ch*32 + akh;
                acbase = ch*32 + akh;
            } else { // M_CT
                int k7 = ch>>1, c0 = (ch&1)*32;
                int p2 = s_aux[am] - k7;
                apred = ((unsigned)p2 < LL);
                int n = (row0+am)>>9;
                off = ((size_t)n*LL + p2)*64 + c0 + akh;
                acbase = c0 + akh;
            }
            if(apred){
                #pragma unroll
                for(int q=0;q<4;q++) a4[q] = *(const float4*)(Araw + off + q*4);
                if(MODE==M_CT){
                    #pragma unroll
                    for(int q=0;q<4;q++) y4[q] = *(const float4*)(g_y + off + q*4);
                }
            }
        };

        auto stsA = [&](int b){
            uint32_t d = smb + b*(BUF_Wc*4) + am*80 + akh*2;
            if(!apred){
                sts128w(d,        0,0,0,0); sts128w(d+16,        0,0,0,0);
                sts128w(d+AL_W*4, 0,0,0,0); sts128w(d+AL_W*4+16, 0,0,0,0);
                return;
            }
            __half hh[16], ll[16];
            const float* af = (const float*)a4;
            const float* yf = (const float*)y4;
            #pragma unroll
            for(int j=0;j<16;j++){
                float v = af[j];
                if(NORM){
                    int c = acbase + j;
                    v = (v - mymn)*myrs*s_w[c] + s_b[c];
                    v = (v >= 0.f) ? v : 0.25f*v;
                    if(MODE==M_CT) v += yf[j];
                }
                __half h = __float2half_rn(v);
                hh[j] = h;
                ll[j] = __float2half_rn(v - __half2float(h));
            }
            sts128w(d,    packh2(hh[0],hh[1]),  packh2(hh[2],hh[3]),  packh2(hh[4],hh[5]),  packh2(hh[6],hh[7]));
            sts128w(d+16, packh2(hh[8],hh[9]),  packh2(hh[10],hh[11]),packh2(hh[12],hh[13]),packh2(hh[14],hh[15]));
            sts128w(d+AL_W*4,    packh2(ll[0],ll[1]),  packh2(ll[2],ll[3]),  packh2(ll[4],ll[5]),  packh2(ll[6],ll[7]));
            sts128w(d+AL_W*4+16, packh2(ll[8],ll[9]),  packh2(ll[10],ll[11]),packh2(ll[12],ll[13]),packh2(ll[14],ll[15]));
        };

        loadA(0);
        cpB(0, 0);
        CP_COMMIT();
        for(int ch=0; ch<KCHUNKS; ch++){
            stsA(ch&1);
            if(ch+1 < KCHUNKS){ cpB(ch+1, (ch+1)&1); CP_COMMIT(); CP_WAIT1(); }
            else { CP_WAIT0(); }
            __syncthreads();
            if(ch+1 < KCHUNKS) loadA(ch+1);
            mma_chunk(ch&1);
            __syncthreads();
        }
    }

    // ---- staged epilogue: smem C tile then coalesced global store ----
    float* Cs = (float*)dsm;   // [128][BN+1]
    #pragma unroll
    for(int mi=0;mi<2;mi++){
        int rl = warp_m*32 + mi*16 + lr;
        #pragma unroll
        for(int ni=0;ni<NI;ni++){
            int cl = warp_n*(BN/2) + ni*8 + 2*lc;
            #pragma unroll
            for(int rr=0;rr<2;rr++){
                Cs[(rl+rr*8)*(BN+1) + cl]   = acc[mi][ni][rr*2];
                Cs[(rl+rr*8)*(BN+1) + cl+1] = acc[mi][ni][rr*2+1];
            }
        }
    }
    __syncthreads();

    if(MODE==M_CT){
        int n = row0 >> 9, p0 = row0 & 511;
        #pragma unroll 4
        for(int i=tid;i<64*128;i+=256){
            int o = i>>7, m = i&127;
            size_t idx = ((size_t)o*F + n)*T + p0 + m;
            outp[idx] = Cs[m*(BN+1)+o] + bias[o] + xs[idx];
        }
    } else if(MODE==M_SRU){
        int d = col0>>7;
        #pragma unroll 4
        for(int i=tid;i<128*BN;i+=256){
            int m = i/BN, o = i%BN;
            g_U[(size_t)d*U_STRIDE + (size_t)(row0+m)*128 + o] = Cs[m*(BN+1)+o];
        }
    } else {
        float* dst = (MODE==M_C1)? g_a1 : (MODE==M_C2)? g_a2 : g_a3r;
        const int stride = (MODE==M_C3)? 64 : 128;
        #pragma unroll 4
        for(int i=tid;i<128*BN;i+=256){
            int m = i/BN, o = i%BN;
            dst[(size_t)(row0+m)*stride + col0 + o] = Cs[m*(BN+1)+o] + bias[col0+o];
        }
    }
}

// ---------------- SRU scan (1-step prefetch, raw store) ----------------
__global__ void k_scan(const float* __restrict__ sruv, const float* __restrict__ srub){
    int w = (blockIdx.x*blockDim.x + threadIdx.x) >> 5;
    int h = threadIdx.x & 31;
    int d = w >> 8; int n = w & 255;
    float vf = sruv[d*64 + h];
    float vr = sruv[d*64 + 32 + h];
    float bf = srub[d*64 + h];
    float br = srub[d*64 + 32 + h];
    float st = 0.f;
    const float* Ubase = g_U + (size_t)d*U_STRIDE + (size_t)n*128;
    int l = d ? (LL-1) : 0;
    const float* u = Ubase + (size_t)l*(256*128);
    float u0=u[h], u1=u[32+h], u2=u[64+h], u3=u[96+h];
    for(int s=0;s<LL;s++){
        float n0=0,n1=0,n2=0,n3=0;
        int ln = 0;
        if(s+1 < LL){
            ln = d ? (LL-2-s) : (s+1);
            const float* un = Ubase + (size_t)ln*(256*128);
            n0=un[h]; n1=un[32+h]; n2=un[64+h]; n3=un[96+h];
        }
        float f  = sigf(u1 + vf*st + bf);
        float cn = f*st + (1.f-f)*u0;
        float rr = sigf(u2 + vr*st + br);
        float hv = rr*cn + (1.f-rr)*u3;
        st = cn;
        g_y[((size_t)n*LL + l)*64 + d*32 + h] = hv;
        l = ln; u0=n0; u1=n1; u2=n2; u3=n3;
    }
}

// ---------------- per-sample layernorm stats ----------------
__global__ void k_stats(int which){
    const float* buf = (which==0) ? g_a1 : (which==1) ? g_a2 : g_a3r;
    int chn = (which==2) ? 64 : 128;
    int n = blockIdx.x;
    int len = LL*chn;
    size_t base = (size_t)n * len;
    double s=0.0, q=0.0;
    for(int i=threadIdx.x;i<len;i+=256){ double v = buf[base+i]; s += v; q += v*v; }
    __shared__ double shs[256], shq[256];
    int tid = threadIdx.x;
    shs[tid]=s; shq[tid]=q; __syncthreads();
    for(int o=128;o>0;o>>=1){ if(tid<o){shs[tid]+=shs[tid+o]; shq[tid]+=shq[tid+o];} __syncthreads(); }
    if(tid==0){
        double m = shs[0]/len;
        double v = shq[0]/len - m*m;
        g_stats[which][n*2]   = (float)m;
        g_stats[which][n*2+1] = rsqrtf((float)v + EPSV);
    }
}

// ---------------- launcher ----------------
extern "C" void kernel_launch(void* const* d_in, const int* in_sizes, int n_in,
                              void* d_out, int out_size){
    const float* x    = (const float*)d_in[0];
    const float* gn0w = (const float*)d_in[1];
    const float* gn0b = (const float*)d_in[2];
    const float* sruw = (const float*)d_in[3];
    const float* sruv = (const float*)d_in[4];
    const float* srub = (const float*)d_in[5];
    const float* c1w  = (const float*)d_in[6];
    const float* c1b  = (const float*)d_in[7];
    const float* gn1w = (const float*)d_in[8];
    const float* gn1b = (const float*)d_in[9];
    const float* c2w  = (const float*)d_in[10];
    const float* c2b  = (const float*)d_in[11];
    const float* gn2w = (const float*)d_in[12];
    const float* gn2b = (const float*)d_in[13];
    const float* c3w  = (const float*)d_in[14];
    const float* c3b  = (const float*)d_in[15];
    const float* gn3w = (const float*)d_in[16];
    const float* gn3b = (const float*)d_in[17];
    const float* ctw  = (const float*)d_in[18];
    const float* ctb  = (const float*)d_in[19];
    float* out = (float*)d_out;

    const int smem128 = 2*(BH_W + 2*128*20)*4;   // 81920
    const int smem64  = 2*(BH_W + 2*64*20)*4;    // 61440
    cudaFuncSetAttribute(k_mma<M_SRU,128,14,448>, cudaFuncAttributeMaxDynamicSharedMemorySize, smem128);
    cudaFuncSetAttribute(k_mma<M_C1 ,128, 2, 64>, cudaFuncAttributeMaxDynamicSharedMemorySize, smem128);
    cudaFuncSetAttribute(k_mma<M_C2 ,128,28,896>, cudaFuncAttributeMaxDynamicSharedMemorySize, smem128);
    cudaFuncSetAttribute(k_mma<M_C3 , 64, 4,128>, cudaFuncAttributeMaxDynamicSharedMemorySize, smem64);
    cudaFuncSetAttribute(k_mma<M_CT , 64,14,448>, cudaFuncAttributeMaxDynamicSharedMemorySize, smem64);

    k_red0 <<<512,256>>>(x);
    k_red0b<<<1,256>>>();
    k_prep <<<1072,256>>>(c1w, c2w, c3w, ctw, sruw);
    k_xn   <<<dim3(16,256),256>>>(x, gn0w, gn0b);

    k_mma<M_SRU,128,14,448><<<dim3(2,M_ROWS/128),256,smem128>>>(nullptr, nullptr, nullptr, nullptr, nullptr);
    k_scan <<<128,128>>>(sruv, srub);

    k_mma<M_C1,128,2,64>  <<<dim3(1,M_ROWS/128),256,smem128>>>(c1b, nullptr, nullptr, nullptr, nullptr);
    k_stats<<<F,256>>>(0);

    k_mma<M_C2,128,28,896><<<dim3(1,M_ROWS/128),256,smem128>>>(c2b, nullptr, nullptr, gn1w, gn1b);
    k_stats<<<F,256>>>(1);

    k_mma<M_C3,64,4,128> <<<dim3(1,M_ROWS/128),256,smem64>>>(c3b, nullptr, nullptr, gn2w, gn2b);
    k_stats<<<F,256>>>(2);

    k_mma<M_CT,64,14,448><<<dim3(1,(F*T)/128),256,smem64>>>(ctb, x, out, gn3w, gn3b);
}

// round 12
// speedup vs baseline: 1.0336x; 1.0336x over previous
#include <cuda_runtime.h>
#include <cuda_fp16.h>
#include <math.h>
#include <stdint.h>

// Problem constants
#define C0 64
#define T  512
#define F  256
#define LL 506
#define KW 7
#define C2 128
#define M_ROWS (F*LL)          // 129536
#define U_STRIDE (M_ROWS*128)  // 16580608
#define EPSV 1e-6f

// ---------------- scratch ----------------
__device__ __half g_X2h[T*F*C0],  g_X2l[T*F*C0];
__device__ float  g_U  [2*M_ROWS*128];
__device__ float  g_y  [M_ROWS*C0];      // raw SRU output
__device__ float  g_a1 [M_ROWS*C2];      // raw c1 out (biased)
__device__ float  g_a2 [M_ROWS*C2];      // raw c2 out (biased)
__device__ float  g_a3r[M_ROWS*C0];      // raw c3 out (biased)
__device__ double g_part[1024];
__device__ float  g_stats0[2];
__device__ float  g_stats[3][F*2];
__device__ double g_pstat[3][F][2];      // fused stats partials (sum, sumsq)
// fp16 hi/lo split, K-major weights: [o][k]
__device__ __half g_wsruh[256*448], g_wsrul[256*448];
__device__ __half g_w2h [128*896],  g_w2l [128*896];
__device__ __half g_w1h [128*64],   g_w1l [128*64];
__device__ __half g_w3h [64*128],   g_w3l [64*128];
__device__ __half g_wcth[64*448],   g_wctl[64*448];

__device__ __forceinline__ float sigf(float v){ return 1.f/(1.f+__expf(-v)); }
__device__ __forceinline__ void split16(float v, __half* hp, __half* lp){
    __half h = __float2half_rn(v);
    *hp = h;
    *lp = __float2half_rn(v - __half2float(h));
}
__device__ __forceinline__ uint32_t smem_u32(const void* p){
    uint32_t a;
    asm("{ .reg .u64 t; cvta.to.shared.u64 t, %1; cvt.u32.u64 %0, t; }" : "=r"(a) : "l"(p));
    return a;
}
__device__ __forceinline__ void cp16(uint32_t dst, const void* src, bool pred){
    int sz = pred ? 16 : 0;
    asm volatile("cp.async.cg.shared.global [%0], [%1], 16, %2;" :: "r"(dst), "l"(src), "r"(sz) : "memory");
}
#define CP_COMMIT() asm volatile("cp.async.commit_group;" ::: "memory")
#define CP_WAIT1()  asm volatile("cp.async.wait_group 1;" ::: "memory")
#define CP_WAIT0()  asm volatile("cp.async.wait_group 0;" ::: "memory")

__device__ __forceinline__ void ldsm4(uint32_t* r, uint32_t addr){
    asm volatile("ldmatrix.sync.aligned.m8n8.x4.shared.b16 {%0,%1,%2,%3}, [%4];"
        : "=r"(r[0]),"=r"(r[1]),"=r"(r[2]),"=r"(r[3]) : "r"(addr));
}
__device__ __forceinline__ void sts128w(uint32_t a, uint32_t x,uint32_t y,uint32_t z,uint32_t w){
    asm volatile("st.shared.v4.b32 [%0], {%1,%2,%3,%4};" :: "r"(a),"r"(x),"r"(y),"r"(z),"r"(w) : "memory");
}
__device__ __forceinline__ uint32_t packh2(__half a, __half b){
    return (uint32_t)__half_as_ushort(a) | ((uint32_t)__half_as_ushort(b) << 16);
}

// ---------------- gn0 reductions ----------------
__global__ void k_red0(const float* __restrict__ x){
    double s=0.0, q=0.0;
    for(int i = blockIdx.x*256 + threadIdx.x; i < T*F*C0; i += 512*256){
        double v = x[i]; s += v; q += v*v;
    }
    __shared__ double shs[256], shq[256];
    int tid = threadIdx.x;
    shs[tid]=s; shq[tid]=q; __syncthreads();
    for(int o=128;o>0;o>>=1){ if(tid<o){shs[tid]+=shs[tid+o]; shq[tid]+=shq[tid+o];} __syncthreads(); }
    if(tid==0){ g_part[blockIdx.x*2]=shs[0]; g_part[blockIdx.x*2+1]=shq[0]; }
}
__global__ void k_red0b(){
    double s=0.0, q=0.0;
    int tid = threadIdx.x;
    for(int b=tid;b<512;b+=256){ s += g_part[2*b]; q += g_part[2*b+1]; }
    __shared__ double shs[256], shq[256];
    shs[tid]=s; shq[tid]=q; __syncthreads();
    for(int o=128;o>0;o>>=1){ if(tid<o){shs[tid]+=shs[tid+o]; shq[tid]+=shq[tid+o];} __syncthreads(); }
    if(tid==0){
        double n = (double)T*F*C0;
        double m = shs[0]/n;
        double v = shq[0]/n - m*m;
        g_stats0[0] = (float)m;
        g_stats0[1] = rsqrtf((float)v + EPSV);
    }
}

// ---------------- weight prep + pstat zero ----------------
__global__ void k_prep(const float* __restrict__ w1, const float* __restrict__ w2,
                       const float* __restrict__ w3, const float* __restrict__ wc,
                       const float* __restrict__ sw){
    int i = blockIdx.x*blockDim.x + threadIdx.x;
    if(i < 1536) ((double*)g_pstat)[i] = 0.0;
    if(i < 114688){
        int o=i/448, kl=i%448, k7=kl>>6, c=kl&63;
        float v = sw[(o>>7)*57344 + (c*7+k7)*128 + (o&127)];
        split16(v, &g_wsruh[i], &g_wsrul[i]); return;
    }
    i -= 114688;
    if(i < 114688){
        int o=i/896, kl=i%896, k7=kl>>7, c=kl&127;
        split16(w2[o*896 + c*7 + k7], &g_w2h[i], &g_w2l[i]); return;
    }
    i -= 114688;
    if(i < 8192){ split16(w1[i], &g_w1h[i], &g_w1l[i]); return; }
    i -= 8192;
    if(i < 8192){ split16(w3[i], &g_w3h[i], &g_w3l[i]); return; }
    i -= 8192;
    if(i < 28672){
        int o=i/448, kl=i%448, k7=kl>>6, c=kl&63;
        split16(wc[c*448 + o*7 + k7], &g_wcth[i], &g_wctl[i]);
    }
}

// ---------------- gn0 apply + transpose to [t][f][c], split store ----------------
__global__ void k_xn(const float* __restrict__ x, const float* __restrict__ w, const float* __restrict__ b){
    __shared__ float sm[32*65];
    int t0 = blockIdx.x*32;
    int f  = blockIdx.y;
    int tid = threadIdx.x;
    float mean = g_stats0[0], rstd = g_stats0[1];
    #pragma unroll
    for(int rep=0;rep<8;rep++){
        int lin = tid + rep*256;
        int c = lin >> 5, tl = lin & 31;
        float v = x[((size_t)c*F + f)*T + t0 + tl];
        v = (v-mean)*rstd*w[c] + b[c];
        sm[tl*65 + c] = v;
    }
    __syncthreads();
    #pragma unroll
    for(int rep=0;rep<8;rep++){
        int lin = tid + rep*256;
        int c = lin & 63, tl = lin >> 6;
        size_t idx = ((size_t)(t0+tl)*F + f)*C0 + c;
        split16(sm[tl*65 + c], &g_X2h[idx], &g_X2l[idx]);
    }
}

// ---------------- fp16x3 mma.sync GEMM with fused A-transform + fused stats ----------------
enum { M_SRU=0, M_C1=1, M_C2=2, M_C3=3, M_CT=4 };

__device__ __forceinline__ void mma16(float* c, const uint32_t* a, const uint32_t* b){
    asm volatile(
        "mma.sync.aligned.m16n8k16.row.col.f32.f16.f16.f32 "
        "{%0,%1,%2,%3},{%4,%5,%6,%7},{%8,%9},{%0,%1,%2,%3};"
        : "+f"(c[0]), "+f"(c[1]), "+f"(c[2]), "+f"(c[3])
        : "r"(a[0]), "r"(a[1]), "r"(a[2]), "r"(a[3]), "r"(b[0]), "r"(b[1]));
}

// smem layout (32-bit words), rows padded to 40 halfs (80 B)
#define AH_W 0
#define AL_W (128*20)              // 2560
#define BH_W (2*128*20)            // 5120

template<int MODE, int BN, int KCHUNKS, int KTOT>
__global__ void __launch_bounds__(256,2)
k_mma(const float* __restrict__ bias, const float* __restrict__ xs, float* __restrict__ outp,
      const float* __restrict__ nw, const float* __restrict__ nb){
    extern __shared__ uint32_t dsm[];
    __shared__ int s_aux[128];
    __shared__ float s_w[128], s_b[128], s_mn[128], s_rs[128];
    constexpr int NI = BN/16;
    constexpr int BUF_Wc = BH_W + 2*BN*20;
    constexpr bool NORM = (MODE==M_C2 || MODE==M_C3 || MODE==M_CT);
    constexpr int SIDX = (MODE==M_C2)?0 : (MODE==M_C3)?1 : 2;
    constexpr int OSIDX = (MODE==M_C1)?0 : (MODE==M_C2)?1 : 2;
    constexpr bool OSTAT = (MODE==M_C1 || MODE==M_C2 || MODE==M_C3);
    constexpr int CHN  = (MODE==M_CT)?64 : 128;

    const int tid = threadIdx.x, lane = tid & 31, wid = tid >> 5;
    const int warp_m = wid & 3, warp_n = wid >> 2;
    const int lr = lane >> 2, lc = lane & 3;
    const int col0 = blockIdx.x * BN;
    const int row0 = blockIdx.y * 128;
    const uint32_t smb = smem_u32(dsm);
    // ldmatrix lane geometry
    const int rin = lane & 7, tt = lane >> 3;
    const int a_row = (tt&1)*8 + rin;
    const int a_kb  = (tt>>1)*16;
    const int b_nt  = (tt>>1)*8;
    const int b_kb  = (tt&1)*16;

    const __half* BpH = (MODE==M_SRU)? g_wsruh: (MODE==M_C1)? g_w1h : (MODE==M_C2)? g_w2h: (MODE==M_C3)? g_w3h: g_wcth;
    const __half* BpL = (MODE==M_SRU)? g_wsrul: (MODE==M_C1)? g_w1l : (MODE==M_C2)? g_w2l: (MODE==M_C3)? g_w3l: g_wctl;
    const float*  Araw = (MODE==M_C1)? g_y : (MODE==M_C2)? g_a1 : (MODE==M_C3)? g_a2 : g_a3r;

    if(MODE==M_C2 || MODE==M_CT){
        if(tid<128){
            int r = row0 + tid;
            s_aux[tid] = (MODE==M_C2) ? (r % LL) : (r & 511);
        }
    }
    if(NORM){
        if(tid < CHN){ s_w[tid] = nw[tid]; s_b[tid] = nb[tid]; }
        if(tid < 128){
            int n = (MODE==M_CT) ? ((row0+tid)>>9) : ((row0+tid)/LL);
            s_mn[tid] = g_stats[SIDX][2*n];
            s_rs[tid] = g_stats[SIDX][2*n+1];
        }
    }
    __syncthreads();

    // B cp.async issue (shared by both paths)
    auto cpB = [&](int ch, int b){
        const int kbase = ch*32;
        const uint32_t base = smb + b*(BUF_Wc*4);
        #pragma unroll
        for(int rep=0;rep<BN/64;rep++){
            int o = rep*64 + (tid>>2), k4 = tid&3;
            size_t off = (size_t)(col0+o)*KTOT + kbase + k4*8;
            uint32_t d = base + BH_W*4 + o*80 + k4*16;
            cp16(d,               BpH+off, true);
            cp16(d + BN*20*4,     BpL+off, true);
        }
    };

    float acc[2][NI][4] = {};

    // ---- mma on one buffered chunk (interleaved: acc reuse distance = 8) ----
    auto mma_chunk = [&](int b){
        const uint32_t bufb = smb + b*(BUF_Wc*4);
        #pragma unroll
        for(int k16=0;k16<2;k16++){
            uint32_t ah[2][4], al[2][4];
            #pragma unroll
            for(int mi=0;mi<2;mi++){
                uint32_t ra = bufb + (warp_m*32 + mi*16 + a_row)*80 + k16*32 + a_kb;
                ldsm4(ah[mi], ra);
                ldsm4(al[mi], ra + AL_W*4);
            }
            #pragma unroll
            for(int pg=0; pg<NI/4; pg++){
                const int p0 = 2*pg, p1 = 2*pg+1;
                uint32_t rb0 = bufb + BH_W*4 + (warp_n*(BN/2) + p0*16 + b_nt + rin)*80 + k16*32 + b_kb;
                uint32_t rb1 = bufb + BH_W*4 + (warp_n*(BN/2) + p1*16 + b_nt + rin)*80 + k16*32 + b_kb;
                uint32_t bh0[4], bl0[4], bh1[4], bl1[4];
                ldsm4(bh0, rb0); ldsm4(bl0, rb0 + BN*20*4);
                ldsm4(bh1, rb1); ldsm4(bl1, rb1 + BN*20*4);
                mma16(acc[0][2*p0],   ah[0], bh0);   mma16(acc[1][2*p0],   ah[1], bh0);
                mma16(acc[0][2*p0+1], ah[0], bh0+2); mma16(acc[1][2*p0+1], ah[1], bh0+2);
                mma16(acc[0][2*p1],   ah[0], bh1);   mma16(acc[1][2*p1],   ah[1], bh1);
                mma16(acc[0][2*p1+1], ah[0], bh1+2); mma16(acc[1][2*p1+1], ah[1], bh1+2);
                mma16(acc[0][2*p0],   al[0], bh0);   mma16(acc[1][2*p0],   al[1], bh0);
                mma16(acc[0][2*p0+1], al[0], bh0+2); mma16(acc[1][2*p0+1], al[1], bh0+2);
                mma16(acc[0][2*p1],   al[0], bh1);   mma16(acc[1][2*p1],   al[1], bh1);
                mma16(acc[0][2*p1+1], al[0], bh1+2); mma16(acc[1][2*p1+1], al[1], bh1+2);
                mma16(acc[0][2*p0],   ah[0], bl0);   mma16(acc[1][2*p0],   ah[1], bl0);
                mma16(acc[0][2*p0+1], ah[0], bl0+2); mma16(acc[1][2*p0+1], ah[1], bl0+2);
                mma16(acc[0][2*p1],   ah[0], bl1);   mma16(acc[1][2*p1],   ah[1], bl1);
                mma16(acc[0][2*p1+1], ah[0], bl1+2); mma16(acc[1][2*p1+1], ah[1], bl1+2);
            }
        }
    };

    if(MODE==M_SRU){
        // ---- cp.async A path (pre-split X2) ----
        auto issue = [&](int ch, int b){
            int k7 = ch>>1, c0 = (ch&1)*32;
            const uint32_t base = smb + b*(BUF_Wc*4);
            #pragma unroll
            for(int rep=0;rep<2;rep++){
                int lin = tid + rep*256;
                int m = lin>>2, k4 = lin&3;
                size_t off=(size_t)(row0+m+k7*256)*64 + c0 + k4*8;
                uint32_t d = base + m*80 + k4*16;
                cp16(d,            g_X2h+off, true);
                cp16(d + AL_W*4,   g_X2l+off, true);
            }
            cpB(ch, b);
        };
        issue(0, 0);
        CP_COMMIT();
        for(int ch=0; ch<KCHUNKS; ch++){
            if(ch+1 < KCHUNKS){ issue(ch+1, (ch+1)&1); CP_COMMIT(); CP_WAIT1(); }
            else { CP_WAIT0(); }
            __syncthreads();
            mma_chunk(ch&1);
            __syncthreads();
        }
    } else {
        // ---- register A path with fused transform ----
        const int am = tid>>1, akh = (tid&1)*16;
        const float mymn = NORM ? s_mn[am] : 0.f;
        const float myrs = NORM ? s_rs[am] : 0.f;
        float4 a4[4], y4[4];
        bool apred = true;
        int acbase = 0;

        auto loadA = [&](int ch){
            size_t off = 0;
            if(MODE==M_C1){
                apred = true;
                off = (size_t)(row0+am)*64 + ch*32 + akh;
            } else if(MODE==M_C2){
                int k7 = ch>>2, c0 = (ch&3)*32;
                int l2 = s_aux[am] + k7 - 3;
                apred = ((unsigned)l2 < LL);
                off = (size_t)(row0+am+k7-3)*128 + c0 + akh;
                acbase = c0 + akh;
            } else if(MODE==M_C3){
                apred = true;
                off = (size_t)(row0+am)*128 + ch*32 + akh;
                acbase = ch*32 + akh;
            } else { // M_CT
                int k7 = ch>>1, c0 = (ch&1)*32;
                int p2 = s_aux[am] - k7;
                apred = ((unsigned)p2 < LL);
                int n = (row0+am)>>9;
                off = ((size_t)n*LL + p2)*64 + c0 + akh;
                acbase = c0 + akh;
            }
            if(apred){
                #pragma unroll
                for(int q=0;q<4;q++) a4[q] = *(const float4*)(Araw + off + q*4);
                if(MODE==M_CT){
                    #pragma unroll
                    for(int q=0;q<4;q++) y4[q] = *(const float4*)(g_y + off + q*4);
                }
            }
        };

        auto stsA = [&](int b){
            uint32_t d = smb + b*(BUF_Wc*4) + am*80 + akh*2;
            if(!apred){
                sts128w(d,        0,0,0,0); sts128w(d+16,        0,0,0,0);
                sts128w(d+AL_W*4, 0,0,0,0); sts128w(d+AL_W*4+16, 0,0,0,0);
                return;
            }
            __half hh[16], ll[16];
            const float* af = (const float*)a4;
            const float* yf = (const float*)y4;
            #pragma unroll
            for(int j=0;j<16;j++){
                float v = af[j];
                if(NORM){
                    int c = acbase + j;
                    v = (v - mymn)*myrs*s_w[c] + s_b[c];
                    v = (v >= 0.f) ? v : 0.25f*v;
                    if(MODE==M_CT) v += yf[j];
                }
                __half h = __float2half_rn(v);
                hh[j] = h;
                ll[j] = __float2half_rn(v - __half2float(h));
            }
            sts128w(d,    packh2(hh[0],hh[1]),  packh2(hh[2],hh[3]),  packh2(hh[4],hh[5]),  packh2(hh[6],hh[7]));
            sts128w(d+16, packh2(hh[8],hh[9]),  packh2(hh[10],hh[11]),packh2(hh[12],hh[13]),packh2(hh[14],hh[15]));
            sts128w(d+AL_W*4,    packh2(ll[0],ll[1]),  packh2(ll[2],ll[3]),  packh2(ll[4],ll[5]),  packh2(ll[6],ll[7]));
            sts128w(d+AL_W*4+16, packh2(ll[8],ll[9]),  packh2(ll[10],ll[11]),packh2(ll[12],ll[13]),packh2(ll[14],ll[15]));
        };

        loadA(0);
        cpB(0, 0);
        CP_COMMIT();
        for(int ch=0; ch<KCHUNKS; ch++){
            stsA(ch&1);
            if(ch+1 < KCHUNKS){ cpB(ch+1, (ch+1)&1); CP_COMMIT(); CP_WAIT1(); }
            else { CP_WAIT0(); }
            __syncthreads();
            if(ch+1 < KCHUNKS) loadA(ch+1);
            mma_chunk(ch&1);
            __syncthreads();
        }
    }

    // ---- staged epilogue: smem C tile, coalesced float4 stores, fused stats ----
    float* Cs = (float*)dsm;   // [128][BN+1]
    #pragma unroll
    for(int mi=0;mi<2;mi++){
        int rl = warp_m*32 + mi*16 + lr;
        #pragma unroll
        for(int ni=0;ni<NI;ni++){
            int cl = warp_n*(BN/2) + ni*8 + 2*lc;
            #pragma unroll
            for(int rr=0;rr<2;rr++){
                Cs[(rl+rr*8)*(BN+1) + cl]   = acc[mi][ni][rr*2];
                Cs[(rl+rr*8)*(BN+1) + cl+1] = acc[mi][ni][rr*2+1];
            }
        }
    }
    __syncthreads();

    if(MODE==M_CT){
        int n = row0 >> 9, p0 = row0 & 511;
        #pragma unroll 4
        for(int i = tid*4; i < 64*128; i += 1024){
            int o = i>>7, m = i&127;
            size_t idx = ((size_t)o*F + n)*T + p0 + m;
            float4 xv = *(const float4*)(xs + idx);
            float bo = bias[o];
            float4 v;
            v.x = Cs[(m  )*(BN+1)+o] + bo + xv.x;
            v.y = Cs[(m+1)*(BN+1)+o] + bo + xv.y;
            v.z = Cs[(m+2)*(BN+1)+o] + bo + xv.z;
            v.w = Cs[(m+3)*(BN+1)+o] + bo + xv.w;
            *(float4*)(outp + idx) = v;
        }
    } else if(MODE==M_SRU){
        int d = col0>>7;
        #pragma unroll 4
        for(int i = tid*4; i < 128*BN; i += 1024){
            int m = i/BN, o = i%BN;
            const float* cr = &Cs[m*(BN+1)+o];
            float4 v = make_float4(cr[0], cr[1], cr[2], cr[3]);
            *(float4*)&g_U[(size_t)d*U_STRIDE + (size_t)(row0+m)*128 + o] = v;
        }
    } else {
        float* dst = (MODE==M_C1)? g_a1 : (MODE==M_C2)? g_a2 : g_a3r;
        const int stride = (MODE==M_C3)? 64 : 128;
        const int n0 = row0 / LL;
        const int split = (n0+1)*LL - row0;   // rows [0,split) -> n0
        float s0=0.f,q0=0.f,s1=0.f,q1=0.f;
        #pragma unroll 4
        for(int i = tid*4; i < 128*BN; i += 1024){
            int m = i/BN, o = i%BN;
            const float* cr = &Cs[m*(BN+1)+o];
            const float* br = &bias[col0+o];
            float4 v = make_float4(cr[0]+br[0], cr[1]+br[1], cr[2]+br[2], cr[3]+br[3]);
            *(float4*)&dst[(size_t)(row0+m)*stride + col0 + o] = v;
            if(OSTAT){
                float ls = v.x + v.y + v.z + v.w;
                float lq = v.x*v.x + v.y*v.y + v.z*v.z + v.w*v.w;
                if(m < split){ s0 += ls; q0 += lq; } else { s1 += ls; q1 += lq; }
            }
        }
        if(OSTAT){
            #pragma unroll
            for(int off=16; off; off>>=1){
                s0 += __shfl_down_sync(0xFFFFFFFFu, s0, off);
                q0 += __shfl_down_sync(0xFFFFFFFFu, q0, off);
                s1 += __shfl_down_sync(0xFFFFFFFFu, s1, off);
                q1 += __shfl_down_sync(0xFFFFFFFFu, q1, off);
            }
            __syncthreads();
            float* red = (float*)dsm + 128*(BN+1);
            if(lane==0){ red[wid]=s0; red[8+wid]=q0; red[16+wid]=s1; red[24+wid]=q1; }
            __syncthreads();
            if(tid==0){
                float S0=0,Q0=0,S1=0,Q1=0;
                #pragma unroll
                for(int w2=0;w2<8;w2++){ S0+=red[w2]; Q0+=red[8+w2]; S1+=red[16+w2]; Q1+=red[24+w2]; }
                atomicAdd(&g_pstat[OSIDX][n0][0], (double)S0);
                atomicAdd(&g_pstat[OSIDX][n0][1], (double)Q0);
                if(split < 128){
                    atomicAdd(&g_pstat[OSIDX][n0+1][0], (double)S1);
                    atomicAdd(&g_pstat[OSIDX][n0+1][1], (double)Q1);
                }
            }
        }
    }
}

// ---------------- stats finalize ----------------
__global__ void k_fin(int which){
    int n = blockIdx.x*blockDim.x + threadIdx.x;
    if(n < F){
        int len = (which==2) ? LL*64 : LL*128;
        double s = g_pstat[which][n][0], q = g_pstat[which][n][1];
        double m = s/len;
        double v = q/len - m*m;
        g_stats[which][n*2]   = (float)m;
        g_stats[which][n*2+1] = rsqrtf((float)v + EPSV);
    }
}

// ---------------- SRU scan (1-step prefetch, raw store) ----------------
__global__ void k_scan(const float* __restrict__ sruv, const float* __restrict__ srub){
    int w = (blockIdx.x*blockDim.x + threadIdx.x) >> 5;
    int h = threadIdx.x & 31;
    int d = w >> 8; int n = w & 255;
    float vf = sruv[d*64 + h];
    float vr = sruv[d*64 + 32 + h];
    float bf = srub[d*64 + h];
    float br = srub[d*64 + 32 + h];
    float st = 0.f;
    const float* Ubase = g_U + (size_t)d*U_STRIDE + (size_t)n*128;
    int l = d ? (LL-1) : 0;
    const float* u = Ubase + (size_t)l*(256*128);
    float u0=u[h], u1=u[32+h], u2=u[64+h], u3=u[96+h];
    for(int s=0;s<LL;s++){
        float n0=0,n1=0,n2=0,n3=0;
        int ln = 0;
        if(s+1 < LL){
            ln = d ? (LL-2-s) : (s+1);
            const float* un = Ubase + (size_t)ln*(256*128);
            n0=un[h]; n1=un[32+h]; n2=un[64+h]; n3=un[96+h];
        }
        float f  = sigf(u1 + vf*st + bf);
        float cn = f*st + (1.f-f)*u0;
        float rr = sigf(u2 + vr*st + br);
        float hv = rr*cn + (1.f-rr)*u3;
        st = cn;
        g_y[((size_t)n*LL + l)*64 + d*32 + h] = hv;
        l = ln; u0=n0; u1=n1; u2=n2; u3=n3;
    }
}

// ---------------- launcher ----------------
extern "C" void kernel_launch(void* const* d_in, const int* in_sizes, int n_in,
                              void* d_out, int out_size){
    const float* x    = (const float*)d_in[0];
    const float* gn0w = (const float*)d_in[1];
    const float* gn0b = (const float*)d_in[2];
    const float* sruw = (const float*)d_in[3];
    const float* sruv = (const float*)d_in[4];
    const float* srub = (const float*)d_in[5];
    const float* c1w  = (const float*)d_in[6];
    const float* c1b  = (const float*)d_in[7];
    const float* gn1w = (const float*)d_in[8];
    const float* gn1b = (const float*)d_in[9];
    const float* c2w  = (const float*)d_in[10];
    const float* c2b  = (const float*)d_in[11];
    const float* gn2w = (const float*)d_in[12];
    const float* gn2b = (const float*)d_in[13];
    const float* c3w  = (const float*)d_in[14];
    const float* c3b  = (const float*)d_in[15];
    const float* gn3w = (const float*)d_in[16];
    const float* gn3b = (const float*)d_in[17];
    const float* ctw  = (const float*)d_in[18];
    const float* ctb  = (const float*)d_in[19];
    float* out = (float*)d_out;

    const int smem128 = 2*(BH_W + 2*128*20)*4;   // 81920
    const int smem64  = 2*(BH_W + 2*64*20)*4;    // 61440
    cudaFuncSetAttribute(k_mma<M_SRU,128,14,448>, cudaFuncAttributeMaxDynamicSharedMemorySize, smem128);
    cudaFuncSetAttribute(k_mma<M_C1 ,128, 2, 64>, cudaFuncAttributeMaxDynamicSharedMemorySize, smem128);
    cudaFuncSetAttribute(k_mma<M_C2 ,128,28,896>, cudaFuncAttributeMaxDynamicSharedMemorySize, smem128);
    cudaFuncSetAttribute(k_mma<M_C3 , 64, 4,128>, cudaFuncAttributeMaxDynamicSharedMemorySize, smem64);
    cudaFuncSetAttribute(k_mma<M_CT , 64,14,448>, cudaFuncAttributeMaxDynamicSharedMemorySize, smem64);

    k_red0 <<<512,256>>>(x);
    k_red0b<<<1,256>>>();
    k_prep <<<1072,256>>>(c1w, c2w, c3w, ctw, sruw);
    k_xn   <<<dim3(16,256),256>>>(x, gn0w, gn0b);

    k_mma<M_SRU,128,14,448><<<dim3(2,M_ROWS/128),256,smem128>>>(nullptr, nullptr, nullptr, nullptr, nullptr);
    k_scan <<<128,128>>>(sruv, srub);

    k_mma<M_C1,128,2,64>  <<<dim3(1,M_ROWS/128),256,smem128>>>(c1b, nullptr, nullptr, nullptr, nullptr);
    k_fin<<<1,256>>>(0);

    k_mma<M_C2,128,28,896><<<dim3(1,M_ROWS/128),256,smem128>>>(c2b, nullptr, nullptr, gn1w, gn1b);
    k_fin<<<1,256>>>(1);

    k_mma<M_C3,64,4,128> <<<dim3(1,M_ROWS/128),256,smem64>>>(c3b, nullptr, nullptr, gn2w, gn2b);
    k_fin<<<1,256>>>(2);

    k_mma<M_CT,64,14,448><<<dim3(1,(F*T)/128),256,smem64>>>(ctb, x, out, gn3w, gn3b);
}

// round 13
// speedup vs baseline: 1.1350x; 1.0981x over previous
#include <cuda_runtime.h>
#include <cuda_fp16.h>
#include <math.h>
#include <stdint.h>

// Problem constants
#define C0 64
#define T  512
#define F  256
#define LL 506
#define KW 7
#define C2 128
#define M_ROWS (F*LL)          // 129536
#define U_STRIDE (M_ROWS*128)  // 16580608
#define EPSV 1e-6f

// ---------------- scratch ----------------
__device__ __half g_X2h[T*F*C0],  g_X2l[T*F*C0];
__device__ float  g_U  [2*M_ROWS*128];
__device__ float  g_y  [M_ROWS*C0];      // raw SRU output
__device__ float  g_a1 [M_ROWS*C2];      // raw c1 out (biased)
__device__ float  g_a2 [M_ROWS*C2];      // raw c2 out (biased)
__device__ float  g_a3r[M_ROWS*C0];      // raw c3 out (biased)
__device__ double g_part[1024];
__device__ float  g_stats0[2];
__device__ float  g_stats[3][F*2];
__device__ double g_pstat[3][F][2];      // fused stats partials (sum, sumsq)
// fp16 hi/lo split, K-major weights: [o][k]
__device__ __half g_wsruh[256*448], g_wsrul[256*448];
__device__ __half g_w2h [128*896],  g_w2l [128*896];
__device__ __half g_w1h [128*64],   g_w1l [128*64];
__device__ __half g_w3h [64*128],   g_w3l [64*128];
__device__ __half g_wcth[64*448],   g_wctl[64*448];

__device__ __forceinline__ float sigf(float v){ return 1.f/(1.f+__expf(-v)); }
__device__ __forceinline__ void split16(float v, __half* hp, __half* lp){
    __half h = __float2half_rn(v);
    *hp = h;
    *lp = __float2half_rn(v - __half2float(h));
}
__device__ __forceinline__ uint32_t smem_u32(const void* p){
    uint32_t a;
    asm("{ .reg .u64 t; cvta.to.shared.u64 t, %1; cvt.u32.u64 %0, t; }" : "=r"(a) : "l"(p));
    return a;
}
__device__ __forceinline__ void cp16(uint32_t dst, const void* src, bool pred){
    int sz = pred ? 16 : 0;
    asm volatile("cp.async.cg.shared.global [%0], [%1], 16, %2;" :: "r"(dst), "l"(src), "r"(sz) : "memory");
}
#define CP_COMMIT() asm volatile("cp.async.commit_group;" ::: "memory")
#define CP_WAIT1()  asm volatile("cp.async.wait_group 1;" ::: "memory")
#define CP_WAIT0()  asm volatile("cp.async.wait_group 0;" ::: "memory")

__device__ __forceinline__ void ldsm4(uint32_t* r, uint32_t addr){
    asm volatile("ldmatrix.sync.aligned.m8n8.x4.shared.b16 {%0,%1,%2,%3}, [%4];"
        : "=r"(r[0]),"=r"(r[1]),"=r"(r[2]),"=r"(r[3]) : "r"(addr));
}
__device__ __forceinline__ void sts128w(uint32_t a, uint32_t x,uint32_t y,uint32_t z,uint32_t w){
    asm volatile("st.shared.v4.b32 [%0], {%1,%2,%3,%4};" :: "r"(a),"r"(x),"r"(y),"r"(z),"r"(w) : "memory");
}
__device__ __forceinline__ uint32_t packh2(__half a, __half b){
    return (uint32_t)__half_as_ushort(a) | ((uint32_t)__half_as_ushort(b) << 16);
}

// ---------------- gn0 reductions ----------------
__global__ void k_red0(const float* __restrict__ x){
    double s=0.0, q=0.0;
    for(int i = blockIdx.x*256 + threadIdx.x; i < T*F*C0; i += 512*256){
        double v = x[i]; s += v; q += v*v;
    }
    __shared__ double shs[256], shq[256];
    int tid = threadIdx.x;
    shs[tid]=s; shq[tid]=q; __syncthreads();
    for(int o=128;o>0;o>>=1){ if(tid<o){shs[tid]+=shs[tid+o]; shq[tid]+=shq[tid+o];} __syncthreads(); }
    if(tid==0){ g_part[blockIdx.x*2]=shs[0]; g_part[blockIdx.x*2+1]=shq[0]; }
}
__global__ void k_red0b(){
    double s=0.0, q=0.0;
    int tid = threadIdx.x;
    for(int b=tid;b<512;b+=256){ s += g_part[2*b]; q += g_part[2*b+1]; }
    __shared__ double shs[256], shq[256];
    shs[tid]=s; shq[tid]=q; __syncthreads();
    for(int o=128;o>0;o>>=1){ if(tid<o){shs[tid]+=shs[tid+o]; shq[tid]+=shq[tid+o];} __syncthreads(); }
    if(tid==0){
        double n = (double)T*F*C0;
        double m = shs[0]/n;
        double v = shq[0]/n - m*m;
        g_stats0[0] = (float)m;
        g_stats0[1] = rsqrtf((float)v + EPSV);
    }
}

// ---------------- weight prep + pstat zero ----------------
__global__ void k_prep(const float* __restrict__ w1, const float* __restrict__ w2,
                       const float* __restrict__ w3, const float* __restrict__ wc,
                       const float* __restrict__ sw){
    int i = blockIdx.x*blockDim.x + threadIdx.x;
    if(i < 1536) ((double*)g_pstat)[i] = 0.0;
    if(i < 114688){
        int o=i/448, kl=i%448, k7=kl>>6, c=kl&63;
        float v = sw[(o>>7)*57344 + (c*7+k7)*128 + (o&127)];
        split16(v, &g_wsruh[i], &g_wsrul[i]); return;
    }
    i -= 114688;
    if(i < 114688){
        int o=i/896, kl=i%896, k7=kl>>7, c=kl&127;
        split16(w2[o*896 + c*7 + k7], &g_w2h[i], &g_w2l[i]); return;
    }
    i -= 114688;
    if(i < 8192){ split16(w1[i], &g_w1h[i], &g_w1l[i]); return; }
    i -= 8192;
    if(i < 8192){ split16(w3[i], &g_w3h[i], &g_w3l[i]); return; }
    i -= 8192;
    if(i < 28672){
        int o=i/448, kl=i%448, k7=kl>>6, c=kl&63;
        split16(wc[c*448 + o*7 + k7], &g_wcth[i], &g_wctl[i]);
    }
}

// ---------------- gn0 apply + transpose to [t][f][c], split store ----------------
__global__ void k_xn(const float* __restrict__ x, const float* __restrict__ w, const float* __restrict__ b){
    __shared__ float sm[32*65];
    int t0 = blockIdx.x*32;
    int f  = blockIdx.y;
    int tid = threadIdx.x;
    float mean = g_stats0[0], rstd = g_stats0[1];
    #pragma unroll
    for(int rep=0;rep<8;rep++){
        int lin = tid + rep*256;
        int c = lin >> 5, tl = lin & 31;
        float v = x[((size_t)c*F + f)*T + t0 + tl];
        v = (v-mean)*rstd*w[c] + b[c];
        sm[tl*65 + c] = v;
    }
    __syncthreads();
    #pragma unroll
    for(int rep=0;rep<8;rep++){
        int lin = tid + rep*256;
        int c = lin & 63, tl = lin >> 6;
        size_t idx = ((size_t)(t0+tl)*F + f)*C0 + c;
        split16(sm[tl*65 + c], &g_X2h[idx], &g_X2l[idx]);
    }
}

// ---------------- fp16x3 mma.sync GEMM with fused A-transform + fused stats ----------------
enum { M_SRU=0, M_C1=1, M_C2=2, M_C3=3, M_CT=4 };

__device__ __forceinline__ void mma16(float* c, const uint32_t* a, const uint32_t* b){
    asm volatile(
        "mma.sync.aligned.m16n8k16.row.col.f32.f16.f16.f32 "
        "{%0,%1,%2,%3},{%4,%5,%6,%7},{%8,%9},{%0,%1,%2,%3};"
        : "+f"(c[0]), "+f"(c[1]), "+f"(c[2]), "+f"(c[3])
        : "r"(a[0]), "r"(a[1]), "r"(a[2]), "r"(a[3]), "r"(b[0]), "r"(b[1]));
}

// smem layout (32-bit words), rows padded to 40 halfs (80 B)
#define AH_W 0
#define AL_W (128*20)              // 2560
#define BH_W (2*128*20)            // 5120

template<int MODE, int BN, int KCHUNKS, int KTOT>
__global__ void __launch_bounds__(256,2)
k_mma(const float* __restrict__ bias, const float* __restrict__ xs, float* __restrict__ outp,
      const float* __restrict__ nw, const float* __restrict__ nb){
    extern __shared__ uint32_t dsm[];
    __shared__ int s_aux[128];
    __shared__ float s_w[128], s_b[128], s_mn[128], s_rs[128];
    constexpr int NI = BN/16;
    constexpr int BUF_Wc = BH_W + 2*BN*20;
    constexpr bool NORM = (MODE==M_C2 || MODE==M_C3 || MODE==M_CT);
    constexpr int SIDX = (MODE==M_C2)?0 : (MODE==M_C3)?1 : 2;
    constexpr int OSIDX = (MODE==M_C1)?0 : (MODE==M_C2)?1 : 2;
    constexpr bool OSTAT = (MODE==M_C1 || MODE==M_C2 || MODE==M_C3);
    constexpr int CHN  = (MODE==M_CT)?64 : 128;

    const int tid = threadIdx.x, lane = tid & 31, wid = tid >> 5;
    const int warp_m = wid & 3, warp_n = wid >> 2;
    const int lr = lane >> 2, lc = lane & 3;
    const int col0 = blockIdx.x * BN;
    const int row0 = blockIdx.y * 128;
    const uint32_t smb = smem_u32(dsm);
    // ldmatrix lane geometry
    const int rin = lane & 7, tt = lane >> 3;
    const int a_row = (tt&1)*8 + rin;
    const int a_kb  = (tt>>1)*16;
    const int b_nt  = (tt>>1)*8;
    const int b_kb  = (tt&1)*16;

    const __half* BpH = (MODE==M_SRU)? g_wsruh: (MODE==M_C1)? g_w1h : (MODE==M_C2)? g_w2h: (MODE==M_C3)? g_w3h: g_wcth;
    const __half* BpL = (MODE==M_SRU)? g_wsrul: (MODE==M_C1)? g_w1l : (MODE==M_C2)? g_w2l: (MODE==M_C3)? g_w3l: g_wctl;
    const float*  Araw = (MODE==M_C1)? g_y : (MODE==M_C2)? g_a1 : (MODE==M_C3)? g_a2 : g_a3r;

    if(MODE==M_C2 || MODE==M_CT){
        if(tid<128){
            int r = row0 + tid;
            s_aux[tid] = (MODE==M_C2) ? (r % LL) : (r & 511);
        }
    }
    if(NORM){
        if(tid < CHN){ s_w[tid] = nw[tid]; s_b[tid] = nb[tid]; }
        if(tid < 128){
            int n = (MODE==M_CT) ? ((row0+tid)>>9) : ((row0+tid)/LL);
            s_mn[tid] = g_stats[SIDX][2*n];
            s_rs[tid] = g_stats[SIDX][2*n+1];
        }
    }
    __syncthreads();

    // B cp.async issue (shared by both paths)
    auto cpB = [&](int ch, int b){
        const int kbase = ch*32;
        const uint32_t base = smb + b*(BUF_Wc*4);
        #pragma unroll
        for(int rep=0;rep<BN/64;rep++){
            int o = rep*64 + (tid>>2), k4 = tid&3;
            size_t off = (size_t)(col0+o)*KTOT + kbase + k4*8;
            uint32_t d = base + BH_W*4 + o*80 + k4*16;
            cp16(d,               BpH+off, true);
            cp16(d + BN*20*4,     BpL+off, true);
        }
    };

    float acc[2][NI][4] = {};

    // ---- mma on one buffered chunk (interleaved: acc reuse distance = 8) ----
    auto mma_chunk = [&](int b){
        const uint32_t bufb = smb + b*(BUF_Wc*4);
        #pragma unroll
        for(int k16=0;k16<2;k16++){
            uint32_t ah[2][4], al[2][4];
            #pragma unroll
            for(int mi=0;mi<2;mi++){
                uint32_t ra = bufb + (warp_m*32 + mi*16 + a_row)*80 + k16*32 + a_kb;
                ldsm4(ah[mi], ra);
                ldsm4(al[mi], ra + AL_W*4);
            }
            #pragma unroll
            for(int pg=0; pg<NI/4; pg++){
                const int p0 = 2*pg, p1 = 2*pg+1;
                uint32_t rb0 = bufb + BH_W*4 + (warp_n*(BN/2) + p0*16 + b_nt + rin)*80 + k16*32 + b_kb;
                uint32_t rb1 = bufb + BH_W*4 + (warp_n*(BN/2) + p1*16 + b_nt + rin)*80 + k16*32 + b_kb;
                uint32_t bh0[4], bl0[4], bh1[4], bl1[4];
                ldsm4(bh0, rb0); ldsm4(bl0, rb0 + BN*20*4);
                ldsm4(bh1, rb1); ldsm4(bl1, rb1 + BN*20*4);
                mma16(acc[0][2*p0],   ah[0], bh0);   mma16(acc[1][2*p0],   ah[1], bh0);
                mma16(acc[0][2*p0+1], ah[0], bh0+2); mma16(acc[1][2*p0+1], ah[1], bh0+2);
                mma16(acc[0][2*p1],   ah[0], bh1);   mma16(acc[1][2*p1],   ah[1], bh1);
                mma16(acc[0][2*p1+1], ah[0], bh1+2); mma16(acc[1][2*p1+1], ah[1], bh1+2);
                mma16(acc[0][2*p0],   al[0], bh0);   mma16(acc[1][2*p0],   al[1], bh0);
                mma16(acc[0][2*p0+1], al[0], bh0+2); mma16(acc[1][2*p0+1], al[1], bh0+2);
                mma16(acc[0][2*p1],   al[0], bh1);   mma16(acc[1][2*p1],   al[1], bh1);
                mma16(acc[0][2*p1+1], al[0], bh1+2); mma16(acc[1][2*p1+1], al[1], bh1+2);
                mma16(acc[0][2*p0],   ah[0], bl0);   mma16(acc[1][2*p0],   ah[1], bl0);
                mma16(acc[0][2*p0+1], ah[0], bl0+2); mma16(acc[1][2*p0+1], ah[1], bl0+2);
                mma16(acc[0][2*p1],   ah[0], bl1);   mma16(acc[1][2*p1],   ah[1], bl1);
                mma16(acc[0][2*p1+1], ah[0], bl1+2); mma16(acc[1][2*p1+1], ah[1], bl1+2);
            }
        }
    };

    if(MODE==M_SRU){
        // ---- cp.async A path (pre-split X2) ----
        auto issue = [&](int ch, int b){
            int k7 = ch>>1, c0 = (ch&1)*32;
            const uint32_t base = smb + b*(BUF_Wc*4);
            #pragma unroll
            for(int rep=0;rep<2;rep++){
                int lin = tid + rep*256;
                int m = lin>>2, k4 = lin&3;
                size_t off=(size_t)(row0+m+k7*256)*64 + c0 + k4*8;
                uint32_t d = base + m*80 + k4*16;
                cp16(d,            g_X2h+off, true);
                cp16(d + AL_W*4,   g_X2l+off, true);
            }
            cpB(ch, b);
        };
        issue(0, 0);
        CP_COMMIT();
        for(int ch=0; ch<KCHUNKS; ch++){
            if(ch+1 < KCHUNKS){ issue(ch+1, (ch+1)&1); CP_COMMIT(); CP_WAIT1(); }
            else { CP_WAIT0(); }
            __syncthreads();
            mma_chunk(ch&1);
            __syncthreads();
        }
    } else {
        // ---- register A path with fused transform ----
        const int am = tid>>1, akh = (tid&1)*16;
        const float mymn = NORM ? s_mn[am] : 0.f;
        const float myrs = NORM ? s_rs[am] : 0.f;
        float4 a4[4], y4[4];
        bool apred = true;
        int acbase = 0;

        auto loadA = [&](int ch){
            size_t off = 0;
            if(MODE==M_C1){
                apred = true;
                off = (size_t)(row0+am)*64 + ch*32 + akh;
            } else if(MODE==M_C2){
                int k7 = ch>>2, c0 = (ch&3)*32;
                int l2 = s_aux[am] + k7 - 3;
                apred = ((unsigned)l2 < LL);
                off = (size_t)(row0+am+k7-3)*128 + c0 + akh;
                acbase = c0 + akh;
            } else if(MODE==M_C3){
                apred = true;
                off = (size_t)(row0+am)*128 + ch*32 + akh;
                acbase = ch*32 + akh;
            } else { // M_CT
                int k7 = ch>>1, c0 = (ch&1)*32;
                int p2 = s_aux[am] - k7;
                apred = ((unsigned)p2 < LL);
                int n = (row0+am)>>9;
                off = ((size_t)n*LL + p2)*64 + c0 + akh;
                acbase = c0 + akh;
            }
            if(apred){
                #pragma unroll
                for(int q=0;q<4;q++) a4[q] = *(const float4*)(Araw + off + q*4);
                if(MODE==M_CT){
                    #pragma unroll
                    for(int q=0;q<4;q++) y4[q] = *(const float4*)(g_y + off + q*4);
                }
            }
        };

        auto stsA = [&](int b){
            uint32_t d = smb + b*(BUF_Wc*4) + am*80 + akh*2;
            if(!apred){
                sts128w(d,        0,0,0,0); sts128w(d+16,        0,0,0,0);
                sts128w(d+AL_W*4, 0,0,0,0); sts128w(d+AL_W*4+16, 0,0,0,0);
                return;
            }
            __half hh[16], ll[16];
            const float* af = (const float*)a4;
            const float* yf = (const float*)y4;
            #pragma unroll
            for(int j=0;j<16;j++){
                float v = af[j];
                if(NORM){
                    int c = acbase + j;
                    v = (v - mymn)*myrs*s_w[c] + s_b[c];
                    v = (v >= 0.f) ? v : 0.25f*v;
                    if(MODE==M_CT) v += yf[j];
                }
                __half h = __float2half_rn(v);
                hh[j] = h;
                ll[j] = __float2half_rn(v - __half2float(h));
            }
            sts128w(d,    packh2(hh[0],hh[1]),  packh2(hh[2],hh[3]),  packh2(hh[4],hh[5]),  packh2(hh[6],hh[7]));
            sts128w(d+16, packh2(hh[8],hh[9]),  packh2(hh[10],hh[11]),packh2(hh[12],hh[13]),packh2(hh[14],hh[15]));
            sts128w(d+AL_W*4,    packh2(ll[0],ll[1]),  packh2(ll[2],ll[3]),  packh2(ll[4],ll[5]),  packh2(ll[6],ll[7]));
            sts128w(d+AL_W*4+16, packh2(ll[8],ll[9]),  packh2(ll[10],ll[11]),packh2(ll[12],ll[13]),packh2(ll[14],ll[15]));
        };

        loadA(0);
        cpB(0, 0);
        CP_COMMIT();
        for(int ch=0; ch<KCHUNKS; ch++){
            stsA(ch&1);
            if(ch+1 < KCHUNKS){ cpB(ch+1, (ch+1)&1); CP_COMMIT(); CP_WAIT1(); }
            else { CP_WAIT0(); }
            __syncthreads();
            if(ch+1 < KCHUNKS) loadA(ch+1);
            mma_chunk(ch&1);
            __syncthreads();
        }
    }

    // ---- staged epilogue: smem C tile, coalesced float4 stores, fused stats ----
    float* Cs = (float*)dsm;   // [128][BN+1]
    #pragma unroll
    for(int mi=0;mi<2;mi++){
        int rl = warp_m*32 + mi*16 + lr;
        #pragma unroll
        for(int ni=0;ni<NI;ni++){
            int cl = warp_n*(BN/2) + ni*8 + 2*lc;
            #pragma unroll
            for(int rr=0;rr<2;rr++){
                Cs[(rl+rr*8)*(BN+1) + cl]   = acc[mi][ni][rr*2];
                Cs[(rl+rr*8)*(BN+1) + cl+1] = acc[mi][ni][rr*2+1];
            }
        }
    }
    __syncthreads();

    if(MODE==M_CT){
        int n = row0 >> 9, p0 = row0 & 511;
        #pragma unroll 4
        for(int i = tid*4; i < 64*128; i += 1024){
            int o = i>>7, m = i&127;
            size_t idx = ((size_t)o*F + n)*T + p0 + m;
            float4 xv = *(const float4*)(xs + idx);
            float bo = bias[o];
            float4 v;
            v.x = Cs[(m  )*(BN+1)+o] + bo + xv.x;
            v.y = Cs[(m+1)*(BN+1)+o] + bo + xv.y;
            v.z = Cs[(m+2)*(BN+1)+o] + bo + xv.z;
            v.w = Cs[(m+3)*(BN+1)+o] + bo + xv.w;
            *(float4*)(outp + idx) = v;
        }
    } else if(MODE==M_SRU){
        int d = col0>>7;
        #pragma unroll 4
        for(int i = tid*4; i < 128*BN; i += 1024){
            int m = i/BN, o = i%BN;
            const float* cr = &Cs[m*(BN+1)+o];
            float4 v = make_float4(cr[0], cr[1], cr[2], cr[3]);
            *(float4*)&g_U[(size_t)d*U_STRIDE + (size_t)(row0+m)*128 + o] = v;
        }
    } else {
        float* dst = (MODE==M_C1)? g_a1 : (MODE==M_C2)? g_a2 : g_a3r;
        const int stride = (MODE==M_C3)? 64 : 128;
        const int n0 = row0 / LL;
        const int split = (n0+1)*LL - row0;   // rows [0,split) -> n0
        float s0=0.f,q0=0.f,s1=0.f,q1=0.f;
        #pragma unroll 4
        for(int i = tid*4; i < 128*BN; i += 1024){
            int m = i/BN, o = i%BN;
            const float* cr = &Cs[m*(BN+1)+o];
            const float* br = &bias[col0+o];
            float4 v = make_float4(cr[0]+br[0], cr[1]+br[1], cr[2]+br[2], cr[3]+br[3]);
            *(float4*)&dst[(size_t)(row0+m)*stride + col0 + o] = v;
            if(OSTAT){
                float ls = v.x + v.y + v.z + v.w;
                float lq = v.x*v.x + v.y*v.y + v.z*v.z + v.w*v.w;
                if(m < split){ s0 += ls; q0 += lq; } else { s1 += ls; q1 += lq; }
            }
        }
        if(OSTAT){
            #pragma unroll
            for(int off=16; off; off>>=1){
                s0 += __shfl_down_sync(0xFFFFFFFFu, s0, off);
                q0 += __shfl_down_sync(0xFFFFFFFFu, q0, off);
                s1 += __shfl_down_sync(0xFFFFFFFFu, s1, off);
                q1 += __shfl_down_sync(0xFFFFFFFFu, q1, off);
            }
            __syncthreads();
            float* red = (float*)dsm + 128*(BN+1);
            if(lane==0){ red[wid]=s0; red[8+wid]=q0; red[16+wid]=s1; red[24+wid]=q1; }
            __syncthreads();
            if(tid==0){
                float S0=0,Q0=0,S1=0,Q1=0;
                #pragma unroll
                for(int w2=0;w2<8;w2++){ S0+=red[w2]; Q0+=red[8+w2]; S1+=red[16+w2]; Q1+=red[24+w2]; }
                atomicAdd(&g_pstat[OSIDX][n0][0], (double)S0);
                atomicAdd(&g_pstat[OSIDX][n0][1], (double)Q0);
                if(split < 128){
                    atomicAdd(&g_pstat[OSIDX][n0+1][0], (double)S1);
                    atomicAdd(&g_pstat[OSIDX][n0+1][1], (double)Q1);
                }
            }
        }
    }
}

// ---------------- stats finalize ----------------
__global__ void k_fin(int which){
    int n = blockIdx.x*blockDim.x + threadIdx.x;
    if(n < F){
        int len = (which==2) ? LL*64 : LL*128;
        double s = g_pstat[which][n][0], q = g_pstat[which][n][1];
        double m = s/len;
        double v = q/len - m*m;
        g_stats[which][n*2]   = (float)m;
        g_stats[which][n*2+1] = rsqrtf((float)v + EPSV);
    }
}

// ---------------- SRU scan: deep prefetch (PF=8 rolling register buffer) ----------------
#define PF 8
__global__ void k_scan(const float* __restrict__ sruv, const float* __restrict__ srub){
    int w = (blockIdx.x*blockDim.x + threadIdx.x) >> 5;
    int h = threadIdx.x & 31;
    int d = w >> 8; int n = w & 255;
    float vf = sruv[d*64 + h];
    float vr = sruv[d*64 + 32 + h];
    float bf = srub[d*64 + h];
    float br = srub[d*64 + 32 + h];
    float st = 0.f;
    const float* Ubase = g_U + (size_t)d*U_STRIDE + (size_t)n*128;

    float pf0[PF], pf1[PF], pf2[PF], pf3[PF];
    int pl[PF];
    #pragma unroll
    for(int i=0;i<PF;i++){
        int l = d ? (LL-1-i) : i;
        pl[i] = l;
        const float* u = Ubase + (size_t)l*(256*128);
        pf0[i]=u[h]; pf1[i]=u[32+h]; pf2[i]=u[64+h]; pf3[i]=u[96+h];
    }

    for(int s=0; s<LL; s+=PF){
        #pragma unroll
        for(int i=0;i<PF;i++){
            if(s+i < LL){
                float u0=pf0[i], u1=pf1[i], u2=pf2[i], u3=pf3[i];
                int l = pl[i];
                float f  = sigf(u1 + vf*st + bf);
                float cn = f*st + (1.f-f)*u0;
                float rr = sigf(u2 + vr*st + br);
                float hv = rr*cn + (1.f-rr)*u3;
                st = cn;
                g_y[((size_t)n*LL + l)*64 + d*32 + h] = hv;
                int sn = s + i + PF;
                if(sn < LL){
                    int ln = d ? (LL-1-sn) : sn;
                    pl[i] = ln;
                    const float* un = Ubase + (size_t)ln*(256*128);
                    pf0[i]=un[h]; pf1[i]=un[32+h]; pf2[i]=un[64+h]; pf3[i]=un[96+h];
                }
            }
        }
    }
}

// ---------------- launcher ----------------
extern "C" void kernel_launch(void* const* d_in, const int* in_sizes, int n_in,
                              void* d_out, int out_size){
    const float* x    = (const float*)d_in[0];
    const float* gn0w = (const float*)d_in[1];
    const float* gn0b = (const float*)d_in[2];
    const float* sruw = (const float*)d_in[3];
    const float* sruv = (const float*)d_in[4];
    const float* srub = (const float*)d_in[5];
    const float* c1w  = (const float*)d_in[6];
    const float* c1b  = (const float*)d_in[7];
    const float* gn1w = (const float*)d_in[8];
    const float* gn1b = (const float*)d_in[9];
    const float* c2w  = (const float*)d_in[10];
    const float* c2b  = (const float*)d_in[11];
    const float* gn2w = (const float*)d_in[12];
    const float* gn2b = (const float*)d_in[13];
    const float* c3w  = (const float*)d_in[14];
    const float* c3b  = (const float*)d_in[15];
    const float* gn3w = (const float*)d_in[16];
    const float* gn3b = (const float*)d_in[17];
    const float* ctw  = (const float*)d_in[18];
    const float* ctb  = (const float*)d_in[19];
    float* out = (float*)d_out;

    const int smem128 = 2*(BH_W + 2*128*20)*4;   // 81920
    const int smem64  = 2*(BH_W + 2*64*20)*4;    // 61440
    cudaFuncSetAttribute(k_mma<M_SRU,128,14,448>, cudaFuncAttributeMaxDynamicSharedMemorySize, smem128);
    cudaFuncSetAttribute(k_mma<M_C1 ,128, 2, 64>, cudaFuncAttributeMaxDynamicSharedMemorySize, smem128);
    cudaFuncSetAttribute(k_mma<M_C2 ,128,28,896>, cudaFuncAttributeMaxDynamicSharedMemorySize, smem128);
    cudaFuncSetAttribute(k_mma<M_C3 , 64, 4,128>, cudaFuncAttributeMaxDynamicSharedMemorySize, smem64);
    cudaFuncSetAttribute(k_mma<M_CT , 64,14,448>, cudaFuncAttributeMaxDynamicSharedMemorySize, smem64);

    k_red0 <<<512,256>>>(x);
    k_red0b<<<1,256>>>();
    k_prep <<<1072,256>>>(c1w, c2w, c3w, ctw, sruw);
    k_xn   <<<dim3(16,256),256>>>(x, gn0w, gn0b);

    k_mma<M_SRU,128,14,448><<<dim3(2,M_ROWS/128),256,smem128>>>(nullptr, nullptr, nullptr, nullptr, nullptr);
    k_scan <<<128,128>>>(sruv, srub);

    k_mma<M_C1,128,2,64>  <<<dim3(1,M_ROWS/128),256,smem128>>>(c1b, nullptr, nullptr, nullptr, nullptr);
    k_fin<<<1,256>>>(0);

    k_mma<M_C2,128,28,896><<<dim3(1,M_ROWS/128),256,smem128>>>(c2b, nullptr, nullptr, gn1w, gn1b);
    k_fin<<<1,256>>>(1);

    k_mma<M_C3,64,4,128> <<<dim3(1,M_ROWS/128),256,smem64>>>(c3b, nullptr, nullptr, gn2w, gn2b);
    k_fin<<<1,256>>>(2);

    k_mma<M_CT,64,14,448><<<dim3(1,(F*T)/128),256,smem64>>>(ctb, x, out, gn3w, gn3b);
}

// round 14
// speedup vs baseline: 1.1936x; 1.0517x over previous
#include <cuda_runtime.h>
#include <cuda_fp16.h>
#include <math.h>
#include <stdint.h>

// Problem constants
#define C0 64
#define T  512
#define F  256
#define LL 506
#define KW 7
#define C2 128
#define M_ROWS (F*LL)          // 129536
#define U_STRIDE (M_ROWS*128)  // 16580608
#define EPSV 1e-6f

// ---------------- scratch ----------------
__device__ __half g_X2h[T*F*C0],  g_X2l[T*F*C0];
__device__ float  g_U  [2*M_ROWS*128];
__device__ float  g_y  [M_ROWS*C0];      // raw SRU output
__device__ float  g_a1 [M_ROWS*C2];      // raw c1 out (biased)
__device__ float  g_a2 [M_ROWS*C2];      // raw c2 out (biased)
__device__ float  g_a3r[M_ROWS*C0];      // raw c3 out (biased)
__device__ double g_part[1024];
__device__ float  g_stats0[2];
__device__ double g_pstat[3][F][2];      // fused stats partials (sum, sumsq)
// fp16 hi/lo split, K-major weights: [o][k]
__device__ __half g_wsruh[256*448], g_wsrul[256*448];
__device__ __half g_w2h [128*896],  g_w2l [128*896];
__device__ __half g_w1h [128*64],   g_w1l [128*64];
__device__ __half g_w3h [64*128],   g_w3l [64*128];
__device__ __half g_wcth[64*448],   g_wctl[64*448];

__device__ __forceinline__ float sigf(float v){ return 1.f/(1.f+__expf(-v)); }
__device__ __forceinline__ void split16(float v, __half* hp, __half* lp){
    __half h = __float2half_rn(v);
    *hp = h;
    *lp = __float2half_rn(v - __half2float(h));
}
__device__ __forceinline__ uint32_t smem_u32(const void* p){
    uint32_t a;
    asm("{ .reg .u64 t; cvta.to.shared.u64 t, %1; cvt.u32.u64 %0, t; }" : "=r"(a) : "l"(p));
    return a;
}
__device__ __forceinline__ void cp16(uint32_t dst, const void* src, bool pred){
    int sz = pred ? 16 : 0;
    asm volatile("cp.async.cg.shared.global [%0], [%1], 16, %2;" :: "r"(dst), "l"(src), "r"(sz) : "memory");
}
#define CP_COMMIT() asm volatile("cp.async.commit_group;" ::: "memory")
#define CP_WAIT0()  asm volatile("cp.async.wait_group 0;" ::: "memory")

__device__ __forceinline__ void ldsm4(uint32_t* r, uint32_t addr){
    asm volatile("ldmatrix.sync.aligned.m8n8.x4.shared.b16 {%0,%1,%2,%3}, [%4];"
        : "=r"(r[0]),"=r"(r[1]),"=r"(r[2]),"=r"(r[3]) : "r"(addr));
}
__device__ __forceinline__ void sts128w(uint32_t a, uint32_t x,uint32_t y,uint32_t z,uint32_t w){
    asm volatile("st.shared.v4.b32 [%0], {%1,%2,%3,%4};" :: "r"(a),"r"(x),"r"(y),"r"(z),"r"(w) : "memory");
}
__device__ __forceinline__ uint32_t packh2(__half a, __half b){
    return (uint32_t)__half_as_ushort(a) | ((uint32_t)__half_as_ushort(b) << 16);
}

// ---------------- gn0 reductions ----------------
__global__ void k_red0(const float* __restrict__ x){
    double s=0.0, q=0.0;
    for(int i = blockIdx.x*256 + threadIdx.x; i < T*F*C0; i += 512*256){
        double v = x[i]; s += v; q += v*v;
    }
    __shared__ double shs[256], shq[256];
    int tid = threadIdx.x;
    shs[tid]=s; shq[tid]=q; __syncthreads();
    for(int o=128;o>0;o>>=1){ if(tid<o){shs[tid]+=shs[tid+o]; shq[tid]+=shq[tid+o];} __syncthreads(); }
    if(tid==0){ g_part[blockIdx.x*2]=shs[0]; g_part[blockIdx.x*2+1]=shq[0]; }
}
__global__ void k_red0b(){
    double s=0.0, q=0.0;
    int tid = threadIdx.x;
    for(int b=tid;b<512;b+=256){ s += g_part[2*b]; q += g_part[2*b+1]; }
    __shared__ double shs[256], shq[256];
    shs[tid]=s; shq[tid]=q; __syncthreads();
    for(int o=128;o>0;o>>=1){ if(tid<o){shs[tid]+=shs[tid+o]; shq[tid]+=shq[tid+o];} __syncthreads(); }
    if(tid==0){
        double n = (double)T*F*C0;
        double m = shs[0]/n;
        double v = shq[0]/n - m*m;
        g_stats0[0] = (float)m;
        g_stats0[1] = rsqrtf((float)v + EPSV);
    }
}

// ---------------- weight prep + pstat zero ----------------
__global__ void k_prep(const float* __restrict__ w1, const float* __restrict__ w2,
                       const float* __restrict__ w3, const float* __restrict__ wc,
                       const float* __restrict__ sw){
    int i = blockIdx.x*blockDim.x + threadIdx.x;
    if(i < 1536) ((double*)g_pstat)[i] = 0.0;
    if(i < 114688){
        int o=i/448, kl=i%448, k7=kl>>6, c=kl&63;
        float v = sw[(o>>7)*57344 + (c*7+k7)*128 + (o&127)];
        split16(v, &g_wsruh[i], &g_wsrul[i]); return;
    }
    i -= 114688;
    if(i < 114688){
        int o=i/896, kl=i%896, k7=kl>>7, c=kl&127;
        split16(w2[o*896 + c*7 + k7], &g_w2h[i], &g_w2l[i]); return;
    }
    i -= 114688;
    if(i < 8192){ split16(w1[i], &g_w1h[i], &g_w1l[i]); return; }
    i -= 8192;
    if(i < 8192){ split16(w3[i], &g_w3h[i], &g_w3l[i]); return; }
    i -= 8192;
    if(i < 28672){
        int o=i/448, kl=i%448, k7=kl>>6, c=kl&63;
        split16(wc[c*448 + o*7 + k7], &g_wcth[i], &g_wctl[i]);
    }
}

// ---------------- gn0 apply + transpose to [t][f][c], split store ----------------
__global__ void k_xn(const float* __restrict__ x, const float* __restrict__ w, const float* __restrict__ b){
    __shared__ float sm[32*65];
    int t0 = blockIdx.x*32;
    int f  = blockIdx.y;
    int tid = threadIdx.x;
    float mean = g_stats0[0], rstd = g_stats0[1];
    #pragma unroll
    for(int rep=0;rep<8;rep++){
        int lin = tid + rep*256;
        int c = lin >> 5, tl = lin & 31;
        float v = x[((size_t)c*F + f)*T + t0 + tl];
        v = (v-mean)*rstd*w[c] + b[c];
        sm[tl*65 + c] = v;
    }
    __syncthreads();
    #pragma unroll
    for(int rep=0;rep<8;rep++){
        int lin = tid + rep*256;
        int c = lin & 63, tl = lin >> 6;
        size_t idx = ((size_t)(t0+tl)*F + f)*C0 + c;
        split16(sm[tl*65 + c], &g_X2h[idx], &g_X2l[idx]);
    }
}

// ---------------- fp16x3 mma.sync GEMM with fused A-transform + fused stats ----------------
enum { M_SRU=0, M_C1=1, M_C2=2, M_C3=3, M_CT=4 };

__device__ __forceinline__ void mma16(float* c, const uint32_t* a, const uint32_t* b){
    asm volatile(
        "mma.sync.aligned.m16n8k16.row.col.f32.f16.f16.f32 "
        "{%0,%1,%2,%3},{%4,%5,%6,%7},{%8,%9},{%0,%1,%2,%3};"
        : "+f"(c[0]), "+f"(c[1]), "+f"(c[2]), "+f"(c[3])
        : "r"(a[0]), "r"(a[1]), "r"(a[2]), "r"(a[3]), "r"(b[0]), "r"(b[1]));
}

// smem layout (32-bit words), rows padded to 40 halfs (80 B)
#define AH_W 0
#define AL_W (128*20)              // 2560
#define BH_W (2*128*20)            // 5120

template<int MODE, int BN, int KCHUNKS, int KTOT>
__global__ void __launch_bounds__(256,2)
k_mma(const float* __restrict__ bias, const float* __restrict__ xs, float* __restrict__ outp,
      const float* __restrict__ nw, const float* __restrict__ nb){
    extern __shared__ uint32_t dsm[];
    __shared__ int s_aux[128];
    __shared__ float s_w[128], s_b[128], s_mn[128], s_rs[128];
    constexpr int NI = BN/16;
    constexpr int BUF_Wc = BH_W + 2*BN*20;
    constexpr bool NORM = (MODE==M_C2 || MODE==M_C3 || MODE==M_CT);
    constexpr int SIDX = (MODE==M_C2)?0 : (MODE==M_C3)?1 : 2;
    constexpr int OSIDX = (MODE==M_C1)?0 : (MODE==M_C2)?1 : 2;
    constexpr bool OSTAT = (MODE==M_C1 || MODE==M_C2 || MODE==M_C3);
    constexpr int CHN  = (MODE==M_CT)?64 : 128;
    constexpr int SLEN = (MODE==M_C3 || MODE==M_CT) ? LL*64 : LL*128;  // gn2 input len... (SIDX source len)

    const int tid = threadIdx.x, lane = tid & 31, wid = tid >> 5;
    const int warp_m = wid & 3, warp_n = wid >> 2;
    const int lr = lane >> 2, lc = lane & 3;
    const int col0 = blockIdx.x * BN;
    const int row0 = blockIdx.y * 128;
    const uint32_t smb = smem_u32(dsm);
    // ldmatrix lane geometry
    const int rin = lane & 7, tt = lane >> 3;
    const int a_row = (tt&1)*8 + rin;
    const int a_kb  = (tt>>1)*16;
    const int b_nt  = (tt>>1)*8;
    const int b_kb  = (tt&1)*16;

    const __half* BpH = (MODE==M_SRU)? g_wsruh: (MODE==M_C1)? g_w1h : (MODE==M_C2)? g_w2h: (MODE==M_C3)? g_w3h: g_wcth;
    const __half* BpL = (MODE==M_SRU)? g_wsrul: (MODE==M_C1)? g_w1l : (MODE==M_C2)? g_w2l: (MODE==M_C3)? g_w3l: g_wctl;
    const float*  Araw = (MODE==M_C1)? g_y : (MODE==M_C2)? g_a1 : (MODE==M_C3)? g_a2 : g_a3r;

    if(MODE==M_C2 || MODE==M_CT){
        if(tid<128){
            int r = row0 + tid;
            s_aux[tid] = (MODE==M_C2) ? (r % LL) : (r & 511);
        }
    }
    if(NORM){
        if(tid < CHN){ s_w[tid] = nw[tid]; s_b[tid] = nb[tid]; }
        if(tid < 128){
            int n = (MODE==M_CT) ? ((row0+tid)>>9) : ((row0+tid)/LL);
            // inline stats finalize (identical math to old k_fin)
            int len = (MODE==M_C2) ? LL*128 : (MODE==M_C3) ? LL*128 : LL*64;
            double s = g_pstat[SIDX][n][0], q = g_pstat[SIDX][n][1];
            double m = s/len;
            double v = q/len - m*m;
            s_mn[tid] = (float)m;
            s_rs[tid] = rsqrtf((float)v + EPSV);
        }
    }
    __syncthreads();

    // B cp.async issue
    auto cpB = [&](int ch, int b){
        const int kbase = ch*32;
        const uint32_t base = smb + b*(BUF_Wc*4);
        #pragma unroll
        for(int rep=0;rep<BN/64;rep++){
            int o = rep*64 + (tid>>2), k4 = tid&3;
            size_t off = (size_t)(col0+o)*KTOT + kbase + k4*8;
            uint32_t d = base + BH_W*4 + o*80 + k4*16;
            cp16(d,               BpH+off, true);
            cp16(d + BN*20*4,     BpL+off, true);
        }
    };

    float acc[2][NI][4] = {};

    // ---- mma on one buffered chunk ----
    auto mma_chunk = [&](int b){
        const uint32_t bufb = smb + b*(BUF_Wc*4);
        #pragma unroll
        for(int k16=0;k16<2;k16++){
            uint32_t ah[2][4], al[2][4];
            #pragma unroll
            for(int mi=0;mi<2;mi++){
                uint32_t ra = bufb + (warp_m*32 + mi*16 + a_row)*80 + k16*32 + a_kb;
                ldsm4(ah[mi], ra);
                ldsm4(al[mi], ra + AL_W*4);
            }
            #pragma unroll
            for(int pg=0; pg<NI/4; pg++){
                const int p0 = 2*pg, p1 = 2*pg+1;
                uint32_t rb0 = bufb + BH_W*4 + (warp_n*(BN/2) + p0*16 + b_nt + rin)*80 + k16*32 + b_kb;
                uint32_t rb1 = bufb + BH_W*4 + (warp_n*(BN/2) + p1*16 + b_nt + rin)*80 + k16*32 + b_kb;
                uint32_t bh0[4], bl0[4], bh1[4], bl1[4];
                ldsm4(bh0, rb0); ldsm4(bl0, rb0 + BN*20*4);
                ldsm4(bh1, rb1); ldsm4(bl1, rb1 + BN*20*4);
                mma16(acc[0][2*p0],   ah[0], bh0);   mma16(acc[1][2*p0],   ah[1], bh0);
                mma16(acc[0][2*p0+1], ah[0], bh0+2); mma16(acc[1][2*p0+1], ah[1], bh0+2);
                mma16(acc[0][2*p1],   ah[0], bh1);   mma16(acc[1][2*p1],   ah[1], bh1);
                mma16(acc[0][2*p1+1], ah[0], bh1+2); mma16(acc[1][2*p1+1], ah[1], bh1+2);
                mma16(acc[0][2*p0],   al[0], bh0);   mma16(acc[1][2*p0],   al[1], bh0);
                mma16(acc[0][2*p0+1], al[0], bh0+2); mma16(acc[1][2*p0+1], al[1], bh0+2);
                mma16(acc[0][2*p1],   al[0], bh1);   mma16(acc[1][2*p1],   al[1], bh1);
                mma16(acc[0][2*p1+1], al[0], bh1+2); mma16(acc[1][2*p1+1], al[1], bh1+2);
                mma16(acc[0][2*p0],   ah[0], bl0);   mma16(acc[1][2*p0],   ah[1], bl0);
                mma16(acc[0][2*p0+1], ah[0], bl0+2); mma16(acc[1][2*p0+1], ah[1], bl0+2);
                mma16(acc[0][2*p1],   ah[0], bl1);   mma16(acc[1][2*p1],   ah[1], bl1);
                mma16(acc[0][2*p1+1], ah[0], bl1+2); mma16(acc[1][2*p1+1], ah[1], bl1+2);
            }
        }
    };

    if(MODE==M_SRU){
        // ---- cp.async A path (pre-split X2), single sync per chunk ----
        auto issue = [&](int ch, int b){
            int k7 = ch>>1, c0 = (ch&1)*32;
            const uint32_t base = smb + b*(BUF_Wc*4);
            #pragma unroll
            for(int rep=0;rep<2;rep++){
                int lin = tid + rep*256;
                int m = lin>>2, k4 = lin&3;
                size_t off=(size_t)(row0+m+k7*256)*64 + c0 + k4*8;
                uint32_t d = base + m*80 + k4*16;
                cp16(d,            g_X2h+off, true);
                cp16(d + AL_W*4,   g_X2l+off, true);
            }
            cpB(ch, b);
        };
        issue(0, 0);
        CP_COMMIT();
        for(int ch=0; ch<KCHUNKS; ch++){
            CP_WAIT0();
            __syncthreads();
            if(ch+1 < KCHUNKS){ issue(ch+1, (ch+1)&1); CP_COMMIT(); }
            mma_chunk(ch&1);
        }
    } else {
        // ---- register A path with fused transform, single sync per chunk ----
        const int am = tid>>1, akh = (tid&1)*16;
        const float mymn = NORM ? s_mn[am] : 0.f;
        const float myrs = NORM ? s_rs[am] : 0.f;
        float4 a4[4], y4[4];
        bool apred = true;
        int acbase = 0;

        auto loadA = [&](int ch){
            size_t off = 0;
            if(MODE==M_C1){
                apred = true;
                off = (size_t)(row0+am)*64 + ch*32 + akh;
            } else if(MODE==M_C2){
                int k7 = ch>>2, c0 = (ch&3)*32;
                int l2 = s_aux[am] + k7 - 3;
                apred = ((unsigned)l2 < LL);
                off = (size_t)(row0+am+k7-3)*128 + c0 + akh;
                acbase = c0 + akh;
            } else if(MODE==M_C3){
                apred = true;
                off = (size_t)(row0+am)*128 + ch*32 + akh;
                acbase = ch*32 + akh;
            } else { // M_CT
                int k7 = ch>>1, c0 = (ch&1)*32;
                int p2 = s_aux[am] - k7;
                apred = ((unsigned)p2 < LL);
                int n = (row0+am)>>9;
                off = ((size_t)n*LL + p2)*64 + c0 + akh;
                acbase = c0 + akh;
            }
            if(apred){
                #pragma unroll
                for(int q=0;q<4;q++) a4[q] = *(const float4*)(Araw + off + q*4);
                if(MODE==M_CT){
                    #pragma unroll
                    for(int q=0;q<4;q++) y4[q] = *(const float4*)(g_y + off + q*4);
                }
            }
        };

        auto stsA = [&](int b){
            uint32_t d = smb + b*(BUF_Wc*4) + am*80 + akh*2;
            if(!apred){
                sts128w(d,        0,0,0,0); sts128w(d+16,        0,0,0,0);
                sts128w(d+AL_W*4, 0,0,0,0); sts128w(d+AL_W*4+16, 0,0,0,0);
                return;
            }
            __half hh[16], ll[16];
            const float* af = (const float*)a4;
            const float* yf = (const float*)y4;
            #pragma unroll
            for(int j=0;j<16;j++){
                float v = af[j];
                if(NORM){
                    int c = acbase + j;
                    v = (v - mymn)*myrs*s_w[c] + s_b[c];
                    v = (v >= 0.f) ? v : 0.25f*v;
                    if(MODE==M_CT) v += yf[j];
                }
                __half h = __float2half_rn(v);
                hh[j] = h;
                ll[j] = __float2half_rn(v - __half2float(h));
            }
            sts128w(d,    packh2(hh[0],hh[1]),  packh2(hh[2],hh[3]),  packh2(hh[4],hh[5]),  packh2(hh[6],hh[7]));
            sts128w(d+16, packh2(hh[8],hh[9]),  packh2(hh[10],hh[11]),packh2(hh[12],hh[13]),packh2(hh[14],hh[15]));
            sts128w(d+AL_W*4,    packh2(ll[0],ll[1]),  packh2(ll[2],ll[3]),  packh2(ll[4],ll[5]),  packh2(ll[6],ll[7]));
            sts128w(d+AL_W*4+16, packh2(ll[8],ll[9]),  packh2(ll[10],ll[11]),packh2(ll[12],ll[13]),packh2(ll[14],ll[15]));
        };

        loadA(0);
        cpB(0, 0);
        CP_COMMIT();
        for(int ch=0; ch<KCHUNKS; ch++){
            stsA(ch&1);
            CP_WAIT0();
            __syncthreads();
            if(ch+1 < KCHUNKS){ cpB(ch+1, (ch+1)&1); CP_COMMIT(); loadA(ch+1); }
            mma_chunk(ch&1);
        }
    }

    // ---- staged epilogue: smem C tile, coalesced float4 stores, fused stats ----
    __syncthreads();
    float* Cs = (float*)dsm;   // [128][BN+1]
    #pragma unroll
    for(int mi=0;mi<2;mi++){
        int rl = warp_m*32 + mi*16 + lr;
        #pragma unroll
        for(int ni=0;ni<NI;ni++){
            int cl = warp_n*(BN/2) + ni*8 + 2*lc;
            #pragma unroll
            for(int rr=0;rr<2;rr++){
                Cs[(rl+rr*8)*(BN+1) + cl]   = acc[mi][ni][rr*2];
                Cs[(rl+rr*8)*(BN+1) + cl+1] = acc[mi][ni][rr*2+1];
            }
        }
    }
    __syncthreads();

    if(MODE==M_CT){
        int n = row0 >> 9, p0 = row0 & 511;
        #pragma unroll 4
        for(int i = tid*4; i < 64*128; i += 1024){
            int o = i>>7, m = i&127;
            size_t idx = ((size_t)o*F + n)*T + p0 + m;
            float4 xv = *(const float4*)(xs + idx);
            float bo = bias[o];
            float4 v;
            v.x = Cs[(m  )*(BN+1)+o] + bo + xv.x;
            v.y = Cs[(m+1)*(BN+1)+o] + bo + xv.y;
            v.z = Cs[(m+2)*(BN+1)+o] + bo + xv.z;
            v.w = Cs[(m+3)*(BN+1)+o] + bo + xv.w;
            *(float4*)(outp + idx) = v;
        }
    } else if(MODE==M_SRU){
        int d = col0>>7;
        #pragma unroll 4
        for(int i = tid*4; i < 128*BN; i += 1024){
            int m = i/BN, o = i%BN;
            const float* cr = &Cs[m*(BN+1)+o];
            float4 v = make_float4(cr[0], cr[1], cr[2], cr[3]);
            *(float4*)&g_U[(size_t)d*U_STRIDE + (size_t)(row0+m)*128 + o] = v;
        }
    } else {
        float* dst = (MODE==M_C1)? g_a1 : (MODE==M_C2)? g_a2 : g_a3r;
        const int stride = (MODE==M_C3)? 64 : 128;
        const int n0 = row0 / LL;
        const int split = (n0+1)*LL - row0;   // rows [0,split) -> n0
        float s0=0.f,q0=0.f,s1=0.f,q1=0.f;
        #pragma unroll 4
        for(int i = tid*4; i < 128*BN; i += 1024){
            int m = i/BN, o = i%BN;
            const float* cr = &Cs[m*(BN+1)+o];
            const float* br = &bias[col0+o];
            float4 v = make_float4(cr[0]+br[0], cr[1]+br[1], cr[2]+br[2], cr[3]+br[3]);
            *(float4*)&dst[(size_t)(row0+m)*stride + col0 + o] = v;
            if(OSTAT){
                float ls = v.x + v.y + v.z + v.w;
                float lq = v.x*v.x + v.y*v.y + v.z*v.z + v.w*v.w;
                if(m < split){ s0 += ls; q0 += lq; } else { s1 += ls; q1 += lq; }
            }
        }
        if(OSTAT){
            #pragma unroll
            for(int off=16; off; off>>=1){
                s0 += __shfl_down_sync(0xFFFFFFFFu, s0, off);
                q0 += __shfl_down_sync(0xFFFFFFFFu, q0, off);
                s1 += __shfl_down_sync(0xFFFFFFFFu, s1, off);
                q1 += __shfl_down_sync(0xFFFFFFFFu, q1, off);
            }
            __syncthreads();
            float* red = (float*)dsm + 128*(BN+1);
            if(lane==0){ red[wid]=s0; red[8+wid]=q0; red[16+wid]=s1; red[24+wid]=q1; }
            __syncthreads();
            if(tid==0){
                float S0=0,Q0=0,S1=0,Q1=0;
                #pragma unroll
                for(int w2=0;w2<8;w2++){ S0+=red[w2]; Q0+=red[8+w2]; S1+=red[16+w2]; Q1+=red[24+w2]; }
                atomicAdd(&g_pstat[OSIDX][n0][0], (double)S0);
                atomicAdd(&g_pstat[OSIDX][n0][1], (double)Q0);
                if(split < 128){
                    atomicAdd(&g_pstat[OSIDX][n0+1][0], (double)S1);
                    atomicAdd(&g_pstat[OSIDX][n0+1][1], (double)Q1);
                }
            }
        }
    }
}

// ---------------- SRU scan: deep prefetch (PF=12 rolling register buffer) ----------------
#define PF 12
__global__ void k_scan(const float* __restrict__ sruv, const float* __restrict__ srub){
    int w = (blockIdx.x*blockDim.x + threadIdx.x) >> 5;
    int h = threadIdx.x & 31;
    int d = w >> 8; int n = w & 255;
    float vf = sruv[d*64 + h];
    float vr = sruv[d*64 + 32 + h];
    float bf = srub[d*64 + h];
    float br = srub[d*64 + 32 + h];
    float st = 0.f;
    const float* Ubase = g_U + (size_t)d*U_STRIDE + (size_t)n*128;

    float pf0[PF], pf1[PF], pf2[PF], pf3[PF];
    int pl[PF];
    #pragma unroll
    for(int i=0;i<PF;i++){
        int l = d ? (LL-1-i) : i;
        pl[i] = l;
        const float* u = Ubase + (size_t)l*(256*128);
        pf0[i]=u[h]; pf1[i]=u[32+h]; pf2[i]=u[64+h]; pf3[i]=u[96+h];
    }

    for(int s=0; s<LL; s+=PF){
        #pragma unroll
        for(int i=0;i<PF;i++){
            if(s+i < LL){
                float u0=pf0[i], u1=pf1[i], u2=pf2[i], u3=pf3[i];
                int l = pl[i];
                float f  = sigf(u1 + vf*st + bf);
                float cn = f*st + (1.f-f)*u0;
                float rr = sigf(u2 + vr*st + br);
                float hv = rr*cn + (1.f-rr)*u3;
                st = cn;
                g_y[((size_t)n*LL + l)*64 + d*32 + h] = hv;
                int sn = s + i + PF;
                if(sn < LL){
                    int ln = d ? (LL-1-sn) : sn;
                    pl[i] = ln;
                    const float* un = Ubase + (size_t)ln*(256*128);
                    pf0[i]=un[h]; pf1[i]=un[32+h]; pf2[i]=un[64+h]; pf3[i]=un[96+h];
                }
            }
        }
    }
}

// ---------------- launcher ----------------
extern "C" void kernel_launch(void* const* d_in, const int* in_sizes, int n_in,
                              void* d_out, int out_size){
    const float* x    = (const float*)d_in[0];
    const float* gn0w = (const float*)d_in[1];
    const float* gn0b = (const float*)d_in[2];
    const float* sruw = (const float*)d_in[3];
    const float* sruv = (const float*)d_in[4];
    const float* srub = (const float*)d_in[5];
    const float* c1w  = (const float*)d_in[6];
    const float* c1b  = (const float*)d_in[7];
    const float* gn1w = (const float*)d_in[8];
    const float* gn1b = (const float*)d_in[9];
    const float* c2w  = (const float*)d_in[10];
    const float* c2b  = (const float*)d_in[11];
    const float* gn2w = (const float*)d_in[12];
    const float* gn2b = (const float*)d_in[13];
    const float* c3w  = (const float*)d_in[14];
    const float* c3b  = (const float*)d_in[15];
    const float* gn3w = (const float*)d_in[16];
    const float* gn3b = (const float*)d_in[17];
    const float* ctw  = (const float*)d_in[18];
    const float* ctb  = (const float*)d_in[19];
    float* out = (float*)d_out;

    const int smem128 = 2*(BH_W + 2*128*20)*4;   // 81920
    const int smem64  = 2*(BH_W + 2*64*20)*4;    // 61440
    cudaFuncSetAttribute(k_mma<M_SRU,128,14,448>, cudaFuncAttributeMaxDynamicSharedMemorySize, smem128);
    cudaFuncSetAttribute(k_mma<M_C1 ,128, 2, 64>, cudaFuncAttributeMaxDynamicSharedMemorySize, smem128);
    cudaFuncSetAttribute(k_mma<M_C2 ,128,28,896>, cudaFuncAttributeMaxDynamicSharedMemorySize, smem128);
    cudaFuncSetAttribute(k_mma<M_C3 , 64, 4,128>, cudaFuncAttributeMaxDynamicSharedMemorySize, smem64);
    cudaFuncSetAttribute(k_mma<M_CT , 64,14,448>, cudaFuncAttributeMaxDynamicSharedMemorySize, smem64);

    k_red0 <<<512,256>>>(x);
    k_red0b<<<1,256>>>();
    k_prep <<<1072,256>>>(c1w, c2w, c3w, ctw, sruw);
    k_xn   <<<dim3(16,256),256>>>(x, gn0w, gn0b);

    k_mma<M_SRU,128,14,448><<<dim3(2,M_ROWS/128),256,smem128>>>(nullptr, nullptr, nullptr, nullptr, nullptr);
    k_scan <<<128,128>>>(sruv, srub);

    k_mma<M_C1,128,2,64>  <<<dim3(1,M_ROWS/128),256,smem128>>>(c1b, nullptr, nullptr, nullptr, nullptr);
    k_mma<M_C2,128,28,896><<<dim3(1,M_ROWS/128),256,smem128>>>(c2b, nullptr, nullptr, gn1w, gn1b);
    k_mma<M_C3,64,4,128> <<<dim3(1,M_ROWS/128),256,smem64>>>(c3b, nullptr, nullptr, gn2w, gn2b);
    k_mma<M_CT,64,14,448><<<dim3(1,(F*T)/128),256,smem64>>>(ctb, x, out, gn3w, gn3b);
}

// round 15
// speedup vs baseline: 1.2170x; 1.0196x over previous
#include <cuda_runtime.h>
#include <cuda_fp16.h>
#include <math.h>
#include <stdint.h>

// Problem constants
#define C0 64
#define T  512
#define F  256
#define LL 506
#define KW 7
#define C2 128
#define M_ROWS (F*LL)          // 129536
#define U_STRIDE (M_ROWS*128)  // 16580608
#define EPSV 1e-6f

// ---------------- scratch ----------------
__device__ __half g_X2h[T*F*C0],  g_X2l[T*F*C0];
__device__ float  g_U  [2*M_ROWS*128];
__device__ float  g_y  [M_ROWS*C0];      // raw SRU output
__device__ float  g_a1 [M_ROWS*C2];      // raw c1 out (biased)
__device__ float  g_a2 [M_ROWS*C2];      // raw c2 out (biased)
__device__ float  g_a3r[M_ROWS*C0];      // raw c3 out (biased)
__device__ double g_part[1024];
__device__ float  g_stats0[2];
__device__ double g_pstat[3][F][2];      // fused stats partials (sum, sumsq)
// fp16 hi/lo split, K-major weights: [o][k]
__device__ __half g_wsruh[256*448], g_wsrul[256*448];
__device__ __half g_w2h [128*896],  g_w2l [128*896];
__device__ __half g_w1h [128*64],   g_w1l [128*64];
__device__ __half g_w3h [64*128],   g_w3l [64*128];
__device__ __half g_wcth[64*448],   g_wctl[64*448];

__device__ __forceinline__ float sigf(float v){ return 1.f/(1.f+__expf(-v)); }
__device__ __forceinline__ void split16(float v, __half* hp, __half* lp){
    __half h = __float2half_rn(v);
    *hp = h;
    *lp = __float2half_rn(v - __half2float(h));
}
// pack 2 floats -> 2 fp16 (rn), elem with lower index in low half
__device__ __forceinline__ uint32_t cvt2(float hi, float lo){
    uint32_t r; asm("cvt.rn.f16x2.f32 %0, %1, %2;" : "=r"(r) : "f"(hi), "f"(lo)); return r;
}
__device__ __forceinline__ uint32_t smem_u32(const void* p){
    uint32_t a;
    asm("{ .reg .u64 t; cvta.to.shared.u64 t, %1; cvt.u32.u64 %0, t; }" : "=r"(a) : "l"(p));
    return a;
}
__device__ __forceinline__ void cp16(uint32_t dst, const void* src, bool pred){
    int sz = pred ? 16 : 0;
    asm volatile("cp.async.cg.shared.global [%0], [%1], 16, %2;" :: "r"(dst), "l"(src), "r"(sz) : "memory");
}
#define CP_COMMIT() asm volatile("cp.async.commit_group;" ::: "memory")
#define CP_WAIT0()  asm volatile("cp.async.wait_group 0;" ::: "memory")

__device__ __forceinline__ void ldsm4(uint32_t* r, uint32_t addr){
    asm volatile("ldmatrix.sync.aligned.m8n8.x4.shared.b16 {%0,%1,%2,%3}, [%4];"
        : "=r"(r[0]),"=r"(r[1]),"=r"(r[2]),"=r"(r[3]) : "r"(addr));
}
__device__ __forceinline__ void sts128w(uint32_t a, uint32_t x,uint32_t y,uint32_t z,uint32_t w){
    asm volatile("st.shared.v4.b32 [%0], {%1,%2,%3,%4};" :: "r"(a),"r"(x),"r"(y),"r"(z),"r"(w) : "memory");
}

// ---------------- gn0 reductions ----------------
__global__ void k_red0(const float* __restrict__ x){
    double s=0.0, q=0.0;
    const float4* x4 = (const float4*)x;
    for(int i = blockIdx.x*256 + threadIdx.x; i < (T*F*C0)/4; i += 512*256){
        float4 v = x4[i];
        s += (double)v.x; q += (double)v.x*(double)v.x;
        s += (double)v.y; q += (double)v.y*(double)v.y;
        s += (double)v.z; q += (double)v.z*(double)v.z;
        s += (double)v.w; q += (double)v.w*(double)v.w;
    }
    __shared__ double shs[256], shq[256];
    int tid = threadIdx.x;
    shs[tid]=s; shq[tid]=q; __syncthreads();
    for(int o=128;o>0;o>>=1){ if(tid<o){shs[tid]+=shs[tid+o]; shq[tid]+=shq[tid+o];} __syncthreads(); }
    if(tid==0){ g_part[blockIdx.x*2]=shs[0]; g_part[blockIdx.x*2+1]=shq[0]; }
}
__global__ void k_red0b(){
    double s=0.0, q=0.0;
    int tid = threadIdx.x;
    for(int b=tid;b<512;b+=256){ s += g_part[2*b]; q += g_part[2*b+1]; }
    __shared__ double shs[256], shq[256];
    shs[tid]=s; shq[tid]=q; __syncthreads();
    for(int o=128;o>0;o>>=1){ if(tid<o){shs[tid]+=shs[tid+o]; shq[tid]+=shq[tid+o];} __syncthreads(); }
    if(tid==0){
        double n = (double)T*F*C0;
        double m = shs[0]/n;
        double v = shq[0]/n - m*m;
        g_stats0[0] = (float)m;
        g_stats0[1] = rsqrtf((float)v + EPSV);
    }
}

// ---------------- weight prep + pstat zero ----------------
__global__ void k_prep(const float* __restrict__ w1, const float* __restrict__ w2,
                       const float* __restrict__ w3, const float* __restrict__ wc,
                       const float* __restrict__ sw){
    int i = blockIdx.x*blockDim.x + threadIdx.x;
    if(i < 1536) ((double*)g_pstat)[i] = 0.0;
    if(i < 114688){
        int o=i/448, kl=i%448, k7=kl>>6, c=kl&63;
        float v = sw[(o>>7)*57344 + (c*7+k7)*128 + (o&127)];
        split16(v, &g_wsruh[i], &g_wsrul[i]); return;
    }
    i -= 114688;
    if(i < 114688){
        int o=i/896, kl=i%896, k7=kl>>7, c=kl&127;
        split16(w2[o*896 + c*7 + k7], &g_w2h[i], &g_w2l[i]); return;
    }
    i -= 114688;
    if(i < 8192){ split16(w1[i], &g_w1h[i], &g_w1l[i]); return; }
    i -= 8192;
    if(i < 8192){ split16(w3[i], &g_w3h[i], &g_w3l[i]); return; }
    i -= 8192;
    if(i < 28672){
        int o=i/448, kl=i%448, k7=kl>>6, c=kl&63;
        split16(wc[c*448 + o*7 + k7], &g_wcth[i], &g_wctl[i]);
    }
}

// ---------------- gn0 apply + transpose to [t][f][c], packed split store ----------------
__global__ void k_xn(const float* __restrict__ x, const float* __restrict__ w, const float* __restrict__ b){
    __shared__ float sm[32*65];
    int t0 = blockIdx.x*32;
    int f  = blockIdx.y;
    int tid = threadIdx.x;
    float mean = g_stats0[0], rstd = g_stats0[1];
    #pragma unroll
    for(int rep=0;rep<8;rep++){
        int lin = tid + rep*256;
        int c = lin >> 5, tl = lin & 31;
        float v = x[((size_t)c*F + f)*T + t0 + tl];
        v = (v-mean)*rstd*w[c] + b[c];
        sm[tl*65 + c] = v;
    }
    __syncthreads();
    #pragma unroll
    for(int rep=0;rep<4;rep++){
        int lin = tid + rep*256;
        int cp = (lin & 31)*2, tl = lin >> 5;
        float v0 = sm[tl*65 + cp];
        float v1 = sm[tl*65 + cp + 1];
        uint32_t h2 = cvt2(v1, v0);
        __half2 hh = *reinterpret_cast<__half2*>(&h2);
        float l0 = v0 - __low2float(hh);
        float l1 = v1 - __high2float(hh);
        uint32_t l2w = cvt2(l1, l0);
        size_t idx = ((size_t)(t0+tl)*F + f)*C0 + cp;
        *(uint32_t*)&g_X2h[idx] = h2;
        *(uint32_t*)&g_X2l[idx] = l2w;
    }
}

// ---------------- fp16x3 mma.sync GEMM with fused A-transform + fused stats ----------------
enum { M_SRU=0, M_C1=1, M_C2=2, M_C3=3, M_CT=4 };

__device__ __forceinline__ void mma16(float* c, const uint32_t* a, const uint32_t* b){
    asm volatile(
        "mma.sync.aligned.m16n8k16.row.col.f32.f16.f16.f32 "
        "{%0,%1,%2,%3},{%4,%5,%6,%7},{%8,%9},{%0,%1,%2,%3};"
        : "+f"(c[0]), "+f"(c[1]), "+f"(c[2]), "+f"(c[3])
        : "r"(a[0]), "r"(a[1]), "r"(a[2]), "r"(a[3]), "r"(b[0]), "r"(b[1]));
}

// smem layout (32-bit words), rows padded to 40 halfs (80 B)
#define AH_W 0
#define AL_W (128*20)              // 2560
#define BH_W (2*128*20)            // 5120

template<int MODE, int BN, int KCHUNKS, int KTOT>
__global__ void __launch_bounds__(256,2)
k_mma(const float* __restrict__ bias, const float* __restrict__ xs, float* __restrict__ outp,
      const float* __restrict__ nw, const float* __restrict__ nb){
    extern __shared__ uint32_t dsm[];
    __shared__ int s_aux[128];
    __shared__ float s_w[128], s_b[128], s_mn[128], s_rs[128];
    constexpr int NI = BN/16;
    constexpr int BUF_Wc = BH_W + 2*BN*20;
    constexpr bool NORM = (MODE==M_C2 || MODE==M_C3 || MODE==M_CT);
    constexpr int SIDX = (MODE==M_C2)?0 : (MODE==M_C3)?1 : 2;
    constexpr int OSIDX = (MODE==M_C1)?0 : (MODE==M_C2)?1 : 2;
    constexpr bool OSTAT = (MODE==M_C1 || MODE==M_C2 || MODE==M_C3);
    constexpr int CHN  = (MODE==M_CT)?64 : 128;

    const int tid = threadIdx.x, lane = tid & 31, wid = tid >> 5;
    const int warp_m = wid & 3, warp_n = wid >> 2;
    const int lr = lane >> 2, lc = lane & 3;
    const int col0 = blockIdx.x * BN;
    const int row0 = blockIdx.y * 128;
    const uint32_t smb = smem_u32(dsm);
    // ldmatrix lane geometry
    const int rin = lane & 7, tt = lane >> 3;
    const int a_row = (tt&1)*8 + rin;
    const int a_kb  = (tt>>1)*16;
    const int b_nt  = (tt>>1)*8;
    const int b_kb  = (tt&1)*16;

    const __half* BpH = (MODE==M_SRU)? g_wsruh: (MODE==M_C1)? g_w1h : (MODE==M_C2)? g_w2h: (MODE==M_C3)? g_w3h: g_wcth;
    const __half* BpL = (MODE==M_SRU)? g_wsrul: (MODE==M_C1)? g_w1l : (MODE==M_C2)? g_w2l: (MODE==M_C3)? g_w3l: g_wctl;
    const float*  Araw = (MODE==M_C1)? g_y : (MODE==M_C2)? g_a1 : (MODE==M_C3)? g_a2 : g_a3r;

    if(MODE==M_C2 || MODE==M_CT){
        if(tid<128){
            int r = row0 + tid;
            s_aux[tid] = (MODE==M_C2) ? (r % LL) : (r & 511);
        }
    }
    if(NORM){
        if(tid < CHN){ s_w[tid] = nw[tid]; s_b[tid] = nb[tid]; }
        if(tid < 128){
            int n = (MODE==M_CT) ? ((row0+tid)>>9) : ((row0+tid)/LL);
            int len = (MODE==M_CT) ? LL*64 : LL*128;
            double s = g_pstat[SIDX][n][0], q = g_pstat[SIDX][n][1];
            double m = s/len;
            double v = q/len - m*m;
            s_mn[tid] = (float)m;
            s_rs[tid] = rsqrtf((float)v + EPSV);
        }
    }
    __syncthreads();

    // B cp.async issue
    auto cpB = [&](int ch, int b){
        const int kbase = ch*32;
        const uint32_t base = smb + b*(BUF_Wc*4);
        #pragma unroll
        for(int rep=0;rep<BN/64;rep++){
            int o = rep*64 + (tid>>2), k4 = tid&3;
            size_t off = (size_t)(col0+o)*KTOT + kbase + k4*8;
            uint32_t d = base + BH_W*4 + o*80 + k4*16;
            cp16(d,               BpH+off, true);
            cp16(d + BN*20*4,     BpL+off, true);
        }
    };

    float acc[2][NI][4] = {};

    // ---- mma on one buffered chunk ----
    auto mma_chunk = [&](int b){
        const uint32_t bufb = smb + b*(BUF_Wc*4);
        #pragma unroll
        for(int k16=0;k16<2;k16++){
            uint32_t ah[2][4], al[2][4];
            #pragma unroll
            for(int mi=0;mi<2;mi++){
                uint32_t ra = bufb + (warp_m*32 + mi*16 + a_row)*80 + k16*32 + a_kb;
                ldsm4(ah[mi], ra);
                ldsm4(al[mi], ra + AL_W*4);
            }
            #pragma unroll
            for(int pg=0; pg<NI/4; pg++){
                const int p0 = 2*pg, p1 = 2*pg+1;
                uint32_t rb0 = bufb + BH_W*4 + (warp_n*(BN/2) + p0*16 + b_nt + rin)*80 + k16*32 + b_kb;
                uint32_t rb1 = bufb + BH_W*4 + (warp_n*(BN/2) + p1*16 + b_nt + rin)*80 + k16*32 + b_kb;
                uint32_t bh0[4], bl0[4], bh1[4], bl1[4];
                ldsm4(bh0, rb0); ldsm4(bl0, rb0 + BN*20*4);
                ldsm4(bh1, rb1); ldsm4(bl1, rb1 + BN*20*4);
                mma16(acc[0][2*p0],   ah[0], bh0);   mma16(acc[1][2*p0],   ah[1], bh0);
                mma16(acc[0][2*p0+1], ah[0], bh0+2); mma16(acc[1][2*p0+1], ah[1], bh0+2);
                mma16(acc[0][2*p1],   ah[0], bh1);   mma16(acc[1][2*p1],   ah[1], bh1);
                mma16(acc[0][2*p1+1], ah[0], bh1+2); mma16(acc[1][2*p1+1], ah[1], bh1+2);
                mma16(acc[0][2*p0],   al[0], bh0);   mma16(acc[1][2*p0],   al[1], bh0);
                mma16(acc[0][2*p0+1], al[0], bh0+2); mma16(acc[1][2*p0+1], al[1], bh0+2);
                mma16(acc[0][2*p1],   al[0], bh1);   mma16(acc[1][2*p1],   al[1], bh1);
                mma16(acc[0][2*p1+1], al[0], bh1+2); mma16(acc[1][2*p1+1], al[1], bh1+2);
                mma16(acc[0][2*p0],   ah[0], bl0);   mma16(acc[1][2*p0],   ah[1], bl0);
                mma16(acc[0][2*p0+1], ah[0], bl0+2); mma16(acc[1][2*p0+1], ah[1], bl0+2);
                mma16(acc[0][2*p1],   ah[0], bl1);   mma16(acc[1][2*p1],   ah[1], bl1);
                mma16(acc[0][2*p1+1], ah[0], bl1+2); mma16(acc[1][2*p1+1], ah[1], bl1+2);
            }
        }
    };

    if(MODE==M_SRU){
        // ---- cp.async A path (pre-split X2), single sync per chunk ----
        auto issue = [&](int ch, int b){
            int k7 = ch>>1, c0 = (ch&1)*32;
            const uint32_t base = smb + b*(BUF_Wc*4);
            #pragma unroll
            for(int rep=0;rep<2;rep++){
                int lin = tid + rep*256;
                int m = lin>>2, k4 = lin&3;
                size_t off=(size_t)(row0+m+k7*256)*64 + c0 + k4*8;
                uint32_t d = base + m*80 + k4*16;
                cp16(d,            g_X2h+off, true);
                cp16(d + AL_W*4,   g_X2l+off, true);
            }
            cpB(ch, b);
        };
        issue(0, 0);
        CP_COMMIT();
        for(int ch=0; ch<KCHUNKS; ch++){
            CP_WAIT0();
            __syncthreads();
            if(ch+1 < KCHUNKS){ issue(ch+1, (ch+1)&1); CP_COMMIT(); }
            mma_chunk(ch&1);
        }
    } else {
        // ---- register A path with fused transform, single sync per chunk ----
        const int am = tid>>1, akh = (tid&1)*16;
        const float mymn = NORM ? s_mn[am] : 0.f;
        const float myrs = NORM ? s_rs[am] : 0.f;
        float4 a4[4], y4[4];
        bool apred = true;
        int acbase = 0;

        auto loadA = [&](int ch){
            size_t off = 0;
            if(MODE==M_C1){
                apred = true;
                off = (size_t)(row0+am)*64 + ch*32 + akh;
            } else if(MODE==M_C2){
                int k7 = ch>>2, c0 = (ch&3)*32;
                int l2 = s_aux[am] + k7 - 3;
                apred = ((unsigned)l2 < LL);
                off = (size_t)(row0+am+k7-3)*128 + c0 + akh;
                acbase = c0 + akh;
            } else if(MODE==M_C3){
                apred = true;
                off = (size_t)(row0+am)*128 + ch*32 + akh;
                acbase = ch*32 + akh;
            } else { // M_CT
                int k7 = ch>>1, c0 = (ch&1)*32;
                int p2 = s_aux[am] - k7;
                apred = ((unsigned)p2 < LL);
                int n = (row0+am)>>9;
                off = ((size_t)n*LL + p2)*64 + c0 + akh;
                acbase = c0 + akh;
            }
            if(apred){
                #pragma unroll
                for(int q=0;q<4;q++) a4[q] = *(const float4*)(Araw + off + q*4);
                if(MODE==M_CT){
                    #pragma unroll
                    for(int q=0;q<4;q++) y4[q] = *(const float4*)(g_y + off + q*4);
                }
            }
        };

        auto stsA = [&](int b){
            uint32_t d = smb + b*(BUF_Wc*4) + am*80 + akh*2;
            if(!apred){
                sts128w(d,        0,0,0,0); sts128w(d+16,        0,0,0,0);
                sts128w(d+AL_W*4, 0,0,0,0); sts128w(d+AL_W*4+16, 0,0,0,0);
                return;
            }
            uint32_t hw[8], lw[8];
            const float* af = (const float*)a4;
            const float* yf = (const float*)y4;
            #pragma unroll
            for(int jp=0;jp<8;jp++){
                float v0 = af[2*jp], v1 = af[2*jp+1];
                if(NORM){
                    int c0i = acbase + 2*jp;
                    v0 = (v0 - mymn)*myrs*s_w[c0i]   + s_b[c0i];
                    v1 = (v1 - mymn)*myrs*s_w[c0i+1] + s_b[c0i+1];
                    v0 = (v0 >= 0.f) ? v0 : 0.25f*v0;
                    v1 = (v1 >= 0.f) ? v1 : 0.25f*v1;
                    if(MODE==M_CT){ v0 += yf[2*jp]; v1 += yf[2*jp+1]; }
                }
                uint32_t h2 = cvt2(v1, v0);
                __half2 hh = *reinterpret_cast<__half2*>(&h2);
                float l0 = v0 - __low2float(hh);
                float l1 = v1 - __high2float(hh);
                hw[jp] = h2;
                lw[jp] = cvt2(l1, l0);
            }
            sts128w(d,    hw[0],hw[1],hw[2],hw[3]);
            sts128w(d+16, hw[4],hw[5],hw[6],hw[7]);
            sts128w(d+AL_W*4,    lw[0],lw[1],lw[2],lw[3]);
            sts128w(d+AL_W*4+16, lw[4],lw[5],lw[6],lw[7]);
        };

        loadA(0);
        cpB(0, 0);
        CP_COMMIT();
        for(int ch=0; ch<KCHUNKS; ch++){
            stsA(ch&1);
            CP_WAIT0();
            __syncthreads();
            if(ch+1 < KCHUNKS){ cpB(ch+1, (ch+1)&1); CP_COMMIT(); loadA(ch+1); }
            mma_chunk(ch&1);
        }
    }

    // ---- staged epilogue: smem C tile, coalesced float4 stores, fused stats ----
    __syncthreads();
    float* Cs = (float*)dsm;   // [128][BN+1]
    #pragma unroll
    for(int mi=0;mi<2;mi++){
        int rl = warp_m*32 + mi*16 + lr;
        #pragma unroll
        for(int ni=0;ni<NI;ni++){
            int cl = warp_n*(BN/2) + ni*8 + 2*lc;
            #pragma unroll
            for(int rr=0;rr<2;rr++){
                Cs[(rl+rr*8)*(BN+1) + cl]   = acc[mi][ni][rr*2];
                Cs[(rl+rr*8)*(BN+1) + cl+1] = acc[mi][ni][rr*2+1];
            }
        }
    }
    __syncthreads();

    if(MODE==M_CT){
        int n = row0 >> 9, p0 = row0 & 511;
        #pragma unroll 4
        for(int i = tid*4; i < 64*128; i += 1024){
            int o = i>>7, m = i&127;
            size_t idx = ((size_t)o*F + n)*T + p0 + m;
            float4 xv = *(const float4*)(xs + idx);
            float bo = bias[o];
            float4 v;
            v.x = Cs[(m  )*(BN+1)+o] + bo + xv.x;
            v.y = Cs[(m+1)*(BN+1)+o] + bo + xv.y;
            v.z = Cs[(m+2)*(BN+1)+o] + bo + xv.z;
            v.w = Cs[(m+3)*(BN+1)+o] + bo + xv.w;
            *(float4*)(outp + idx) = v;
        }
    } else if(MODE==M_SRU){
        int d = col0>>7;
        #pragma unroll 4
        for(int i = tid*4; i < 128*BN; i += 1024){
            int m = i/BN, o = i%BN;
            const float* cr = &Cs[m*(BN+1)+o];
            float4 v = make_float4(cr[0], cr[1], cr[2], cr[3]);
            *(float4*)&g_U[(size_t)d*U_STRIDE + (size_t)(row0+m)*128 + o] = v;
        }
    } else {
        float* dst = (MODE==M_C1)? g_a1 : (MODE==M_C2)? g_a2 : g_a3r;
        const int stride = (MODE==M_C3)? 64 : 128;
        const int n0 = row0 / LL;
        const int split = (n0+1)*LL - row0;   // rows [0,split) -> n0
        float s0=0.f,q0=0.f,s1=0.f,q1=0.f;
        #pragma unroll 4
        for(int i = tid*4; i < 128*BN; i += 1024){
            int m = i/BN, o = i%BN;
            const float* cr = &Cs[m*(BN+1)+o];
            const float* br = &bias[col0+o];
            float4 v = make_float4(cr[0]+br[0], cr[1]+br[1], cr[2]+br[2], cr[3]+br[3]);
            *(float4*)&dst[(size_t)(row0+m)*stride + col0 + o] = v;
            if(OSTAT){
                float ls = v.x + v.y + v.z + v.w;
                float lq = v.x*v.x + v.y*v.y + v.z*v.z + v.w*v.w;
                if(m < split){ s0 += ls; q0 += lq; } else { s1 += ls; q1 += lq; }
            }
        }
        if(OSTAT){
            #pragma unroll
            for(int off=16; off; off>>=1){
                s0 += __shfl_down_sync(0xFFFFFFFFu, s0, off);
                q0 += __shfl_down_sync(0xFFFFFFFFu, q0, off);
                s1 += __shfl_down_sync(0xFFFFFFFFu, s1, off);
                q1 += __shfl_down_sync(0xFFFFFFFFu, q1, off);
            }
            __syncthreads();
            float* red = (float*)dsm + 128*(BN+1);
            if(lane==0){ red[wid]=s0; red[8+wid]=q0; red[16+wid]=s1; red[24+wid]=q1; }
            __syncthreads();
            if(tid==0){
                float S0=0,Q0=0,S1=0,Q1=0;
                #pragma unroll
                for(int w2=0;w2<8;w2++){ S0+=red[w2]; Q0+=red[8+w2]; S1+=red[16+w2]; Q1+=red[24+w2]; }
                atomicAdd(&g_pstat[OSIDX][n0][0], (double)S0);
                atomicAdd(&g_pstat[OSIDX][n0][1], (double)Q0);
                if(split < 128){
                    atomicAdd(&g_pstat[OSIDX][n0+1][0], (double)S1);
                    atomicAdd(&g_pstat[OSIDX][n0+1][1], (double)Q1);
                }
            }
        }
    }
}

// ---------------- SRU scan: deep prefetch (PF=12 rolling register buffer) ----------------
#define PF 12
__global__ void k_scan(const float* __restrict__ sruv, const float* __restrict__ srub){
    int w = (blockIdx.x*blockDim.x + threadIdx.x) >> 5;
    int h = threadIdx.x & 31;
    int d = w >> 8; int n = w & 255;
    float vf = sruv[d*64 + h];
    float vr = sruv[d*64 + 32 + h];
    float bf = srub[d*64 + h];
    float br = srub[d*64 + 32 + h];
    float st = 0.f;
    const float* Ubase = g_U + (size_t)d*U_STRIDE + (size_t)n*128;

    float pf0[PF], pf1[PF], pf2[PF], pf3[PF];
    int pl[PF];
    #pragma unroll
    for(int i=0;i<PF;i++){
        int l = d ? (LL-1-i) : i;
        pl[i] = l;
        const float* u = Ubase + (size_t)l*(256*128);
        pf0[i]=u[h]; pf1[i]=u[32+h]; pf2[i]=u[64+h]; pf3[i]=u[96+h];
    }

    for(int s=0; s<LL; s+=PF){
        #pragma unroll
        for(int i=0;i<PF;i++){
            if(s+i < LL){
                float u0=pf0[i], u1=pf1[i], u2=pf2[i], u3=pf3[i];
                int l = pl[i];
                float f  = sigf(u1 + vf*st + bf);
                float cn = f*st + (1.f-f)*u0;
                float rr = sigf(u2 + vr*st + br);
                float hv = rr*cn + (1.f-rr)*u3;
                st = cn;
                g_y[((size_t)n*LL + l)*64 + d*32 + h] = hv;
                int sn = s + i + PF;
                if(sn < LL){
                    int ln = d ? (LL-1-sn) : sn;
                    pl[i] = ln;
                    const float* un = Ubase + (size_t)ln*(256*128);
                    pf0[i]=un[h]; pf1[i]=un[32+h]; pf2[i]=un[64+h]; pf3[i]=un[96+h];
                }
            }
        }
    }
}

// ---------------- launcher ----------------
extern "C" void kernel_launch(void* const* d_in, const int* in_sizes, int n_in,
                              void* d_out, int out_size){
    const float* x    = (const float*)d_in[0];
    const float* gn0w = (const float*)d_in[1];
    const float* gn0b = (const float*)d_in[2];
    const float* sruw = (const float*)d_in[3];
    const float* sruv = (const float*)d_in[4];
    const float* srub = (const float*)d_in[5];
    const float* c1w  = (const float*)d_in[6];
    const float* c1b  = (const float*)d_in[7];
    const float* gn1w = (const float*)d_in[8];
    const float* gn1b = (const float*)d_in[9];
    const float* c2w  = (const float*)d_in[10];
    const float* c2b  = (const float*)d_in[11];
    const float* gn2w = (const float*)d_in[12];
    const float* gn2b = (const float*)d_in[13];
    const float* c3w  = (const float*)d_in[14];
    const float* c3b  = (const float*)d_in[15];
    const float* gn3w = (const float*)d_in[16];
    const float* gn3b = (const float*)d_in[17];
    const float* ctw  = (const float*)d_in[18];
    const float* ctb  = (const float*)d_in[19];
    float* out = (float*)d_out;

    const int smem128 = 2*(BH_W + 2*128*20)*4;   // 81920
    const int smem64  = 2*(BH_W + 2*64*20)*4;    // 61440
    cudaFuncSetAttribute(k_mma<M_SRU,128,14,448>, cudaFuncAttributeMaxDynamicSharedMemorySize, smem128);
    cudaFuncSetAttribute(k_mma<M_C1 ,128, 2, 64>, cudaFuncAttributeMaxDynamicSharedMemorySize, smem128);
    cudaFuncSetAttribute(k_mma<M_C2 ,128,28,896>, cudaFuncAttributeMaxDynamicSharedMemorySize, smem128);
    cudaFuncSetAttribute(k_mma<M_C3 , 64, 4,128>, cudaFuncAttributeMaxDynamicSharedMemorySize, smem64);
    cudaFuncSetAttribute(k_mma<M_CT , 64,14,448>, cudaFuncAttributeMaxDynamicSharedMemorySize, smem64);

    k_red0 <<<512,256>>>(x);
    k_red0b<<<1,256>>>();
    k_prep <<<1072,256>>>(c1w, c2w, c3w, ctw, sruw);
    k_xn   <<<dim3(16,256),256>>>(x, gn0w, gn0b);

    k_mma<M_SRU,128,14,448><<<dim3(2,M_ROWS/128),256,smem128>>>(nullptr, nullptr, nullptr, nullptr, nullptr);
    k_scan <<<128,128>>>(sruv, srub);

    k_mma<M_C1,128,2,64>  <<<dim3(1,M_ROWS/128),256,smem128>>>(c1b, nullptr, nullptr, nullptr, nullptr);
    k_mma<M_C2,128,28,896><<<dim3(1,M_ROWS/128),256,smem128>>>(c2b, nullptr, nullptr, gn1w, gn1b);
    k_mma<M_C3,64,4,128> <<<dim3(1,M_ROWS/128),256,smem64>>>(c3b, nullptr, nullptr, gn2w, gn2b);
    k_mma<M_CT,64,14,448><<<dim3(1,(F*T)/128),256,smem64>>>(ctb, x, out, gn3w, gn3b);
}

// round 16
// speedup vs baseline: 1.2172x; 1.0002x over previous
#include <cuda_runtime.h>
#include <cuda_fp16.h>
#include <math.h>
#include <stdint.h>

// Problem constants
#define C0 64
#define T  512
#define F  256
#define LL 506
#define KW 7
#define C2 128
#define M_ROWS (F*LL)          // 129536
#define U_STRIDE (M_ROWS*128)  // 16580608
#define EPSV 1e-6f

// ---------------- scratch ----------------
__device__ __half g_X2h[T*F*C0],  g_X2l[T*F*C0];
__device__ float  g_U  [2*M_ROWS*128];   // layout: [d][n][l][128]
__device__ float  g_y  [M_ROWS*C0];      // raw SRU output
__device__ float  g_a1 [M_ROWS*C2];      // raw c1 out (biased)
__device__ float  g_a2 [M_ROWS*C2];      // raw c2 out (biased)
__device__ float  g_a3r[M_ROWS*C0];      // raw c3 out (biased)
__device__ double g_part[1024];
__device__ float  g_stats0[2];
__device__ double g_pstat[3][F][2];      // fused stats partials (sum, sumsq)
// fp16 hi/lo split, K-major weights: [o][k]
__device__ __half g_wsruh[256*448], g_wsrul[256*448];
__device__ __half g_w2h [128*896],  g_w2l [128*896];
__device__ __half g_w1h [128*64],   g_w1l [128*64];
__device__ __half g_w3h [64*128],   g_w3l [64*128];
__device__ __half g_wcth[64*448],   g_wctl[64*448];

__device__ __forceinline__ float sigf(float v){ return 1.f/(1.f+__expf(-v)); }
__device__ __forceinline__ void split16(float v, __half* hp, __half* lp){
    __half h = __float2half_rn(v);
    *hp = h;
    *lp = __float2half_rn(v - __half2float(h));
}
// pack 2 floats -> 2 fp16 (rn), elem with lower index in low half
__device__ __forceinline__ uint32_t cvt2(float hi, float lo){
    uint32_t r; asm("cvt.rn.f16x2.f32 %0, %1, %2;" : "=r"(r) : "f"(hi), "f"(lo)); return r;
}
__device__ __forceinline__ uint32_t smem_u32(const void* p){
    uint32_t a;
    asm("{ .reg .u64 t; cvta.to.shared.u64 t, %1; cvt.u32.u64 %0, t; }" : "=r"(a) : "l"(p));
    return a;
}
__device__ __forceinline__ void cp16(uint32_t dst, const void* src, bool pred){
    int sz = pred ? 16 : 0;
    asm volatile("cp.async.cg.shared.global [%0], [%1], 16, %2;" :: "r"(dst), "l"(src), "r"(sz) : "memory");
}
#define CP_COMMIT() asm volatile("cp.async.commit_group;" ::: "memory")
#define CP_WAIT0()  asm volatile("cp.async.wait_group 0;" ::: "memory")

__device__ __forceinline__ void ldsm4(uint32_t* r, uint32_t addr){
    asm volatile("ldmatrix.sync.aligned.m8n8.x4.shared.b16 {%0,%1,%2,%3}, [%4];"
        : "=r"(r[0]),"=r"(r[1]),"=r"(r[2]),"=r"(r[3]) : "r"(addr));
}
__device__ __forceinline__ void sts128w(uint32_t a, uint32_t x,uint32_t y,uint32_t z,uint32_t w){
    asm volatile("st.shared.v4.b32 [%0], {%1,%2,%3,%4};" :: "r"(a),"r"(x),"r"(y),"r"(z),"r"(w) : "memory");
}

// ---------------- gn0 reduction pass 1 ----------------
__global__ void k_red0(const float* __restrict__ x){
    double s=0.0, q=0.0;
    const float4* x4 = (const float4*)x;
    for(int i = blockIdx.x*256 + threadIdx.x; i < (T*F*C0)/4; i += 512*256){
        float4 v = x4[i];
        s += (double)v.x; q += (double)v.x*(double)v.x;
        s += (double)v.y; q += (double)v.y*(double)v.y;
        s += (double)v.z; q += (double)v.z*(double)v.z;
        s += (double)v.w; q += (double)v.w*(double)v.w;
    }
    __shared__ double shs[256], shq[256];
    int tid = threadIdx.x;
    shs[tid]=s; shq[tid]=q; __syncthreads();
    for(int o=128;o>0;o>>=1){ if(tid<o){shs[tid]+=shs[tid+o]; shq[tid]+=shq[tid+o];} __syncthreads(); }
    if(tid==0){ g_part[blockIdx.x*2]=shs[0]; g_part[blockIdx.x*2+1]=shq[0]; }
}

// ---------------- weight prep + pstat zero + fused red0b (block 0) ----------------
__global__ void k_prep(const float* __restrict__ w1, const float* __restrict__ w2,
                       const float* __restrict__ w3, const float* __restrict__ wc,
                       const float* __restrict__ sw){
    // block 0: finalize gn0 stats (all 256 threads participate before any return)
    if(blockIdx.x == 0){
        __shared__ double shs[256], shq[256];
        int tid = threadIdx.x;
        double s=0.0, q=0.0;
        for(int b=tid;b<512;b+=256){ s += g_part[2*b]; q += g_part[2*b+1]; }
        shs[tid]=s; shq[tid]=q; __syncthreads();
        for(int o=128;o>0;o>>=1){ if(tid<o){shs[tid]+=shs[tid+o]; shq[tid]+=shq[tid+o];} __syncthreads(); }
        if(tid==0){
            double n = (double)T*F*C0;
            double m = shs[0]/n;
            double v = shq[0]/n - m*m;
            g_stats0[0] = (float)m;
            g_stats0[1] = rsqrtf((float)v + EPSV);
        }
    }
    int i = blockIdx.x*blockDim.x + threadIdx.x;
    if(i < 1536) ((double*)g_pstat)[i] = 0.0;
    if(i < 114688){
        int o=i/448, kl=i%448, k7=kl>>6, c=kl&63;
        float v = sw[(o>>7)*57344 + (c*7+k7)*128 + (o&127)];
        split16(v, &g_wsruh[i], &g_wsrul[i]); return;
    }
    i -= 114688;
    if(i < 114688){
        int o=i/896, kl=i%896, k7=kl>>7, c=kl&127;
        split16(w2[o*896 + c*7 + k7], &g_w2h[i], &g_w2l[i]); return;
    }
    i -= 114688;
    if(i < 8192){ split16(w1[i], &g_w1h[i], &g_w1l[i]); return; }
    i -= 8192;
    if(i < 8192){ split16(w3[i], &g_w3h[i], &g_w3l[i]); return; }
    i -= 8192;
    if(i < 28672){
        int o=i/448, kl=i%448, k7=kl>>6, c=kl&63;
        split16(wc[c*448 + o*7 + k7], &g_wcth[i], &g_wctl[i]);
    }
}

// ---------------- gn0 apply + transpose to [t][f][c], packed split store ----------------
__global__ void k_xn(const float* __restrict__ x, const float* __restrict__ w, const float* __restrict__ b){
    __shared__ float sm[32*65];
    int t0 = blockIdx.x*32;
    int f  = blockIdx.y;
    int tid = threadIdx.x;
    float mean = g_stats0[0], rstd = g_stats0[1];
    #pragma unroll
    for(int rep=0;rep<8;rep++){
        int lin = tid + rep*256;
        int c = lin >> 5, tl = lin & 31;
        float v = x[((size_t)c*F + f)*T + t0 + tl];
        v = (v-mean)*rstd*w[c] + b[c];
        sm[tl*65 + c] = v;
    }
    __syncthreads();
    #pragma unroll
    for(int rep=0;rep<4;rep++){
        int lin = tid + rep*256;
        int cp = (lin & 31)*2, tl = lin >> 5;
        float v0 = sm[tl*65 + cp];
        float v1 = sm[tl*65 + cp + 1];
        uint32_t h2 = cvt2(v1, v0);
        __half2 hh = *reinterpret_cast<__half2*>(&h2);
        float l0 = v0 - __low2float(hh);
        float l1 = v1 - __high2float(hh);
        uint32_t l2w = cvt2(l1, l0);
        size_t idx = ((size_t)(t0+tl)*F + f)*C0 + cp;
        *(uint32_t*)&g_X2h[idx] = h2;
        *(uint32_t*)&g_X2l[idx] = l2w;
    }
}

// ---------------- fp16x3 mma.sync GEMM with fused A-transform + fused stats ----------------
enum { M_SRU=0, M_C1=1, M_C2=2, M_C3=3, M_CT=4 };

__device__ __forceinline__ void mma16(float* c, const uint32_t* a, const uint32_t* b){
    asm volatile(
        "mma.sync.aligned.m16n8k16.row.col.f32.f16.f16.f32 "
        "{%0,%1,%2,%3},{%4,%5,%6,%7},{%8,%9},{%0,%1,%2,%3};"
        : "+f"(c[0]), "+f"(c[1]), "+f"(c[2]), "+f"(c[3])
        : "r"(a[0]), "r"(a[1]), "r"(a[2]), "r"(a[3]), "r"(b[0]), "r"(b[1]));
}

// smem layout (32-bit words), rows padded to 40 halfs (80 B)
#define AH_W 0
#define AL_W (128*20)              // 2560
#define BH_W (2*128*20)            // 5120

template<int MODE, int BN, int KCHUNKS, int KTOT>
__global__ void __launch_bounds__(256,2)
k_mma(const float* __restrict__ bias, const float* __restrict__ xs, float* __restrict__ outp,
      const float* __restrict__ nw, const float* __restrict__ nb){
    extern __shared__ uint32_t dsm[];
    __shared__ int s_aux[128];
    __shared__ float s_w[128], s_b[128], s_mn[128], s_rs[128];
    constexpr int NI = BN/16;
    constexpr int BUF_Wc = BH_W + 2*BN*20;
    constexpr bool NORM = (MODE==M_C2 || MODE==M_C3 || MODE==M_CT);
    constexpr int SIDX = (MODE==M_C2)?0 : (MODE==M_C3)?1 : 2;
    constexpr int OSIDX = (MODE==M_C1)?0 : (MODE==M_C2)?1 : 2;
    constexpr bool OSTAT = (MODE==M_C1 || MODE==M_C2 || MODE==M_C3);
    constexpr int CHN  = (MODE==M_CT)?64 : 128;

    const int tid = threadIdx.x, lane = tid & 31, wid = tid >> 5;
    const int warp_m = wid & 3, warp_n = wid >> 2;
    const int lr = lane >> 2, lc = lane & 3;
    const int col0 = blockIdx.x * BN;
    const int row0 = blockIdx.y * 128;
    const uint32_t smb = smem_u32(dsm);
    // ldmatrix lane geometry
    const int rin = lane & 7, tt = lane >> 3;
    const int a_row = (tt&1)*8 + rin;
    const int a_kb  = (tt>>1)*16;
    const int b_nt  = (tt>>1)*8;
    const int b_kb  = (tt&1)*16;

    const __half* BpH = (MODE==M_SRU)? g_wsruh: (MODE==M_C1)? g_w1h : (MODE==M_C2)? g_w2h: (MODE==M_C3)? g_w3h: g_wcth;
    const __half* BpL = (MODE==M_SRU)? g_wsrul: (MODE==M_C1)? g_w1l : (MODE==M_C2)? g_w2l: (MODE==M_C3)? g_w3l: g_wctl;
    const float*  Araw = (MODE==M_C1)? g_y : (MODE==M_C2)? g_a1 : (MODE==M_C3)? g_a2 : g_a3r;

    if(MODE==M_C2 || MODE==M_CT){
        if(tid<128){
            int r = row0 + tid;
            s_aux[tid] = (MODE==M_C2) ? (r % LL) : (r & 511);
        }
    }
    if(NORM){
        if(tid < CHN){ s_w[tid] = nw[tid]; s_b[tid] = nb[tid]; }
        if(tid < 128){
            int n = (MODE==M_CT) ? ((row0+tid)>>9) : ((row0+tid)/LL);
            int len = (MODE==M_CT) ? LL*64 : LL*128;
            double s = g_pstat[SIDX][n][0], q = g_pstat[SIDX][n][1];
            double m = s/len;
            double v = q/len - m*m;
            s_mn[tid] = (float)m;
            s_rs[tid] = rsqrtf((float)v + EPSV);
        }
    }
    __syncthreads();

    // B cp.async issue
    auto cpB = [&](int ch, int b){
        const int kbase = ch*32;
        const uint32_t base = smb + b*(BUF_Wc*4);
        #pragma unroll
        for(int rep=0;rep<BN/64;rep++){
            int o = rep*64 + (tid>>2), k4 = tid&3;
            size_t off = (size_t)(col0+o)*KTOT + kbase + k4*8;
            uint32_t d = base + BH_W*4 + o*80 + k4*16;
            cp16(d,               BpH+off, true);
            cp16(d + BN*20*4,     BpL+off, true);
        }
    };

    float acc[2][NI][4] = {};

    // ---- mma on one buffered chunk ----
    auto mma_chunk = [&](int b){
        const uint32_t bufb = smb + b*(BUF_Wc*4);
        #pragma unroll
        for(int k16=0;k16<2;k16++){
            uint32_t ah[2][4], al[2][4];
            #pragma unroll
            for(int mi=0;mi<2;mi++){
                uint32_t ra = bufb + (warp_m*32 + mi*16 + a_row)*80 + k16*32 + a_kb;
                ldsm4(ah[mi], ra);
                ldsm4(al[mi], ra + AL_W*4);
            }
            #pragma unroll
            for(int pg=0; pg<NI/4; pg++){
                const int p0 = 2*pg, p1 = 2*pg+1;
                uint32_t rb0 = bufb + BH_W*4 + (warp_n*(BN/2) + p0*16 + b_nt + rin)*80 + k16*32 + b_kb;
                uint32_t rb1 = bufb + BH_W*4 + (warp_n*(BN/2) + p1*16 + b_nt + rin)*80 + k16*32 + b_kb;
                uint32_t bh0[4], bl0[4], bh1[4], bl1[4];
                ldsm4(bh0, rb0); ldsm4(bl0, rb0 + BN*20*4);
                ldsm4(bh1, rb1); ldsm4(bl1, rb1 + BN*20*4);
                mma16(acc[0][2*p0],   ah[0], bh0);   mma16(acc[1][2*p0],   ah[1], bh0);
                mma16(acc[0][2*p0+1], ah[0], bh0+2); mma16(acc[1][2*p0+1], ah[1], bh0+2);
                mma16(acc[0][2*p1],   ah[0], bh1);   mma16(acc[1][2*p1],   ah[1], bh1);
                mma16(acc[0][2*p1+1], ah[0], bh1+2); mma16(acc[1][2*p1+1], ah[1], bh1+2);
                mma16(acc[0][2*p0],   al[0], bh0);   mma16(acc[1][2*p0],   al[1], bh0);
                mma16(acc[0][2*p0+1], al[0], bh0+2); mma16(acc[1][2*p0+1], al[1], bh0+2);
                mma16(acc[0][2*p1],   al[0], bh1);   mma16(acc[1][2*p1],   al[1], bh1);
                mma16(acc[0][2*p1+1], al[0], bh1+2); mma16(acc[1][2*p1+1], al[1], bh1+2);
                mma16(acc[0][2*p0],   ah[0], bl0);   mma16(acc[1][2*p0],   ah[1], bl0);
                mma16(acc[0][2*p0+1], ah[0], bl0+2); mma16(acc[1][2*p0+1], ah[1], bl0+2);
                mma16(acc[0][2*p1],   ah[0], bl1);   mma16(acc[1][2*p1],   ah[1], bl1);
                mma16(acc[0][2*p1+1], ah[0], bl1+2); mma16(acc[1][2*p1+1], ah[1], bl1+2);
            }
        }
    };

    if(MODE==M_SRU){
        // ---- cp.async A path (pre-split X2), single sync per chunk ----
        auto issue = [&](int ch, int b){
            int k7 = ch>>1, c0 = (ch&1)*32;
            const uint32_t base = smb + b*(BUF_Wc*4);
            #pragma unroll
            for(int rep=0;rep<2;rep++){
                int lin = tid + rep*256;
                int m = lin>>2, k4 = lin&3;
                size_t off=(size_t)(row0+m+k7*256)*64 + c0 + k4*8;
                uint32_t d = base + m*80 + k4*16;
                cp16(d,            g_X2h+off, true);
                cp16(d + AL_W*4,   g_X2l+off, true);
            }
            cpB(ch, b);
        };
        issue(0, 0);
        CP_COMMIT();
        for(int ch=0; ch<KCHUNKS; ch++){
            CP_WAIT0();
            __syncthreads();
            if(ch+1 < KCHUNKS){ issue(ch+1, (ch+1)&1); CP_COMMIT(); }
            mma_chunk(ch&1);
        }
    } else {
        // ---- register A path with fused transform, single sync per chunk ----
        const int am = tid>>1, akh = (tid&1)*16;
        const float mymn = NORM ? s_mn[am] : 0.f;
        const float myrs = NORM ? s_rs[am] : 0.f;
        float4 a4[4], y4[4];
        bool apred = true;
        int acbase = 0;

        auto loadA = [&](int ch){
            size_t off = 0;
            if(MODE==M_C1){
                apred = true;
                off = (size_t)(row0+am)*64 + ch*32 + akh;
            } else if(MODE==M_C2){
                int k7 = ch>>2, c0 = (ch&3)*32;
                int l2 = s_aux[am] + k7 - 3;
                apred = ((unsigned)l2 < LL);
                off = (size_t)(row0+am+k7-3)*128 + c0 + akh;
                acbase = c0 + akh;
            } else if(MODE==M_C3){
                apred = true;
                off = (size_t)(row0+am)*128 + ch*32 + akh;
                acbase = ch*32 + akh;
            } else { // M_CT
                int k7 = ch>>1, c0 = (ch&1)*32;
                int p2 = s_aux[am] - k7;
                apred = ((unsigned)p2 < LL);
                int n = (row0+am)>>9;
                off = ((size_t)n*LL + p2)*64 + c0 + akh;
                acbase = c0 + akh;
            }
            if(apred){
                #pragma unroll
                for(int q=0;q<4;q++) a4[q] = *(const float4*)(Araw + off + q*4);
                if(MODE==M_CT){
                    #pragma unroll
                    for(int q=0;q<4;q++) y4[q] = *(const float4*)(g_y + off + q*4);
                }
            }
        };

        auto stsA = [&](int b){
            uint32_t d = smb + b*(BUF_Wc*4) + am*80 + akh*2;
            if(!apred){
                sts128w(d,        0,0,0,0); sts128w(d+16,        0,0,0,0);
                sts128w(d+AL_W*4, 0,0,0,0); sts128w(d+AL_W*4+16, 0,0,0,0);
                return;
            }
            uint32_t hw[8], lw[8];
            const float* af = (const float*)a4;
            const float* yf = (const float*)y4;
            #pragma unroll
            for(int jp=0;jp<8;jp++){
                float v0 = af[2*jp], v1 = af[2*jp+1];
                if(NORM){
                    int c0i = acbase + 2*jp;
                    v0 = (v0 - mymn)*myrs*s_w[c0i]   + s_b[c0i];
                    v1 = (v1 - mymn)*myrs*s_w[c0i+1] + s_b[c0i+1];
                    v0 = (v0 >= 0.f) ? v0 : 0.25f*v0;
                    v1 = (v1 >= 0.f) ? v1 : 0.25f*v1;
                    if(MODE==M_CT){ v0 += yf[2*jp]; v1 += yf[2*jp+1]; }
                }
                uint32_t h2 = cvt2(v1, v0);
                __half2 hh = *reinterpret_cast<__half2*>(&h2);
                float l0 = v0 - __low2float(hh);
                float l1 = v1 - __high2float(hh);
                hw[jp] = h2;
                lw[jp] = cvt2(l1, l0);
            }
            sts128w(d,    hw[0],hw[1],hw[2],hw[3]);
            sts128w(d+16, hw[4],hw[5],hw[6],hw[7]);
            sts128w(d+AL_W*4,    lw[0],lw[1],lw[2],lw[3]);
            sts128w(d+AL_W*4+16, lw[4],lw[5],lw[6],lw[7]);
        };

        loadA(0);
        cpB(0, 0);
        CP_COMMIT();
        for(int ch=0; ch<KCHUNKS; ch++){
            stsA(ch&1);
            CP_WAIT0();
            __syncthreads();
            if(ch+1 < KCHUNKS){ cpB(ch+1, (ch+1)&1); CP_COMMIT(); loadA(ch+1); }
            mma_chunk(ch&1);
        }
    }

    // ---- staged epilogue: smem C tile, coalesced float4 stores, fused stats ----
    __syncthreads();
    float* Cs = (float*)dsm;   // [128][BN+1]
    #pragma unroll
    for(int mi=0;mi<2;mi++){
        int rl = warp_m*32 + mi*16 + lr;
        #pragma unroll
        for(int ni=0;ni<NI;ni++){
            int cl = warp_n*(BN/2) + ni*8 + 2*lc;
            #pragma unroll
            for(int rr=0;rr<2;rr++){
                Cs[(rl+rr*8)*(BN+1) + cl]   = acc[mi][ni][rr*2];
                Cs[(rl+rr*8)*(BN+1) + cl+1] = acc[mi][ni][rr*2+1];
            }
        }
    }
    __syncthreads();

    if(MODE==M_CT){
        int n = row0 >> 9, p0 = row0 & 511;
        #pragma unroll 4
        for(int i = tid*4; i < 64*128; i += 1024){
            int o = i>>7, m = i&127;
            size_t idx = ((size_t)o*F + n)*T + p0 + m;
            float4 xv = *(const float4*)(xs + idx);
            float bo = bias[o];
            float4 v;
            v.x = Cs[(m  )*(BN+1)+o] + bo + xv.x;
            v.y = Cs[(m+1)*(BN+1)+o] + bo + xv.y;
            v.z = Cs[(m+2)*(BN+1)+o] + bo + xv.z;
            v.w = Cs[(m+3)*(BN+1)+o] + bo + xv.w;
            *(float4*)(outp + idx) = v;
        }
    } else if(MODE==M_SRU){
        int d = col0>>7;
        // scan-friendly layout: [d][n][l][128];  row r = l*256+n
        const int lrow = row0 >> 8, nbase = row0 & 255;
        #pragma unroll 4
        for(int i = tid*4; i < 128*BN; i += 1024){
            int m = i/BN, o = i%BN;
            const float* cr = &Cs[m*(BN+1)+o];
            float4 v = make_float4(cr[0], cr[1], cr[2], cr[3]);
            size_t idx = (size_t)d*U_STRIDE + ((size_t)(nbase+m)*LL + lrow)*128 + o;
            *(float4*)&g_U[idx] = v;
        }
    } else {
        float* dst = (MODE==M_C1)? g_a1 : (MODE==M_C2)? g_a2 : g_a3r;
        const int stride = (MODE==M_C3)? 64 : 128;
        const int n0 = row0 / LL;
        const int split = (n0+1)*LL - row0;   // rows [0,split) -> n0
        float s0=0.f,q0=0.f,s1=0.f,q1=0.f;
        #pragma unroll 4
        for(int i = tid*4; i < 128*BN; i += 1024){
            int m = i/BN, o = i%BN;
            const float* cr = &Cs[m*(BN+1)+o];
            const float* br = &bias[col0+o];
            float4 v = make_float4(cr[0]+br[0], cr[1]+br[1], cr[2]+br[2], cr[3]+br[3]);
            *(float4*)&dst[(size_t)(row0+m)*stride + col0 + o] = v;
            if(OSTAT){
                float ls = v.x + v.y + v.z + v.w;
                float lq = v.x*v.x + v.y*v.y + v.z*v.z + v.w*v.w;
                if(m < split){ s0 += ls; q0 += lq; } else { s1 += ls; q1 += lq; }
            }
        }
        if(OSTAT){
            #pragma unroll
            for(int off=16; off; off>>=1){
                s0 += __shfl_down_sync(0xFFFFFFFFu, s0, off);
                q0 += __shfl_down_sync(0xFFFFFFFFu, q0, off);
                s1 += __shfl_down_sync(0xFFFFFFFFu, s1, off);
                q1 += __shfl_down_sync(0xFFFFFFFFu, q1, off);
            }
            __syncthreads();
            float* red = (float*)dsm + 128*(BN+1);
            if(lane==0){ red[wid]=s0; red[8+wid]=q0; red[16+wid]=s1; red[24+wid]=q1; }
            __syncthreads();
            if(tid==0){
                float S0=0,Q0=0,S1=0,Q1=0;
                #pragma unroll
                for(int w2=0;w2<8;w2++){ S0+=red[w2]; Q0+=red[8+w2]; S1+=red[16+w2]; Q1+=red[24+w2]; }
                atomicAdd(&g_pstat[OSIDX][n0][0], (double)S0);
                atomicAdd(&g_pstat[OSIDX][n0][1], (double)Q0);
                if(split < 128){
                    atomicAdd(&g_pstat[OSIDX][n0+1][0], (double)S1);
                    atomicAdd(&g_pstat[OSIDX][n0+1][1], (double)Q1);
                }
            }
        }
    }
}

// ---------------- SRU scan: deep prefetch, sequential U layout ----------------
#define PF 12
__global__ void k_scan(const float* __restrict__ sruv, const float* __restrict__ srub){
    int w = (blockIdx.x*blockDim.x + threadIdx.x) >> 5;
    int h = threadIdx.x & 31;
    int d = w >> 8; int n = w & 255;
    float vf = sruv[d*64 + h];
    float vr = sruv[d*64 + 32 + h];
    float bf = srub[d*64 + h];
    float br = srub[d*64 + 32 + h];
    float st = 0.f;
    const float* Ubase = g_U + (size_t)d*U_STRIDE + (size_t)n*LL*128;

    float pf0[PF], pf1[PF], pf2[PF], pf3[PF];
    int pl[PF];
    #pragma unroll
    for(int i=0;i<PF;i++){
        int l = d ? (LL-1-i) : i;
        pl[i] = l;
        const float* u = Ubase + (size_t)l*128;
        pf0[i]=u[h]; pf1[i]=u[32+h]; pf2[i]=u[64+h]; pf3[i]=u[96+h];
    }

    for(int s=0; s<LL; s+=PF){
        #pragma unroll
        for(int i=0;i<PF;i++){
            if(s+i < LL){
                float u0=pf0[i], u1=pf1[i], u2=pf2[i], u3=pf3[i];
                int l = pl[i];
                float f  = sigf(u1 + vf*st + bf);
                float cn = f*st + (1.f-f)*u0;
                float rr = sigf(u2 + vr*st + br);
                float hv = rr*cn + (1.f-rr)*u3;
                st = cn;
                g_y[((size_t)n*LL + l)*64 + d*32 + h] = hv;
                int sn = s + i + PF;
                if(sn < LL){
                    int ln = d ? (LL-1-sn) : sn;
                    pl[i] = ln;
                    const float* un = Ubase + (size_t)ln*128;
                    pf0[i]=un[h]; pf1[i]=un[32+h]; pf2[i]=un[64+h]; pf3[i]=un[96+h];
                }
            }
        }
    }
}

// ---------------- launcher ----------------
extern "C" void kernel_launch(void* const* d_in, const int* in_sizes, int n_in,
                              void* d_out, int out_size){
    const float* x    = (const float*)d_in[0];
    const float* gn0w = (const float*)d_in[1];
    const float* gn0b = (const float*)d_in[2];
    const float* sruw = (const float*)d_in[3];
    const float* sruv = (const float*)d_in[4];
    const float* srub = (const float*)d_in[5];
    const float* c1w  = (const float*)d_in[6];
    const float* c1b  = (const float*)d_in[7];
    const float* gn1w = (const float*)d_in[8];
    const float* gn1b = (const float*)d_in[9];
    const float* c2w  = (const float*)d_in[10];
    const float* c2b  = (const float*)d_in[11];
    const float* gn2w = (const float*)d_in[12];
    const float* gn2b = (const float*)d_in[13];
    const float* c3w  = (const float*)d_in[14];
    const float* c3b  = (const float*)d_in[15];
    const float* gn3w = (const float*)d_in[16];
    const float* gn3b = (const float*)d_in[17];
    const float* ctw  = (const float*)d_in[18];
    const float* ctb  = (const float*)d_in[19];
    float* out = (float*)d_out;

    const int smem128 = 2*(BH_W + 2*128*20)*4;   // 81920
    const int smem64  = 2*(BH_W + 2*64*20)*4;    // 61440
    cudaFuncSetAttribute(k_mma<M_SRU,128,14,448>, cudaFuncAttributeMaxDynamicSharedMemorySize, smem128);
    cudaFuncSetAttribute(k_mma<M_C1 ,128, 2, 64>, cudaFuncAttributeMaxDynamicSharedMemorySize, smem128);
    cudaFuncSetAttribute(k_mma<M_C2 ,128,28,896>, cudaFuncAttributeMaxDynamicSharedMemorySize, smem128);
    cudaFuncSetAttribute(k_mma<M_C3 , 64, 4,128>, cudaFuncAttributeMaxDynamicSharedMemorySize, smem64);
    cudaFuncSetAttribute(k_mma<M_CT , 64,14,448>, cudaFuncAttributeMaxDynamicSharedMemorySize, smem64);

    k_red0 <<<512,256>>>(x);
    k_prep <<<1072,256>>>(c1w, c2w, c3w, ctw, sruw);
    k_xn   <<<dim3(16,256),256>>>(x, gn0w, gn0b);

    k_mma<M_SRU,128,14,448><<<dim3(2,M_ROWS/128),256,smem128>>>(nullptr, nullptr, nullptr, nullptr, nullptr);
    k_scan <<<128,128>>>(sruv, srub);

    k_mma<M_C1,128,2,64>  <<<dim3(1,M_ROWS/128),256,smem128>>>(c1b, nullptr, nullptr, nullptr, nullptr);
    k_mma<M_C2,128,28,896><<<dim3(1,M_ROWS/128),256,smem128>>>(c2b, nullptr, nullptr, gn1w, gn1b);
    k_mma<M_C3,64,4,128> <<<dim3(1,M_ROWS/128),256,smem64>>>(c3b, nullptr, nullptr, gn2w, gn2b);
    k_mma<M_CT,64,14,448><<<dim3(1,(F*T)/128),256,smem64>>>(ctb, x, out, gn3w, gn3b);
}

// round 17
// speedup vs baseline: 1.2558x; 1.0317x over previous
#include <cuda_runtime.h>
#include <cuda_fp16.h>
#include <math.h>
#include <stdint.h>

// Problem constants
#define C0 64
#define T  512
#define F  256
#define LL 506
#define KW 7
#define C2 128
#define M_ROWS (F*LL)          // 129536
#define U_STRIDE (M_ROWS*128)  // 16580608
#define EPSV 1e-6f

// ---------------- scratch ----------------
__device__ __half g_X2h[T*F*C0],  g_X2l[T*F*C0];
__device__ float  g_U  [2*M_ROWS*128];   // layout: [d][n][l][128]
__device__ float  g_y  [M_ROWS*C0];      // raw SRU output
__device__ float  g_a1 [M_ROWS*C2];      // raw c1 out (biased)
__device__ float  g_a2 [M_ROWS*C2];      // raw c2 out (biased)
__device__ float  g_a3r[M_ROWS*C0];      // raw c3 out (biased)
__device__ double g_part[1024];
__device__ float  g_stats0[2];
__device__ double g_pstat[3][F][2];      // fused stats partials (sum, sumsq)
// fp16 hi/lo split, K-major weights: [o][k]
__device__ __half g_wsruh[256*448], g_wsrul[256*448];
__device__ __half g_w2h [128*896],  g_w2l [128*896];
__device__ __half g_w1h [128*64],   g_w1l [128*64];
__device__ __half g_w3h [64*128],   g_w3l [64*128];
__device__ __half g_wcth[64*448],   g_wctl[64*448];

__device__ __forceinline__ float rcpa(float v){
    float r; asm("rcp.approx.f32 %0, %1;" : "=f"(r) : "f"(v)); return r;
}
__device__ __forceinline__ float sigfast(float v){
    return rcpa(1.f + __expf(-v));
}
__device__ __forceinline__ void split16(float v, __half* hp, __half* lp){
    __half h = __float2half_rn(v);
    *hp = h;
    *lp = __float2half_rn(v - __half2float(h));
}
// pack 2 floats -> 2 fp16 (rn), elem with lower index in low half
__device__ __forceinline__ uint32_t cvt2(float hi, float lo){
    uint32_t r; asm("cvt.rn.f16x2.f32 %0, %1, %2;" : "=r"(r) : "f"(hi), "f"(lo)); return r;
}
__device__ __forceinline__ uint32_t smem_u32(const void* p){
    uint32_t a;
    asm("{ .reg .u64 t; cvta.to.shared.u64 t, %1; cvt.u32.u64 %0, t; }" : "=r"(a) : "l"(p));
    return a;
}
__device__ __forceinline__ void cp16(uint32_t dst, const void* src, bool pred){
    int sz = pred ? 16 : 0;
    asm volatile("cp.async.cg.shared.global [%0], [%1], 16, %2;" :: "r"(dst), "l"(src), "r"(sz) : "memory");
}
#define CP_COMMIT() asm volatile("cp.async.commit_group;" ::: "memory")
#define CP_WAIT0()  asm volatile("cp.async.wait_group 0;" ::: "memory")

__device__ __forceinline__ void ldsm4(uint32_t* r, uint32_t addr){
    asm volatile("ldmatrix.sync.aligned.m8n8.x4.shared.b16 {%0,%1,%2,%3}, [%4];"
        : "=r"(r[0]),"=r"(r[1]),"=r"(r[2]),"=r"(r[3]) : "r"(addr));
}
__device__ __forceinline__ void sts128w(uint32_t a, uint32_t x,uint32_t y,uint32_t z,uint32_t w){
    asm volatile("st.shared.v4.b32 [%0], {%1,%2,%3,%4};" :: "r"(a),"r"(x),"r"(y),"r"(z),"r"(w) : "memory");
}

// ---------------- gn0 reduction pass 1 ----------------
__global__ void k_red0(const float* __restrict__ x){
    double s=0.0, q=0.0;
    const float4* x4 = (const float4*)x;
    for(int i = blockIdx.x*256 + threadIdx.x; i < (T*F*C0)/4; i += 512*256){
        float4 v = x4[i];
        s += (double)v.x; q += (double)v.x*(double)v.x;
        s += (double)v.y; q += (double)v.y*(double)v.y;
        s += (double)v.z; q += (double)v.z*(double)v.z;
        s += (double)v.w; q += (double)v.w*(double)v.w;
    }
    __shared__ double shs[256], shq[256];
    int tid = threadIdx.x;
    shs[tid]=s; shq[tid]=q; __syncthreads();
    for(int o=128;o>0;o>>=1){ if(tid<o){shs[tid]+=shs[tid+o]; shq[tid]+=shq[tid+o];} __syncthreads(); }
    if(tid==0){ g_part[blockIdx.x*2]=shs[0]; g_part[blockIdx.x*2+1]=shq[0]; }
}

// ---------------- weight prep + pstat zero + fused red0b (block 0) ----------------
__global__ void k_prep(const float* __restrict__ w1, const float* __restrict__ w2,
                       const float* __restrict__ w3, const float* __restrict__ wc,
                       const float* __restrict__ sw){
    if(blockIdx.x == 0){
        __shared__ double shs[256], shq[256];
        int tid = threadIdx.x;
        double s=0.0, q=0.0;
        for(int b=tid;b<512;b+=256){ s += g_part[2*b]; q += g_part[2*b+1]; }
        shs[tid]=s; shq[tid]=q; __syncthreads();
        for(int o=128;o>0;o>>=1){ if(tid<o){shs[tid]+=shs[tid+o]; shq[tid]+=shq[tid+o];} __syncthreads(); }
        if(tid==0){
            double n = (double)T*F*C0;
            double m = shs[0]/n;
            double v = shq[0]/n - m*m;
            g_stats0[0] = (float)m;
            g_stats0[1] = rsqrtf((float)v + EPSV);
        }
    }
    int i = blockIdx.x*blockDim.x + threadIdx.x;
    if(i < 1536) ((double*)g_pstat)[i] = 0.0;
    if(i < 114688){
        int o=i/448, kl=i%448, k7=kl>>6, c=kl&63;
        float v = sw[(o>>7)*57344 + (c*7+k7)*128 + (o&127)];
        split16(v, &g_wsruh[i], &g_wsrul[i]); return;
    }
    i -= 114688;
    if(i < 114688){
        int o=i/896, kl=i%896, k7=kl>>7, c=kl&127;
        split16(w2[o*896 + c*7 + k7], &g_w2h[i], &g_w2l[i]); return;
    }
    i -= 114688;
    if(i < 8192){ split16(w1[i], &g_w1h[i], &g_w1l[i]); return; }
    i -= 8192;
    if(i < 8192){ split16(w3[i], &g_w3h[i], &g_w3l[i]); return; }
    i -= 8192;
    if(i < 28672){
        int o=i/448, kl=i%448, k7=kl>>6, c=kl&63;
        split16(wc[c*448 + o*7 + k7], &g_wcth[i], &g_wctl[i]);
    }
}

// ---------------- gn0 apply + transpose to [t][f][c], packed split store ----------------
__global__ void k_xn(const float* __restrict__ x, const float* __restrict__ w, const float* __restrict__ b){
    __shared__ float sm[32*65];
    int t0 = blockIdx.x*32;
    int f  = blockIdx.y;
    int tid = threadIdx.x;
    float mean = g_stats0[0], rstd = g_stats0[1];
    #pragma unroll
    for(int rep=0;rep<8;rep++){
        int lin = tid + rep*256;
        int c = lin >> 5, tl = lin & 31;
        float v = x[((size_t)c*F + f)*T + t0 + tl];
        v = (v-mean)*rstd*w[c] + b[c];
        sm[tl*65 + c] = v;
    }
    __syncthreads();
    #pragma unroll
    for(int rep=0;rep<4;rep++){
        int lin = tid + rep*256;
        int cp = (lin & 31)*2, tl = lin >> 5;
        float v0 = sm[tl*65 + cp];
        float v1 = sm[tl*65 + cp + 1];
        uint32_t h2 = cvt2(v1, v0);
        __half2 hh = *reinterpret_cast<__half2*>(&h2);
        float l0 = v0 - __low2float(hh);
        float l1 = v1 - __high2float(hh);
        uint32_t l2w = cvt2(l1, l0);
        size_t idx = ((size_t)(t0+tl)*F + f)*C0 + cp;
        *(uint32_t*)&g_X2h[idx] = h2;
        *(uint32_t*)&g_X2l[idx] = l2w;
    }
}

// ---------------- fp16x3 mma.sync GEMM with fused A-transform + fused stats ----------------
enum { M_SRU=0, M_C1=1, M_C2=2, M_C3=3, M_CT=4 };

__device__ __forceinline__ void mma16(float* c, const uint32_t* a, const uint32_t* b){
    asm volatile(
        "mma.sync.aligned.m16n8k16.row.col.f32.f16.f16.f32 "
        "{%0,%1,%2,%3},{%4,%5,%6,%7},{%8,%9},{%0,%1,%2,%3};"
        : "+f"(c[0]), "+f"(c[1]), "+f"(c[2]), "+f"(c[3])
        : "r"(a[0]), "r"(a[1]), "r"(a[2]), "r"(a[3]), "r"(b[0]), "r"(b[1]));
}

// smem layout (32-bit words), rows padded to 40 halfs (80 B)
#define AH_W 0
#define AL_W (128*20)              // 2560
#define BH_W (2*128*20)            // 5120

template<int MODE, int BN, int KCHUNKS, int KTOT>
__global__ void __launch_bounds__(256,2)
k_mma(const float* __restrict__ bias, const float* __restrict__ xs, float* __restrict__ outp,
      const float* __restrict__ nw, const float* __restrict__ nb){
    extern __shared__ uint32_t dsm[];
    __shared__ int s_aux[128];
    __shared__ float s_w[128], s_b[128], s_mn[128], s_rs[128];
    constexpr int NI = BN/16;
    constexpr int BUF_Wc = BH_W + 2*BN*20;
    constexpr bool NORM = (MODE==M_C2 || MODE==M_C3 || MODE==M_CT);
    constexpr int SIDX = (MODE==M_C2)?0 : (MODE==M_C3)?1 : 2;
    constexpr int OSIDX = (MODE==M_C1)?0 : (MODE==M_C2)?1 : 2;
    constexpr bool OSTAT = (MODE==M_C1 || MODE==M_C2 || MODE==M_C3);
    constexpr int CHN  = (MODE==M_CT)?64 : 128;

    const int tid = threadIdx.x, lane = tid & 31, wid = tid >> 5;
    const int warp_m = wid & 3, warp_n = wid >> 2;
    const int lr = lane >> 2, lc = lane & 3;
    const int col0 = blockIdx.x * BN;
    const int row0 = blockIdx.y * 128;
    const uint32_t smb = smem_u32(dsm);
    // ldmatrix lane geometry
    const int rin = lane & 7, tt = lane >> 3;
    const int a_row = (tt&1)*8 + rin;
    const int a_kb  = (tt>>1)*16;
    const int b_nt  = (tt>>1)*8;
    const int b_kb  = (tt&1)*16;

    const __half* BpH = (MODE==M_SRU)? g_wsruh: (MODE==M_C1)? g_w1h : (MODE==M_C2)? g_w2h: (MODE==M_C3)? g_w3h: g_wcth;
    const __half* BpL = (MODE==M_SRU)? g_wsrul: (MODE==M_C1)? g_w1l : (MODE==M_C2)? g_w2l: (MODE==M_C3)? g_w3l: g_wctl;
    const float*  Araw = (MODE==M_C1)? g_y : (MODE==M_C2)? g_a1 : (MODE==M_C3)? g_a2 : g_a3r;

    if(MODE==M_C2 || MODE==M_CT){
        if(tid<128){
            int r = row0 + tid;
            s_aux[tid] = (MODE==M_C2) ? (r % LL) : (r & 511);
        }
    }
    if(NORM){
        if(tid < CHN){ s_w[tid] = nw[tid]; s_b[tid] = nb[tid]; }
        if(tid < 128){
            int n = (MODE==M_CT) ? ((row0+tid)>>9) : ((row0+tid)/LL);
            int len = (MODE==M_CT) ? LL*64 : LL*128;
            double s = g_pstat[SIDX][n][0], q = g_pstat[SIDX][n][1];
            double m = s/len;
            double v = q/len - m*m;
            s_mn[tid] = (float)m;
            s_rs[tid] = rsqrtf((float)v + EPSV);
        }
    }
    __syncthreads();

    // B cp.async issue
    auto cpB = [&](int ch, int b){
        const int kbase = ch*32;
        const uint32_t base = smb + b*(BUF_Wc*4);
        #pragma unroll
        for(int rep=0;rep<BN/64;rep++){
            int o = rep*64 + (tid>>2), k4 = tid&3;
            size_t off = (size_t)(col0+o)*KTOT + kbase + k4*8;
            uint32_t d = base + BH_W*4 + o*80 + k4*16;
            cp16(d,               BpH+off, true);
            cp16(d + BN*20*4,     BpL+off, true);
        }
    };

    float acc[2][NI][4] = {};

    // ---- mma on one buffered chunk ----
    auto mma_chunk = [&](int b){
        const uint32_t bufb = smb + b*(BUF_Wc*4);
        #pragma unroll
        for(int k16=0;k16<2;k16++){
            uint32_t ah[2][4], al[2][4];
            #pragma unroll
            for(int mi=0;mi<2;mi++){
                uint32_t ra = bufb + (warp_m*32 + mi*16 + a_row)*80 + k16*32 + a_kb;
                ldsm4(ah[mi], ra);
                ldsm4(al[mi], ra + AL_W*4);
            }
            #pragma unroll
            for(int pg=0; pg<NI/4; pg++){
                const int p0 = 2*pg, p1 = 2*pg+1;
                uint32_t rb0 = bufb + BH_W*4 + (warp_n*(BN/2) + p0*16 + b_nt + rin)*80 + k16*32 + b_kb;
                uint32_t rb1 = bufb + BH_W*4 + (warp_n*(BN/2) + p1*16 + b_nt + rin)*80 + k16*32 + b_kb;
                uint32_t bh0[4], bl0[4], bh1[4], bl1[4];
                ldsm4(bh0, rb0); ldsm4(bl0, rb0 + BN*20*4);
                ldsm4(bh1, rb1); ldsm4(bl1, rb1 + BN*20*4);
                mma16(acc[0][2*p0],   ah[0], bh0);   mma16(acc[1][2*p0],   ah[1], bh0);
                mma16(acc[0][2*p0+1], ah[0], bh0+2); mma16(acc[1][2*p0+1], ah[1], bh0+2);
                mma16(acc[0][2*p1],   ah[0], bh1);   mma16(acc[1][2*p1],   ah[1], bh1);
                mma16(acc[0][2*p1+1], ah[0], bh1+2); mma16(acc[1][2*p1+1], ah[1], bh1+2);
                mma16(acc[0][2*p0],   al[0], bh0);   mma16(acc[1][2*p0],   al[1], bh0);
                mma16(acc[0][2*p0+1], al[0], bh0+2); mma16(acc[1][2*p0+1], al[1], bh0+2);
                mma16(acc[0][2*p1],   al[0], bh1);   mma16(acc[1][2*p1],   al[1], bh1);
                mma16(acc[0][2*p1+1], al[0], bh1+2); mma16(acc[1][2*p1+1], al[1], bh1+2);
                mma16(acc[0][2*p0],   ah[0], bl0);   mma16(acc[1][2*p0],   ah[1], bl0);
                mma16(acc[0][2*p0+1], ah[0], bl0+2); mma16(acc[1][2*p0+1], ah[1], bl0+2);
                mma16(acc[0][2*p1],   ah[0], bl1);   mma16(acc[1][2*p1],   ah[1], bl1);
                mma16(acc[0][2*p1+1], ah[0], bl1+2); mma16(acc[1][2*p1+1], ah[1], bl1+2);
            }
        }
    };

    if(MODE==M_SRU){
        // ---- cp.async A path (pre-split X2), single sync per chunk ----
        auto issue = [&](int ch, int b){
            int k7 = ch>>1, c0 = (ch&1)*32;
            const uint32_t base = smb + b*(BUF_Wc*4);
            #pragma unroll
            for(int rep=0;rep<2;rep++){
                int lin = tid + rep*256;
                int m = lin>>2, k4 = lin&3;
                size_t off=(size_t)(row0+m+k7*256)*64 + c0 + k4*8;
                uint32_t d = base + m*80 + k4*16;
                cp16(d,            g_X2h+off, true);
                cp16(d + AL_W*4,   g_X2l+off, true);
            }
            cpB(ch, b);
        };
        issue(0, 0);
        CP_COMMIT();
        for(int ch=0; ch<KCHUNKS; ch++){
            CP_WAIT0();
            __syncthreads();
            if(ch+1 < KCHUNKS){ issue(ch+1, (ch+1)&1); CP_COMMIT(); }
            mma_chunk(ch&1);
        }
    } else {
        // ---- register A path with fused transform, single sync per chunk ----
        const int am = tid>>1, akh = (tid&1)*16;
        const float mymn = NORM ? s_mn[am] : 0.f;
        const float myrs = NORM ? s_rs[am] : 0.f;
        float4 a4[4], y4[4];
        bool apred = true;
        int acbase = 0;

        auto loadA = [&](int ch){
            size_t off = 0;
            if(MODE==M_C1){
                apred = true;
                off = (size_t)(row0+am)*64 + ch*32 + akh;
            } else if(MODE==M_C2){
                int k7 = ch>>2, c0 = (ch&3)*32;
                int l2 = s_aux[am] + k7 - 3;
                apred = ((unsigned)l2 < LL);
                off = (size_t)(row0+am+k7-3)*128 + c0 + akh;
                acbase = c0 + akh;
            } else if(MODE==M_C3){
                apred = true;
                off = (size_t)(row0+am)*128 + ch*32 + akh;
                acbase = ch*32 + akh;
            } else { // M_CT
                int k7 = ch>>1, c0 = (ch&1)*32;
                int p2 = s_aux[am] - k7;
                apred = ((unsigned)p2 < LL);
                int n = (row0+am)>>9;
                off = ((size_t)n*LL + p2)*64 + c0 + akh;
                acbase = c0 + akh;
            }
            if(apred){
                #pragma unroll
                for(int q=0;q<4;q++) a4[q] = *(const float4*)(Araw + off + q*4);
                if(MODE==M_CT){
                    #pragma unroll
                    for(int q=0;q<4;q++) y4[q] = *(const float4*)(g_y + off + q*4);
                }
            }
        };

        auto stsA = [&](int b){
            uint32_t d = smb + b*(BUF_Wc*4) + am*80 + akh*2;
            if(!apred){
                sts128w(d,        0,0,0,0); sts128w(d+16,        0,0,0,0);
                sts128w(d+AL_W*4, 0,0,0,0); sts128w(d+AL_W*4+16, 0,0,0,0);
                return;
            }
            uint32_t hw[8], lw[8];
            const float* af = (const float*)a4;
            const float* yf = (const float*)y4;
            #pragma unroll
            for(int jp=0;jp<8;jp++){
                float v0 = af[2*jp], v1 = af[2*jp+1];
                if(NORM){
                    int c0i = acbase + 2*jp;
                    v0 = (v0 - mymn)*myrs*s_w[c0i]   + s_b[c0i];
                    v1 = (v1 - mymn)*myrs*s_w[c0i+1] + s_b[c0i+1];
                    v0 = (v0 >= 0.f) ? v0 : 0.25f*v0;
                    v1 = (v1 >= 0.f) ? v1 : 0.25f*v1;
                    if(MODE==M_CT){ v0 += yf[2*jp]; v1 += yf[2*jp+1]; }
                }
                uint32_t h2 = cvt2(v1, v0);
                __half2 hh = *reinterpret_cast<__half2*>(&h2);
                float l0 = v0 - __low2float(hh);
                float l1 = v1 - __high2float(hh);
                hw[jp] = h2;
                lw[jp] = cvt2(l1, l0);
            }
            sts128w(d,    hw[0],hw[1],hw[2],hw[3]);
            sts128w(d+16, hw[4],hw[5],hw[6],hw[7]);
            sts128w(d+AL_W*4,    lw[0],lw[1],lw[2],lw[3]);
            sts128w(d+AL_W*4+16, lw[4],lw[5],lw[6],lw[7]);
        };

        loadA(0);
        cpB(0, 0);
        CP_COMMIT();
        for(int ch=0; ch<KCHUNKS; ch++){
            stsA(ch&1);
            CP_WAIT0();
            __syncthreads();
            if(ch+1 < KCHUNKS){ cpB(ch+1, (ch+1)&1); CP_COMMIT(); loadA(ch+1); }
            mma_chunk(ch&1);
        }
    }

    // ---- staged epilogue: smem C tile, coalesced float4 stores, fused stats ----
    __syncthreads();
    float* Cs = (float*)dsm;   // [128][BN+1]
    #pragma unroll
    for(int mi=0;mi<2;mi++){
        int rl = warp_m*32 + mi*16 + lr;
        #pragma unroll
        for(int ni=0;ni<NI;ni++){
            int cl = warp_n*(BN/2) + ni*8 + 2*lc;
            #pragma unroll
            for(int rr=0;rr<2;rr++){
                Cs[(rl+rr*8)*(BN+1) + cl]   = acc[mi][ni][rr*2];
                Cs[(rl+rr*8)*(BN+1) + cl+1] = acc[mi][ni][rr*2+1];
            }
        }
    }
    __syncthreads();

    if(MODE==M_CT){
        int n = row0 >> 9, p0 = row0 & 511;
        #pragma unroll 4
        for(int i = tid*4; i < 64*128; i += 1024){
            int o = i>>7, m = i&127;
            size_t idx = ((size_t)o*F + n)*T + p0 + m;
            float4 xv = *(const float4*)(xs + idx);
            float bo = bias[o];
            float4 v;
            v.x = Cs[(m  )*(BN+1)+o] + bo + xv.x;
            v.y = Cs[(m+1)*(BN+1)+o] + bo + xv.y;
            v.z = Cs[(m+2)*(BN+1)+o] + bo + xv.z;
            v.w = Cs[(m+3)*(BN+1)+o] + bo + xv.w;
            *(float4*)(outp + idx) = v;
        }
    } else if(MODE==M_SRU){
        int d = col0>>7;
        const int lrow = row0 >> 8, nbase = row0 & 255;
        #pragma unroll 4
        for(int i = tid*4; i < 128*BN; i += 1024){
            int m = i/BN, o = i%BN;
            const float* cr = &Cs[m*(BN+1)+o];
            float4 v = make_float4(cr[0], cr[1], cr[2], cr[3]);
            size_t idx = (size_t)d*U_STRIDE + ((size_t)(nbase+m)*LL + lrow)*128 + o;
            *(float4*)&g_U[idx] = v;
        }
    } else {
        float* dst = (MODE==M_C1)? g_a1 : (MODE==M_C2)? g_a2 : g_a3r;
        const int stride = (MODE==M_C3)? 64 : 128;
        const int n0 = row0 / LL;
        const int split = (n0+1)*LL - row0;   // rows [0,split) -> n0
        float s0=0.f,q0=0.f,s1=0.f,q1=0.f;
        #pragma unroll 4
        for(int i = tid*4; i < 128*BN; i += 1024){
            int m = i/BN, o = i%BN;
            const float* cr = &Cs[m*(BN+1)+o];
            const float* br = &bias[col0+o];
            float4 v = make_float4(cr[0]+br[0], cr[1]+br[1], cr[2]+br[2], cr[3]+br[3]);
            *(float4*)&dst[(size_t)(row0+m)*stride + col0 + o] = v;
            if(OSTAT){
                float ls = v.x + v.y + v.z + v.w;
                float lq = v.x*v.x + v.y*v.y + v.z*v.z + v.w*v.w;
                if(m < split){ s0 += ls; q0 += lq; } else { s1 += ls; q1 += lq; }
            }
        }
        if(OSTAT){
            #pragma unroll
            for(int off=16; off; off>>=1){
                s0 += __shfl_down_sync(0xFFFFFFFFu, s0, off);
                q0 += __shfl_down_sync(0xFFFFFFFFu, q0, off);
                s1 += __shfl_down_sync(0xFFFFFFFFu, s1, off);
                q1 += __shfl_down_sync(0xFFFFFFFFu, q1, off);
            }
            __syncthreads();
            float* red = (float*)dsm + 128*(BN+1);
            if(lane==0){ red[wid]=s0; red[8+wid]=q0; red[16+wid]=s1; red[24+wid]=q1; }
            __syncthreads();
            if(tid==0){
                float S0=0,Q0=0,S1=0,Q1=0;
                #pragma unroll
                for(int w2=0;w2<8;w2++){ S0+=red[w2]; Q0+=red[8+w2]; S1+=red[16+w2]; Q1+=red[24+w2]; }
                atomicAdd(&g_pstat[OSIDX][n0][0], (double)S0);
                atomicAdd(&g_pstat[OSIDX][n0][1], (double)Q0);
                if(split < 128){
                    atomicAdd(&g_pstat[OSIDX][n0+1][0], (double)S1);
                    atomicAdd(&g_pstat[OSIDX][n0+1][1], (double)Q1);
                }
            }
        }
    }
}

// ---------------- SRU scan: deep prefetch, fast sigmoid ----------------
#define PF 12
__global__ void k_scan(const float* __restrict__ sruv, const float* __restrict__ srub){
    int w = (blockIdx.x*blockDim.x + threadIdx.x) >> 5;
    int h = threadIdx.x & 31;
    int d = w >> 8; int n = w & 255;
    float vf = sruv[d*64 + h];
    float vr = sruv[d*64 + 32 + h];
    float bf = srub[d*64 + h];
    float br = srub[d*64 + 32 + h];
    float st = 0.f;
    const float* Ubase = g_U + (size_t)d*U_STRIDE + (size_t)n*LL*128;

    float pf0[PF], pf1[PF], pf2[PF], pf3[PF];
    int pl[PF];
    #pragma unroll
    for(int i=0;i<PF;i++){
        int l = d ? (LL-1-i) : i;
        pl[i] = l;
        const float* u = Ubase + (size_t)l*128;
        pf0[i]=u[h]; pf1[i]=u[32+h]; pf2[i]=u[64+h]; pf3[i]=u[96+h];
    }

    for(int s=0; s<LL; s+=PF){
        #pragma unroll
        for(int i=0;i<PF;i++){
            if(s+i < LL){
                float u0=pf0[i], u1=pf1[i], u2=pf2[i], u3=pf3[i];
                int l = pl[i];
                float f  = sigfast(u1 + vf*st + bf);
                float cn = f*st + (1.f-f)*u0;
                float rr = sigfast(u2 + vr*st + br);
                float hv = rr*cn + (1.f-rr)*u3;
                st = cn;
                g_y[((size_t)n*LL + l)*64 + d*32 + h] = hv;
                int sn = s + i + PF;
                if(sn < LL){
                    int ln = d ? (LL-1-sn) : sn;
                    pl[i] = ln;
                    const float* un = Ubase + (size_t)ln*128;
                    pf0[i]=un[h]; pf1[i]=un[32+h]; pf2[i]=un[64+h]; pf3[i]=un[96+h];
                }
            }
        }
    }
}

// ---------------- launcher ----------------
extern "C" void kernel_launch(void* const* d_in, const int* in_sizes, int n_in,
                              void* d_out, int out_size){
    const float* x    = (const float*)d_in[0];
    const float* gn0w = (const float*)d_in[1];
    const float* gn0b = (const float*)d_in[2];
    const float* sruw = (const float*)d_in[3];
    const float* sruv = (const float*)d_in[4];
    const float* srub = (const float*)d_in[5];
    const float* c1w  = (const float*)d_in[6];
    const float* c1b  = (const float*)d_in[7];
    const float* gn1w = (const float*)d_in[8];
    const float* gn1b = (const float*)d_in[9];
    const float* c2w  = (const float*)d_in[10];
    const float* c2b  = (const float*)d_in[11];
    const float* gn2w = (const float*)d_in[12];
    const float* gn2b = (const float*)d_in[13];
    const float* c3w  = (const float*)d_in[14];
    const float* c3b  = (const float*)d_in[15];
    const float* gn3w = (const float*)d_in[16];
    const float* gn3b = (const float*)d_in[17];
    const float* ctw  = (const float*)d_in[18];
    const float* ctb  = (const float*)d_in[19];
    float* out = (float*)d_out;

    const int smem128 = 2*(BH_W + 2*128*20)*4;   // 81920
    const int smem64  = 2*(BH_W + 2*64*20)*4;    // 61440
    cudaFuncSetAttribute(k_mma<M_SRU,128,14,448>, cudaFuncAttributeMaxDynamicSharedMemorySize, smem128);
    cudaFuncSetAttribute(k_mma<M_C1 ,128, 2, 64>, cudaFuncAttributeMaxDynamicSharedMemorySize, smem128);
    cudaFuncSetAttribute(k_mma<M_C2 ,128,28,896>, cudaFuncAttributeMaxDynamicSharedMemorySize, smem128);
    cudaFuncSetAttribute(k_mma<M_C3 , 64, 4,128>, cudaFuncAttributeMaxDynamicSharedMemorySize, smem64);
    cudaFuncSetAttribute(k_mma<M_CT , 64,14,448>, cudaFuncAttributeMaxDynamicSharedMemorySize, smem64);

    k_red0 <<<512,256>>>(x);
    k_prep <<<1072,256>>>(c1w, c2w, c3w, ctw, sruw);
    k_xn   <<<dim3(16,256),256>>>(x, gn0w, gn0b);

    k_mma<M_SRU,128,14,448><<<dim3(2,M_ROWS/128),256,smem128>>>(nullptr, nullptr, nullptr, nullptr, nullptr);
    k_scan <<<128,128>>>(sruv, srub);

    k_mma<M_C1,128,2,64>  <<<dim3(1,M_ROWS/128),256,smem128>>>(c1b, nullptr, nullptr, nullptr, nullptr);
    k_mma<M_C2,128,28,896><<<dim3(1,M_ROWS/128),256,smem128>>>(c2b, nullptr, nullptr, gn1w, gn1b);
    k_mma<M_C3,64,4,128> <<<dim3(1,M_ROWS/128),256,smem64>>>(c3b, nullptr, nullptr, gn2w, gn2b);
    k_mma<M_CT,64,14,448><<<dim3(1,(F*T)/128),256,smem64>>>(ctb, x, out, gn3w, gn3b);
}